// round 1
// baseline (speedup 1.0000x reference)
#include <cuda_runtime.h>
#include <math.h>

// ---------------- problem constants ----------------
#define N_MAX 40000
#define E_MAX 640000
#define F_IN  512
#define H     128
#define C_OUT 40
#define NEG_SLOPE 0.01f

// ---------------- scratch (device globals; no runtime alloc) ----------------
__device__ float g_xh [N_MAX * H];
__device__ float g_tx1[N_MAX * H];
__device__ float g_s  [N_MAX * H];
__device__ float g_o2 [N_MAX * H];
__device__ float g_t  [N_MAX * H];
__device__ float g_x1 [N_MAX * H];

__device__ float g_deg   [N_MAX];
__device__ float g_dis   [N_MAX];
__device__ float g_loopw [N_MAX];
__device__ float g_invcnt[N_MAX];
__device__ float g_cntf  [N_MAX];
__device__ int   g_hist  [N_MAX];
__device__ int   g_off   [N_MAX + 1];
__device__ int   g_cursor[N_MAX];
__device__ int   g_esrc  [E_MAX];
__device__ float g_enorm [E_MAX];
__device__ float g_ewe   [E_MAX];

// ---------------- small utility kernels ----------------
__global__ void fill_ones(float* p, int n) {
    int i = blockIdx.x * blockDim.x + threadIdx.x;
    if (i < n) p[i] = 1.0f;
}

// pass 1: degrees (over src, non-loop), sage counts (over dst, non-loop),
// loop weights, and dst histogram (all edges).
__global__ void edge_pass1(const int* __restrict__ src, const int* __restrict__ dst,
                           const float* __restrict__ w,
                           float* __restrict__ deg, float* __restrict__ cntf,
                           float* __restrict__ loopw, int* __restrict__ hist, int E) {
    int i = blockIdx.x * blockDim.x + threadIdx.x;
    if (i >= E) return;
    int s = src[i], d = dst[i];
    float wt = w[i];
    if (s == d) {
        loopw[s] = wt;                  // PyG: keep existing self-loop weight
    } else {
        atomicAdd(&deg[s], wt);
        atomicAdd(&cntf[d], 1.0f);
    }
    atomicAdd(&hist[d], 1);
}

__global__ void node_prep(const float* __restrict__ deg, const float* __restrict__ cntf,
                          float* __restrict__ dis, float* __restrict__ invcnt, int N) {
    int i = blockIdx.x * blockDim.x + threadIdx.x;
    if (i >= N) return;
    float dg = deg[i];
    dis[i]    = (dg > 0.0f) ? rsqrtf(dg) : 0.0f;
    invcnt[i] = 1.0f / (cntf[i] + 1.0f);
}

// exclusive scan of hist[0..n) into off[0..n], cursor = off. Single block.
__global__ void scan_kernel(const int* __restrict__ hist, int* __restrict__ off,
                            int* __restrict__ cursor, int n) {
    __shared__ int partial[1024];
    int tid = threadIdx.x;
    int chunk = (n + 1023) / 1024;
    int beg = tid * chunk;
    int end = beg + chunk; if (end > n) end = n; if (beg > n) beg = n;
    int sum = 0;
    for (int i = beg; i < end; i++) sum += hist[i];
    partial[tid] = sum;
    __syncthreads();
    for (int s = 1; s < 1024; s <<= 1) {
        int v = (tid >= s) ? partial[tid - s] : 0;
        __syncthreads();
        partial[tid] += v;
        __syncthreads();
    }
    int run = (tid == 0) ? 0 : partial[tid - 1];
    for (int i = beg; i < end; i++) {
        off[i] = run; cursor[i] = run;
        run += hist[i];
    }
    if (tid == 0) off[n] = partial[1023];
}

// pass 2: per-edge cheb norm + sage weight; bucket edges by dst (CSR)
__global__ void edge_pass2(const int* __restrict__ src, const int* __restrict__ dst,
                           const float* __restrict__ w, const float* __restrict__ dis,
                           int* __restrict__ cursor,
                           int* __restrict__ esrc, float* __restrict__ enorm,
                           float* __restrict__ ewe, int E) {
    int i = blockIdx.x * blockDim.x + threadIdx.x;
    if (i >= E) return;
    int s = src[i], d = dst[i];
    float wt = w[i];
    float wc = (s == d) ? 0.0f : wt;
    float nm = -dis[s] * wc * dis[d];
    int pos = atomicAdd(&cursor[d], 1);
    esrc[pos]  = s;
    enorm[pos] = nm;
    ewe[pos]   = wc;
}

// warp-per-node CSR aggregation: tx1[v] = sum norm*xh[src], s[v] = sum we*xh[src]
__global__ void __launch_bounds__(256) aggregate(
        const float* __restrict__ xh, const int* __restrict__ off,
        const int* __restrict__ esrc, const float* __restrict__ enorm,
        const float* __restrict__ ewe,
        float* __restrict__ tx1, float* __restrict__ s, int N) {
    int warp = (blockIdx.x * blockDim.x + threadIdx.x) >> 5;
    int lane = threadIdx.x & 31;
    if (warp >= N) return;
    int beg = off[warp], end = off[warp + 1];
    const float4* xh4 = (const float4*)xh;
    float4 a1 = make_float4(0, 0, 0, 0);
    float4 a2 = make_float4(0, 0, 0, 0);
    for (int j = beg; j < end; j++) {
        int sn = __ldg(&esrc[j]);
        float nm = __ldg(&enorm[j]);
        float we = __ldg(&ewe[j]);
        float4 v = __ldg(&xh4[(size_t)sn * 32 + lane]);
        a1.x += nm * v.x; a1.y += nm * v.y; a1.z += nm * v.z; a1.w += nm * v.w;
        a2.x += we * v.x; a2.y += we * v.y; a2.z += we * v.z; a2.w += we * v.w;
    }
    ((float4*)tx1)[(size_t)warp * 32 + lane] = a1;
    ((float4*)s  )[(size_t)warp * 32 + lane] = a2;
}

// elementwise sage-mean: s <- (s + loopw[node]*xh) * invcnt[node]   (in place)
__global__ void mean_ew(float* __restrict__ s, const float* __restrict__ xh,
                        const float* __restrict__ loopw, const float* __restrict__ invcnt,
                        int N) {
    int i = blockIdx.x * blockDim.x + threadIdx.x;   // float4 index
    if (i >= N * 32) return;
    int node = i >> 5;
    float lw = loopw[node], ic = invcnt[node];
    float4 sv = ((const float4*)s)[i];
    float4 xv = ((const float4*)xh)[i];
    sv.x = (sv.x + lw * xv.x) * ic;
    sv.y = (sv.y + lw * xv.y) * ic;
    sv.z = (sv.z + lw * xv.z) * ic;
    sv.w = (sv.w + lw * xv.w) * ic;
    ((float4*)s)[i] = sv;
}

// ---------------- GEMM (BN fixed = 128) ----------------
// C[M,128] = A0@B0 (+ A1@B1) + bias;  EPI: 0=none, 1=LReLU, 2=LReLU then +=addsrc
template<bool DUAL, int EPI>
__global__ void __launch_bounds__(256) gemm_h128(
        const float* __restrict__ A0, const float* __restrict__ A1,
        const float* __restrict__ B0, const float* __restrict__ B1,
        const float* __restrict__ bias, const float* __restrict__ addsrc,
        float* __restrict__ C, int M, int K) {
    constexpr int BM = 128, BN = 128, BK = 16;
    __shared__ float As0[BK][BM];
    __shared__ float Bs0[BK][BN];
    __shared__ float As1[DUAL ? BK : 1][DUAL ? BM : 1];
    __shared__ float Bs1[DUAL ? BK : 1][DUAL ? BN : 1];

    int tid = threadIdx.x;
    int brow = blockIdx.x * BM;
    int tx = tid & 15, ty = tid >> 4;
    float acc[8][8];
#pragma unroll
    for (int i = 0; i < 8; i++)
#pragma unroll
        for (int j = 0; j < 8; j++) acc[i][j] = 0.0f;

    for (int k0 = 0; k0 < K; k0 += BK) {
#pragma unroll
        for (int t = tid; t < 512; t += 256) {
            // A: 128 rows x 16 cols = 512 float4
            int r = t >> 2, c4 = (t & 3) * 4;
            int row = brow + r;
            float4 v = make_float4(0, 0, 0, 0);
            if (row < M) v = *(const float4*)(A0 + (size_t)row * K + k0 + c4);
            As0[c4 + 0][r] = v.x; As0[c4 + 1][r] = v.y;
            As0[c4 + 2][r] = v.z; As0[c4 + 3][r] = v.w;
            if constexpr (DUAL) {
                float4 u = make_float4(0, 0, 0, 0);
                if (row < M) u = *(const float4*)(A1 + (size_t)row * K + k0 + c4);
                As1[c4 + 0][r] = u.x; As1[c4 + 1][r] = u.y;
                As1[c4 + 2][r] = u.z; As1[c4 + 3][r] = u.w;
            }
            // B: 16 rows x 128 cols = 512 float4
            int rb = t >> 5, cb = (t & 31) * 4;
            *(float4*)&Bs0[rb][cb] = *(const float4*)(B0 + (size_t)(k0 + rb) * BN + cb);
            if constexpr (DUAL)
                *(float4*)&Bs1[rb][cb] = *(const float4*)(B1 + (size_t)(k0 + rb) * BN + cb);
        }
        __syncthreads();
#pragma unroll
        for (int kk = 0; kk < BK; kk++) {
            float a[8], b[8];
#pragma unroll
            for (int j = 0; j < 8; j++) { a[j] = As0[kk][ty * 8 + j]; b[j] = Bs0[kk][tx * 8 + j]; }
#pragma unroll
            for (int i = 0; i < 8; i++)
#pragma unroll
                for (int j = 0; j < 8; j++) acc[i][j] += a[i] * b[j];
            if constexpr (DUAL) {
                float a1[8], b1[8];
#pragma unroll
                for (int j = 0; j < 8; j++) { a1[j] = As1[kk][ty * 8 + j]; b1[j] = Bs1[kk][tx * 8 + j]; }
#pragma unroll
                for (int i = 0; i < 8; i++)
#pragma unroll
                    for (int j = 0; j < 8; j++) acc[i][j] += a1[i] * b1[j];
            }
        }
        __syncthreads();
    }

    // epilogue: float4 stores
#pragma unroll
    for (int i = 0; i < 8; i++) {
        int row = brow + ty * 8 + i;
        if (row >= M) break;
#pragma unroll
        for (int jj = 0; jj < 2; jj++) {
            int col = tx * 8 + jj * 4;
            float4 v;
            v.x = acc[i][jj * 4 + 0] + bias[col + 0];
            v.y = acc[i][jj * 4 + 1] + bias[col + 1];
            v.z = acc[i][jj * 4 + 2] + bias[col + 2];
            v.w = acc[i][jj * 4 + 3] + bias[col + 3];
            if constexpr (EPI >= 1) {
                v.x = v.x > 0.0f ? v.x : NEG_SLOPE * v.x;
                v.y = v.y > 0.0f ? v.y : NEG_SLOPE * v.y;
                v.z = v.z > 0.0f ? v.z : NEG_SLOPE * v.z;
                v.w = v.w > 0.0f ? v.w : NEG_SLOPE * v.w;
            }
            if constexpr (EPI == 2) {
                float4 o = *(const float4*)(addsrc + (size_t)row * 128 + col);
                v.x += o.x; v.y += o.y; v.z += o.z; v.w += o.w;
            }
            *(float4*)(C + (size_t)row * 128 + col) = v;
        }
    }
}

// ---------------- classifier + log_softmax (warp per row) ----------------
__global__ void __launch_bounds__(256) cls_kernel(
        const float* __restrict__ x, const float* __restrict__ W,   // W: [128, C_OUT]
        const float* __restrict__ b, float* __restrict__ out, int M) {
    __shared__ float Wt[C_OUT][128];
    __shared__ float bs[C_OUT];
    for (int i = threadIdx.x; i < 128 * C_OUT; i += 256) {
        int k = i / C_OUT, c = i % C_OUT;
        Wt[c][k] = W[i];
    }
    if (threadIdx.x < C_OUT) bs[threadIdx.x] = b[threadIdx.x];
    __syncthreads();

    int warp = threadIdx.x >> 5, lane = threadIdx.x & 31;
    int row = blockIdx.x * 8 + warp;
    if (row >= M) return;

    float xr[4];
#pragma unroll
    for (int j = 0; j < 4; j++) xr[j] = x[(size_t)row * 128 + lane + 32 * j];

    float acc[C_OUT];
#pragma unroll
    for (int c = 0; c < C_OUT; c++) {
        float a = 0.0f;
#pragma unroll
        for (int j = 0; j < 4; j++) a += xr[j] * Wt[c][lane + 32 * j];
#pragma unroll
        for (int o = 16; o > 0; o >>= 1) a += __shfl_down_sync(0xFFFFFFFFu, a, o);
        acc[c] = a;
    }
    if (lane == 0) {
        float mx = -1e30f;
#pragma unroll
        for (int c = 0; c < C_OUT; c++) { acc[c] += bs[c]; mx = fmaxf(mx, acc[c]); }
        float se = 0.0f;
#pragma unroll
        for (int c = 0; c < C_OUT; c++) se += expf(acc[c] - mx);
        float l = mx + logf(se);
#pragma unroll
        for (int c = 0; c < C_OUT; c++) out[(size_t)row * C_OUT + c] = acc[c] - l;
    }
}

// ---------------- host ----------------
static void* symaddr(const void* sym) {
    void* p = nullptr;
    cudaGetSymbolAddress(&p, sym);
    return p;
}

static void run_cell(const float* x_in, int Kin,
                     const float* pw, const float* pb,
                     const float* cw0, const float* cw1, const float* cb,
                     const float* sw, const float* sb,
                     const float* lw, const float* lb,
                     float* xh, float* tx1, float* s, float* o2, float* t,
                     float* x_out,
                     const int* off, const int* esrc, const float* enorm, const float* ewe,
                     const float* loopw, const float* invcnt, int N) {
    int gG = (N + 127) / 128;
    // xh = x_in @ pw + pb
    gemm_h128<false, 0><<<gG, 256>>>(x_in, nullptr, pw, nullptr, pb, nullptr, xh, N, Kin);
    // tx1, s  (CSR aggregation, both scatters fused into one gather pass)
    aggregate<<<(N * 32 + 255) / 256, 256>>>(xh, off, esrc, enorm, ewe, tx1, s, N);
    // s <- sage mean input
    mean_ew<<<(N * 32 + 255) / 256, 256>>>(s, xh, loopw, invcnt, N);
    // o2 = LReLU(s @ sw + sb)
    gemm_h128<false, 1><<<gG, 256>>>(s, nullptr, sw, nullptr, sb, nullptr, o2, N, H);
    // t = LReLU(xh@cw0 + tx1@cw1 + cb) + o2
    gemm_h128<true, 2><<<gG, 256>>>(xh, tx1, cw0, cw1, cb, o2, t, N, H);
    // x_out = t @ lw + lb
    gemm_h128<false, 0><<<gG, 256>>>(t, nullptr, lw, nullptr, lb, nullptr, x_out, N, H);
}

extern "C" void kernel_launch(void* const* d_in, const int* in_sizes, int n_in,
                              void* d_out, int out_size) {
    const float* x   = (const float*)d_in[0];
    const int*   ei  = (const int*)d_in[1];
    const float* ew  = (const float*)d_in[2];
    const float* pre_w1 = (const float*)d_in[3];  const float* pre_b1 = (const float*)d_in[4];
    const float* cw0_1  = (const float*)d_in[5];  const float* cw1_1  = (const float*)d_in[6];
    const float* cb_1   = (const float*)d_in[7];
    const float* sw_1   = (const float*)d_in[8];  const float* sb_1   = (const float*)d_in[9];
    const float* lw_1   = (const float*)d_in[10]; const float* lb_1   = (const float*)d_in[11];
    const float* pre_w2 = (const float*)d_in[12]; const float* pre_b2 = (const float*)d_in[13];
    const float* cw0_2  = (const float*)d_in[14]; const float* cw1_2  = (const float*)d_in[15];
    const float* cb_2   = (const float*)d_in[16];
    const float* sw_2   = (const float*)d_in[17]; const float* sb_2   = (const float*)d_in[18];
    const float* lw_2   = (const float*)d_in[19]; const float* lb_2   = (const float*)d_in[20];
    const float* cls_w  = (const float*)d_in[21]; const float* cls_b  = (const float*)d_in[22];
    float* out = (float*)d_out;

    int E = in_sizes[2];
    int N = in_sizes[0] / F_IN;
    const int* src = ei;
    const int* dst = ei + E;

    float* xh    = (float*)symaddr(g_xh);
    float* tx1   = (float*)symaddr(g_tx1);
    float* sbuf  = (float*)symaddr(g_s);
    float* o2    = (float*)symaddr(g_o2);
    float* tbuf  = (float*)symaddr(g_t);
    float* x1    = (float*)symaddr(g_x1);
    float* deg   = (float*)symaddr(g_deg);
    float* dis   = (float*)symaddr(g_dis);
    float* loopw = (float*)symaddr(g_loopw);
    float* invc  = (float*)symaddr(g_invcnt);
    float* cntf  = (float*)symaddr(g_cntf);
    int*   hist  = (int*)symaddr(g_hist);
    int*   off   = (int*)symaddr(g_off);
    int*   cur   = (int*)symaddr(g_cursor);
    int*   esrc  = (int*)symaddr(g_esrc);
    float* enorm = (float*)symaddr(g_enorm);
    float* ewe   = (float*)symaddr(g_ewe);

    int eB = (E + 255) / 256;
    int nB = (N + 255) / 256;

    // ---- graph-structure preprocessing (cell-independent) ----
    cudaMemsetAsync(deg,  0, (size_t)N * sizeof(float));
    cudaMemsetAsync(cntf, 0, (size_t)N * sizeof(float));
    cudaMemsetAsync(hist, 0, (size_t)N * sizeof(int));
    fill_ones<<<nB, 256>>>(loopw, N);
    edge_pass1<<<eB, 256>>>(src, dst, ew, deg, cntf, loopw, hist, E);
    node_prep<<<nB, 256>>>(deg, cntf, dis, invc, N);
    scan_kernel<<<1, 1024>>>(hist, off, cur, N);
    edge_pass2<<<eB, 256>>>(src, dst, ew, dis, cur, esrc, enorm, ewe, E);

    // ---- cell 1 (512 -> 128) ----
    run_cell(x, F_IN, pre_w1, pre_b1, cw0_1, cw1_1, cb_1, sw_1, sb_1, lw_1, lb_1,
             xh, tx1, sbuf, o2, tbuf, x1,
             off, esrc, enorm, ewe, loopw, invc, N);
    // ---- cell 2 (128 -> 128), output reuses o2 buffer ----
    run_cell(x1, H, pre_w2, pre_b2, cw0_2, cw1_2, cb_2, sw_2, sb_2, lw_2, lb_2,
             xh, tx1, sbuf, o2, tbuf, x1,
             off, esrc, enorm, ewe, loopw, invc, N);

    // ---- classifier + log_softmax ----
    cls_kernel<<<(N + 7) / 8, 256>>>(x1, cls_w, cls_b, out, N);
}

// round 2
// speedup vs baseline: 1.2605x; 1.2605x over previous
#include <cuda_runtime.h>
#include <math.h>

// ---------------- problem constants ----------------
#define N_MAX 40000
#define E_MAX 640000
#define F_IN  512
#define H     128
#define C_OUT 40
#define NEG_SLOPE 0.01f

// ---------------- scratch (device globals; no runtime alloc) ----------------
__device__ float g_xh [N_MAX * H];
__device__ float g_tx1[N_MAX * H];
__device__ float g_s  [N_MAX * H];
__device__ float g_o2 [N_MAX * H];
__device__ float g_t  [N_MAX * H];

__device__ float g_deg   [N_MAX];
__device__ float g_dis   [N_MAX];
__device__ float g_loopw [N_MAX];
__device__ float g_invcnt[N_MAX];
__device__ float g_cntf  [N_MAX];
__device__ int   g_hist  [N_MAX];
__device__ int   g_off   [N_MAX + 1];
__device__ int   g_cursor[N_MAX];
__device__ int   g_bsum  [64];
__device__ int   g_esrc  [E_MAX];
__device__ float g_enorm [E_MAX];
__device__ float g_ewe   [E_MAX];

__device__ float g_W12[H * H];
__device__ float g_b12[H];
__device__ float g_Wc [H * C_OUT];
__device__ float g_bc [C_OUT];

// ---------------- f32x2 helpers ----------------
__device__ __forceinline__ unsigned long long pack2(float lo, float hi) {
    unsigned long long r;
    asm("mov.b64 %0,{%1,%2};" : "=l"(r) : "f"(lo), "f"(hi));
    return r;
}
__device__ __forceinline__ void ffma2(unsigned long long& d, unsigned long long a,
                                      unsigned long long b) {
    asm("fma.rn.f32x2 %0,%1,%2,%0;" : "+l"(d) : "l"(a), "l"(b));
}
__device__ __forceinline__ float2 unpack2(unsigned long long v) {
    float2 r;
    asm("mov.b64 {%0,%1},%2;" : "=f"(r.x), "=f"(r.y) : "l"(v));
    return r;
}

// ---------------- small utility kernels ----------------
__global__ void fill_ones(float* p, int n) {
    int i = blockIdx.x * blockDim.x + threadIdx.x;
    if (i < n) p[i] = 1.0f;
}

// pass 1: degrees (over src, non-loop), sage counts (over dst, non-loop),
// loop weights, and dst histogram (all edges).
__global__ void edge_pass1(const int* __restrict__ src, const int* __restrict__ dst,
                           const float* __restrict__ w,
                           float* __restrict__ deg, float* __restrict__ cntf,
                           float* __restrict__ loopw, int* __restrict__ hist, int E) {
    int i = blockIdx.x * blockDim.x + threadIdx.x;
    if (i >= E) return;
    int s = src[i], d = dst[i];
    float wt = w[i];
    if (s == d) {
        loopw[s] = wt;                  // PyG: keep existing self-loop weight
    } else {
        atomicAdd(&deg[s], wt);
        atomicAdd(&cntf[d], 1.0f);
    }
    atomicAdd(&hist[d], 1);
}

__global__ void node_prep(const float* __restrict__ deg, const float* __restrict__ cntf,
                          float* __restrict__ dis, float* __restrict__ invcnt, int N) {
    int i = blockIdx.x * blockDim.x + threadIdx.x;
    if (i >= N) return;
    float dg = deg[i];
    dis[i]    = (dg > 0.0f) ? rsqrtf(dg) : 0.0f;
    invcnt[i] = 1.0f / (cntf[i] + 1.0f);
}

// ---- multi-block exclusive scan of hist -> off, cursor ----
// phase 1: per-block (1024 elems) sums
__global__ void scan1(const int* __restrict__ hist, int* __restrict__ bsum, int n) {
    __shared__ int sh[256];
    int base = blockIdx.x * 1024;
    int s = 0;
#pragma unroll
    for (int j = 0; j < 4; j++) {
        int i = base + threadIdx.x + j * 256;
        s += (i < n) ? hist[i] : 0;
    }
    sh[threadIdx.x] = s;
    __syncthreads();
    for (int o = 128; o > 0; o >>= 1) {
        if (threadIdx.x < o) sh[threadIdx.x] += sh[threadIdx.x + o];
        __syncthreads();
    }
    if (threadIdx.x == 0) bsum[blockIdx.x] = sh[0];
}
// phase 2: serial exclusive scan of block sums (nb <= 64) + off[n]=total
__global__ void scan2(int* __restrict__ bsum, int nb, int* __restrict__ off, int n) {
    if (threadIdx.x == 0) {
        int run = 0;
        for (int i = 0; i < nb; i++) { int v = bsum[i]; bsum[i] = run; run += v; }
        off[n] = run;
    }
}
// phase 3: local rescan + global offset -> off, cursor
__global__ void scan3(const int* __restrict__ hist, const int* __restrict__ bsum,
                      int* __restrict__ off, int* __restrict__ cursor, int n) {
    __shared__ int sh[256];
    int base = blockIdx.x * 1024 + threadIdx.x * 4;
    int v[4]; int s = 0;
#pragma unroll
    for (int j = 0; j < 4; j++) {
        int i = base + j;
        v[j] = (i < n) ? hist[i] : 0;
        s += v[j];
    }
    sh[threadIdx.x] = s;
    __syncthreads();
    // inclusive Hillis-Steele over 256
    for (int o = 1; o < 256; o <<= 1) {
        int t = (threadIdx.x >= o) ? sh[threadIdx.x - o] : 0;
        __syncthreads();
        sh[threadIdx.x] += t;
        __syncthreads();
    }
    int run = bsum[blockIdx.x] + sh[threadIdx.x] - s;   // exclusive prefix for this thread
#pragma unroll
    for (int j = 0; j < 4; j++) {
        int i = base + j;
        if (i < n) { off[i] = run; cursor[i] = run; }
        run += v[j];
    }
}

// pass 2: per-edge cheb norm + sage weight; bucket edges by dst (CSR)
__global__ void edge_pass2(const int* __restrict__ src, const int* __restrict__ dst,
                           const float* __restrict__ w, const float* __restrict__ dis,
                           int* __restrict__ cursor,
                           int* __restrict__ esrc, float* __restrict__ enorm,
                           float* __restrict__ ewe, int E) {
    int i = blockIdx.x * blockDim.x + threadIdx.x;
    if (i >= E) return;
    int s = src[i], d = dst[i];
    float wt = w[i];
    float wc = (s == d) ? 0.0f : wt;
    float nm = -dis[s] * wc * dis[d];
    int pos = atomicAdd(&cursor[d], 1);
    esrc[pos]  = s;
    enorm[pos] = nm;
    ewe[pos]   = wc;
}

// warp-per-node CSR aggregation with fused sage-mean:
//   tx1[v] = sum norm*xh[src];  s[v] = (sum we*xh[src] + loopw[v]*xh[v]) * invcnt[v]
__global__ void __launch_bounds__(256) aggregate(
        const float* __restrict__ xh, const int* __restrict__ off,
        const int* __restrict__ esrc, const float* __restrict__ enorm,
        const float* __restrict__ ewe,
        const float* __restrict__ loopw, const float* __restrict__ invcnt,
        float* __restrict__ tx1, float* __restrict__ s, int N) {
    int warp = (blockIdx.x * blockDim.x + threadIdx.x) >> 5;
    int lane = threadIdx.x & 31;
    if (warp >= N) return;
    int beg = off[warp], end = off[warp + 1];
    const float4* xh4 = (const float4*)xh;
    float4 a1 = make_float4(0, 0, 0, 0);
    float4 a2 = make_float4(0, 0, 0, 0);
    for (int j = beg; j < end; j++) {
        int sn = __ldg(&esrc[j]);
        float nm = __ldg(&enorm[j]);
        float we = __ldg(&ewe[j]);
        float4 v = __ldg(&xh4[(size_t)sn * 32 + lane]);
        a1.x += nm * v.x; a1.y += nm * v.y; a1.z += nm * v.z; a1.w += nm * v.w;
        a2.x += we * v.x; a2.y += we * v.y; a2.z += we * v.z; a2.w += we * v.w;
    }
    float lw = __ldg(&loopw[warp]);
    float ic = __ldg(&invcnt[warp]);
    float4 xv = __ldg(&xh4[(size_t)warp * 32 + lane]);
    a2.x = (a2.x + lw * xv.x) * ic;
    a2.y = (a2.y + lw * xv.y) * ic;
    a2.z = (a2.z + lw * xv.z) * ic;
    a2.w = (a2.w + lw * xv.w) * ic;
    ((float4*)tx1)[(size_t)warp * 32 + lane] = a1;
    ((float4*)s  )[(size_t)warp * 32 + lane] = a2;
}

// weight pre-fusion: W[row,c] = sum_j A[row,j]*B[j,c]  (row-major),
// blockIdx == ROWS handles bias: bOut[c] = sum_j bA[j]*B[j,c] + bB[c]
__global__ void wfuse(const float* __restrict__ A, const float* __restrict__ B,
                      const float* __restrict__ bA, const float* __restrict__ bB,
                      float* __restrict__ W, float* __restrict__ bOut, int K2) {
    int c = threadIdx.x;
    if (blockIdx.x < H) {
        int row = blockIdx.x;
        float acc = 0.0f;
        for (int j = 0; j < H; j++) acc += __ldg(&A[row * H + j]) * __ldg(&B[j * K2 + c]);
        W[row * K2 + c] = acc;
    } else {
        float acc = bB[c];
        for (int j = 0; j < H; j++) acc += __ldg(&bA[j]) * __ldg(&B[j * K2 + c]);
        bOut[c] = acc;
    }
}

// ---------------- GEMM (BN fixed = 128), f32x2 packed FMA ----------------
// C[M,128] = A0@B0 (+ A1@B1) + bias;  EPI: 0=none, 1=LReLU, 2=LReLU then +=addsrc
template<bool DUAL, int EPI>
__global__ void __launch_bounds__(256) gemm_h128(
        const float* __restrict__ A0, const float* __restrict__ A1,
        const float* __restrict__ B0, const float* __restrict__ B1,
        const float* __restrict__ bias, const float* __restrict__ addsrc,
        float* __restrict__ C, int M, int K) {
    constexpr int BM = 128, BN = 128, BK = 16;
    __shared__ __align__(16) float As0[BK][BM];
    __shared__ __align__(16) float Bs0[BK][BN];
    __shared__ __align__(16) float As1[DUAL ? BK : 1][DUAL ? BM : 1];
    __shared__ __align__(16) float Bs1[DUAL ? BK : 1][DUAL ? BN : 1];

    int tid = threadIdx.x;
    int brow = blockIdx.x * BM;
    int tx = tid & 15, ty = tid >> 4;

    unsigned long long acc2[8][4];
#pragma unroll
    for (int i = 0; i < 8; i++)
#pragma unroll
        for (int j = 0; j < 4; j++) acc2[i][j] = 0ull;

    for (int k0 = 0; k0 < K; k0 += BK) {
#pragma unroll
        for (int t = tid; t < 512; t += 256) {
            // A: 128 rows x 16 cols = 512 float4
            int r = t >> 2, c4 = (t & 3) * 4;
            int row = brow + r;
            float4 v = make_float4(0, 0, 0, 0);
            if (row < M) v = *(const float4*)(A0 + (size_t)row * K + k0 + c4);
            As0[c4 + 0][r] = v.x; As0[c4 + 1][r] = v.y;
            As0[c4 + 2][r] = v.z; As0[c4 + 3][r] = v.w;
            if constexpr (DUAL) {
                float4 u = make_float4(0, 0, 0, 0);
                if (row < M) u = *(const float4*)(A1 + (size_t)row * K + k0 + c4);
                As1[c4 + 0][r] = u.x; As1[c4 + 1][r] = u.y;
                As1[c4 + 2][r] = u.z; As1[c4 + 3][r] = u.w;
            }
            // B: 16 rows x 128 cols = 512 float4
            int rb = t >> 5, cb = (t & 31) * 4;
            *(float4*)&Bs0[rb][cb] = *(const float4*)(B0 + (size_t)(k0 + rb) * BN + cb);
            if constexpr (DUAL)
                *(float4*)&Bs1[rb][cb] = *(const float4*)(B1 + (size_t)(k0 + rb) * BN + cb);
        }
        __syncthreads();
#pragma unroll
        for (int kk = 0; kk < BK; kk++) {
            {
                const float* ar = &As0[kk][ty * 8];
                const unsigned long long* bp = (const unsigned long long*)&Bs0[kk][tx * 8];
                unsigned long long b2[4];
#pragma unroll
                for (int j = 0; j < 4; j++) b2[j] = bp[j];
#pragma unroll
                for (int i = 0; i < 8; i++) {
                    float av = ar[i];
                    unsigned long long ad = pack2(av, av);
#pragma unroll
                    for (int j = 0; j < 4; j++) ffma2(acc2[i][j], ad, b2[j]);
                }
            }
            if constexpr (DUAL) {
                const float* ar = &As1[kk][ty * 8];
                const unsigned long long* bp = (const unsigned long long*)&Bs1[kk][tx * 8];
                unsigned long long b2[4];
#pragma unroll
                for (int j = 0; j < 4; j++) b2[j] = bp[j];
#pragma unroll
                for (int i = 0; i < 8; i++) {
                    float av = ar[i];
                    unsigned long long ad = pack2(av, av);
#pragma unroll
                    for (int j = 0; j < 4; j++) ffma2(acc2[i][j], ad, b2[j]);
                }
            }
        }
        __syncthreads();
    }

    // epilogue: unpack + float4 stores
#pragma unroll
    for (int i = 0; i < 8; i++) {
        int row = brow + ty * 8 + i;
        if (row >= M) break;
#pragma unroll
        for (int jj = 0; jj < 2; jj++) {
            int col = tx * 8 + jj * 4;
            float2 p0 = unpack2(acc2[i][jj * 2 + 0]);
            float2 p1 = unpack2(acc2[i][jj * 2 + 1]);
            float4 v;
            v.x = p0.x + bias[col + 0];
            v.y = p0.y + bias[col + 1];
            v.z = p1.x + bias[col + 2];
            v.w = p1.y + bias[col + 3];
            if constexpr (EPI >= 1) {
                v.x = v.x > 0.0f ? v.x : NEG_SLOPE * v.x;
                v.y = v.y > 0.0f ? v.y : NEG_SLOPE * v.y;
                v.z = v.z > 0.0f ? v.z : NEG_SLOPE * v.z;
                v.w = v.w > 0.0f ? v.w : NEG_SLOPE * v.w;
            }
            if constexpr (EPI == 2) {
                float4 o = *(const float4*)(addsrc + (size_t)row * 128 + col);
                v.x += o.x; v.y += o.y; v.z += o.z; v.w += o.w;
            }
            *(float4*)(C + (size_t)row * 128 + col) = v;
        }
    }
}

// ---------------- classifier + log_softmax (warp per row) ----------------
__global__ void __launch_bounds__(256) cls_kernel(
        const float* __restrict__ x, const float* __restrict__ W,   // W: [128, C_OUT]
        const float* __restrict__ b, float* __restrict__ out, int M) {
    __shared__ float Wt[C_OUT][128];
    __shared__ float bs[C_OUT];
    for (int i = threadIdx.x; i < 128 * C_OUT; i += 256) {
        int k = i / C_OUT, c = i % C_OUT;
        Wt[c][k] = W[i];
    }
    if (threadIdx.x < C_OUT) bs[threadIdx.x] = b[threadIdx.x];
    __syncthreads();

    int warp = threadIdx.x >> 5, lane = threadIdx.x & 31;
    int row = blockIdx.x * 8 + warp;
    if (row >= M) return;

    float xr[4];
#pragma unroll
    for (int j = 0; j < 4; j++) xr[j] = x[(size_t)row * 128 + lane + 32 * j];

    float acc[C_OUT];
#pragma unroll
    for (int c = 0; c < C_OUT; c++) {
        float a = 0.0f;
#pragma unroll
        for (int j = 0; j < 4; j++) a += xr[j] * Wt[c][lane + 32 * j];
#pragma unroll
        for (int o = 16; o > 0; o >>= 1) a += __shfl_down_sync(0xFFFFFFFFu, a, o);
        acc[c] = a;
    }
    if (lane == 0) {
        float mx = -1e30f;
#pragma unroll
        for (int c = 0; c < C_OUT; c++) { acc[c] += bs[c]; mx = fmaxf(mx, acc[c]); }
        float se = 0.0f;
#pragma unroll
        for (int c = 0; c < C_OUT; c++) se += expf(acc[c] - mx);
        float l = mx + logf(se);
#pragma unroll
        for (int c = 0; c < C_OUT; c++) out[(size_t)row * C_OUT + c] = acc[c] - l;
    }
}

// ---------------- host ----------------
static void* symaddr(const void* sym) {
    void* p = nullptr;
    cudaGetSymbolAddress(&p, sym);
    return p;
}

extern "C" void kernel_launch(void* const* d_in, const int* in_sizes, int n_in,
                              void* d_out, int out_size) {
    const float* x   = (const float*)d_in[0];
    const int*   ei  = (const int*)d_in[1];
    const float* ew  = (const float*)d_in[2];
    const float* pre_w1 = (const float*)d_in[3];  const float* pre_b1 = (const float*)d_in[4];
    const float* cw0_1  = (const float*)d_in[5];  const float* cw1_1  = (const float*)d_in[6];
    const float* cb_1   = (const float*)d_in[7];
    const float* sw_1   = (const float*)d_in[8];  const float* sb_1   = (const float*)d_in[9];
    const float* lw_1   = (const float*)d_in[10]; const float* lb_1   = (const float*)d_in[11];
    const float* pre_w2 = (const float*)d_in[12]; const float* pre_b2 = (const float*)d_in[13];
    const float* cw0_2  = (const float*)d_in[14]; const float* cw1_2  = (const float*)d_in[15];
    const float* cb_2   = (const float*)d_in[16];
    const float* sw_2   = (const float*)d_in[17]; const float* sb_2   = (const float*)d_in[18];
    const float* lw_2   = (const float*)d_in[19]; const float* lb_2   = (const float*)d_in[20];
    const float* cls_w  = (const float*)d_in[21]; const float* cls_b  = (const float*)d_in[22];
    float* out = (float*)d_out;

    int E = in_sizes[2];
    int N = in_sizes[0] / F_IN;
    const int* src = ei;
    const int* dst = ei + E;

    float* xh    = (float*)symaddr(g_xh);
    float* tx1   = (float*)symaddr(g_tx1);
    float* sbuf  = (float*)symaddr(g_s);
    float* o2    = (float*)symaddr(g_o2);
    float* tbuf  = (float*)symaddr(g_t);
    float* deg   = (float*)symaddr(g_deg);
    float* dis   = (float*)symaddr(g_dis);
    float* loopw = (float*)symaddr(g_loopw);
    float* invc  = (float*)symaddr(g_invcnt);
    float* cntf  = (float*)symaddr(g_cntf);
    int*   hist  = (int*)symaddr(g_hist);
    int*   off   = (int*)symaddr(g_off);
    int*   cur   = (int*)symaddr(g_cursor);
    int*   bsum  = (int*)symaddr(g_bsum);
    int*   esrc  = (int*)symaddr(g_esrc);
    float* enorm = (float*)symaddr(g_enorm);
    float* ewe   = (float*)symaddr(g_ewe);
    float* W12   = (float*)symaddr(g_W12);
    float* b12   = (float*)symaddr(g_b12);
    float* Wc    = (float*)symaddr(g_Wc);
    float* bc    = (float*)symaddr(g_bc);

    int eB = (E + 255) / 256;
    int nB = (N + 255) / 256;
    int nbScan = (N + 1023) / 1024;
    int gG = (N + 127) / 128;
    int aggB = (N * 32 + 255) / 256;

    // ---- fused weights (tiny) ----
    wfuse<<<H + 1, H>>>(lw_1, pre_w2, lb_1, pre_b2, W12, b12, H);
    wfuse<<<H + 1, C_OUT>>>(lw_2, cls_w, lb_2, cls_b, Wc, bc, C_OUT);

    // ---- graph-structure preprocessing (cell-independent) ----
    cudaMemsetAsync(deg,  0, (size_t)N * sizeof(float));
    cudaMemsetAsync(cntf, 0, (size_t)N * sizeof(float));
    cudaMemsetAsync(hist, 0, (size_t)N * sizeof(int));
    fill_ones<<<nB, 256>>>(loopw, N);
    edge_pass1<<<eB, 256>>>(src, dst, ew, deg, cntf, loopw, hist, E);
    node_prep<<<nB, 256>>>(deg, cntf, dis, invc, N);
    scan1<<<nbScan, 256>>>(hist, bsum, N);
    scan2<<<1, 32>>>(bsum, nbScan, off, N);
    scan3<<<nbScan, 256>>>(hist, bsum, off, cur, N);
    edge_pass2<<<eB, 256>>>(src, dst, ew, dis, cur, esrc, enorm, ewe, E);

    // ---- cell 1 (512 -> 128) ----
    gemm_h128<false, 0><<<gG, 256>>>(x, nullptr, pre_w1, nullptr, pre_b1, nullptr, xh, N, F_IN);
    aggregate<<<aggB, 256>>>(xh, off, esrc, enorm, ewe, loopw, invc, tx1, sbuf, N);
    gemm_h128<false, 1><<<gG, 256>>>(sbuf, nullptr, sw_1, nullptr, sb_1, nullptr, o2, N, H);
    gemm_h128<true, 2><<<gG, 256>>>(xh, tx1, cw0_1, cw1_1, cb_1, o2, tbuf, N, H);

    // ---- fused lin1 + pre2:  xh2 = t1 @ (lw1@pw2) + (lb1@pw2 + pb2) ----
    gemm_h128<false, 0><<<gG, 256>>>(tbuf, nullptr, W12, nullptr, b12, nullptr, xh, N, H);

    // ---- cell 2 (128 -> 128) ----
    aggregate<<<aggB, 256>>>(xh, off, esrc, enorm, ewe, loopw, invc, tx1, sbuf, N);
    gemm_h128<false, 1><<<gG, 256>>>(sbuf, nullptr, sw_2, nullptr, sb_2, nullptr, o2, N, H);
    gemm_h128<true, 2><<<gG, 256>>>(xh, tx1, cw0_2, cw1_2, cb_2, o2, tbuf, N, H);

    // ---- fused lin2 + classifier + log_softmax ----
    cls_kernel<<<(N + 7) / 8, 256>>>(tbuf, Wc, bc, out, N);
}

// round 4
// speedup vs baseline: 1.5445x; 1.2253x over previous
#include <cuda_runtime.h>
#include <cuda_bf16.h>
#include <math.h>
#include <stdint.h>

// ---------------- problem constants ----------------
#define N_MAX 40000
#define E_MAX 640000
#define F_IN  512
#define H     128
#define C_OUT 40
#define NEG_SLOPE 0.01f

// ---------------- scratch (device globals; no runtime alloc) ----------------
__device__ float g_xh [N_MAX * H];     // fp32 (aggregate input)
__device__ float g_o2 [N_MAX * H];
__device__ float g_t  [N_MAX * H];     // cheb2 output (cls input)

// bf16 hi/lo planes for tensor-core A operands
__device__ __nv_bfloat16 g_xe_h[N_MAX * F_IN];
__device__ __nv_bfloat16 g_xe_l[N_MAX * F_IN];
__device__ __nv_bfloat16 g_xh_h[N_MAX * H];
__device__ __nv_bfloat16 g_xh_l[N_MAX * H];
__device__ __nv_bfloat16 g_tx_h[N_MAX * H];
__device__ __nv_bfloat16 g_tx_l[N_MAX * H];
__device__ __nv_bfloat16 g_s_h [N_MAX * H];
__device__ __nv_bfloat16 g_s_l [N_MAX * H];
__device__ __nv_bfloat16 g_t_h [N_MAX * H];
__device__ __nv_bfloat16 g_t_l [N_MAX * H];

__device__ float g_deg   [N_MAX];
__device__ float g_dis   [N_MAX];
__device__ float g_loopw [N_MAX];
__device__ float g_invcnt[N_MAX];
__device__ float g_cntf  [N_MAX];
__device__ int   g_hist  [N_MAX];
__device__ int   g_off   [N_MAX + 1];
__device__ int   g_cursor[N_MAX];
__device__ int   g_bsum  [64];
__device__ int   g_esrc  [E_MAX];
__device__ float g_enorm [E_MAX];
__device__ float g_ewe   [E_MAX];

__device__ float g_W12[H * H];
__device__ float g_b12[H];
__device__ float g_Wc [H * C_OUT];
__device__ float g_bc [C_OUT];

// prestaged weights as [n=128][K] bf16, hi plane then lo plane
__device__ __nv_bfloat16 g_Bpre1 [2 * 128 * 512];
__device__ __nv_bfloat16 g_Bcw0_1[2 * 128 * 128];
__device__ __nv_bfloat16 g_Bcw1_1[2 * 128 * 128];
__device__ __nv_bfloat16 g_Bsw1  [2 * 128 * 128];
__device__ __nv_bfloat16 g_BW12  [2 * 128 * 128];
__device__ __nv_bfloat16 g_Bcw0_2[2 * 128 * 128];
__device__ __nv_bfloat16 g_Bcw1_2[2 * 128 * 128];
__device__ __nv_bfloat16 g_Bsw2  [2 * 128 * 128];

// ---------------- helpers ----------------
__device__ __forceinline__ uint32_t smem_u32(const void* p) {
    uint32_t a;
    asm("{ .reg .u64 t; cvta.to.shared.u64 t, %1; cvt.u32.u64 %0, t; }"
        : "=r"(a) : "l"(p));
    return a;
}
// split (a,b) fp32 -> packed bf16x2 hi (lo-half = a) + packed bf16x2 residual
__device__ __forceinline__ void split2(float a, float b, uint32_t& h, uint32_t& l) {
    asm("cvt.rn.bf16x2.f32 %0,%1,%2;" : "=r"(h) : "f"(b), "f"(a));
    float fa = __uint_as_float(h << 16);
    float fb = __uint_as_float(h & 0xFFFF0000u);
    float la = a - fa, lb = b - fb;
    asm("cvt.rn.bf16x2.f32 %0,%1,%2;" : "=r"(l) : "f"(lb), "f"(la));
}
__device__ __forceinline__ void ldm4(uint32_t* r, uint32_t addr) {
    asm volatile("ldmatrix.sync.aligned.m8n8.x4.shared.b16 {%0,%1,%2,%3},[%4];"
                 : "=r"(r[0]), "=r"(r[1]), "=r"(r[2]), "=r"(r[3]) : "r"(addr));
}
__device__ __forceinline__ void mma16816(float* d, const uint32_t* a, uint32_t b0, uint32_t b1) {
    asm volatile("mma.sync.aligned.m16n8k16.row.col.f32.bf16.bf16.f32 "
                 "{%0,%1,%2,%3},{%4,%5,%6,%7},{%8,%9},{%0,%1,%2,%3};"
                 : "+f"(d[0]), "+f"(d[1]), "+f"(d[2]), "+f"(d[3])
                 : "r"(a[0]), "r"(a[1]), "r"(a[2]), "r"(a[3]), "r"(b0), "r"(b1));
}

// ---------------- small utility kernels ----------------
__global__ void fill_ones(float* p, int n) {
    int i = blockIdx.x * blockDim.x + threadIdx.x;
    if (i < n) p[i] = 1.0f;
}

__global__ void convert_split(const float* __restrict__ in,
                              __nv_bfloat16* __restrict__ hi,
                              __nv_bfloat16* __restrict__ lo, int total4) {
    int i = blockIdx.x * blockDim.x + threadIdx.x;
    if (i >= total4) return;
    float4 v = __ldg(&((const float4*)in)[i]);
    uint32_t h0, l0, h1, l1;
    split2(v.x, v.y, h0, l0);
    split2(v.z, v.w, h1, l1);
    ((uint2*)hi)[i] = make_uint2(h0, h1);
    ((uint2*)lo)[i] = make_uint2(l0, l1);
}

__global__ void edge_pass1(const int* __restrict__ src, const int* __restrict__ dst,
                           const float* __restrict__ w,
                           float* __restrict__ deg, float* __restrict__ cntf,
                           float* __restrict__ loopw, int* __restrict__ hist, int E) {
    int i = blockIdx.x * blockDim.x + threadIdx.x;
    if (i >= E) return;
    int s = src[i], d = dst[i];
    float wt = w[i];
    if (s == d) {
        loopw[s] = wt;
    } else {
        atomicAdd(&deg[s], wt);
        atomicAdd(&cntf[d], 1.0f);
    }
    atomicAdd(&hist[d], 1);
}

__global__ void node_prep(const float* __restrict__ deg, const float* __restrict__ cntf,
                          float* __restrict__ dis, float* __restrict__ invcnt, int N) {
    int i = blockIdx.x * blockDim.x + threadIdx.x;
    if (i >= N) return;
    float dg = deg[i];
    dis[i]    = (dg > 0.0f) ? rsqrtf(dg) : 0.0f;
    invcnt[i] = 1.0f / (cntf[i] + 1.0f);
}

__global__ void scan1(const int* __restrict__ hist, int* __restrict__ bsum, int n) {
    __shared__ int sh[256];
    int base = blockIdx.x * 1024;
    int s = 0;
#pragma unroll
    for (int j = 0; j < 4; j++) {
        int i = base + threadIdx.x + j * 256;
        s += (i < n) ? hist[i] : 0;
    }
    sh[threadIdx.x] = s;
    __syncthreads();
    for (int o = 128; o > 0; o >>= 1) {
        if (threadIdx.x < o) sh[threadIdx.x] += sh[threadIdx.x + o];
        __syncthreads();
    }
    if (threadIdx.x == 0) bsum[blockIdx.x] = sh[0];
}
__global__ void scan2(int* __restrict__ bsum, int nb, int* __restrict__ off, int n) {
    if (threadIdx.x == 0) {
        int run = 0;
        for (int i = 0; i < nb; i++) { int v = bsum[i]; bsum[i] = run; run += v; }
        off[n] = run;
    }
}
__global__ void scan3(const int* __restrict__ hist, const int* __restrict__ bsum,
                      int* __restrict__ off, int* __restrict__ cursor, int n) {
    __shared__ int sh[256];
    int base = blockIdx.x * 1024 + threadIdx.x * 4;
    int v[4]; int s = 0;
#pragma unroll
    for (int j = 0; j < 4; j++) {
        int i = base + j;
        v[j] = (i < n) ? hist[i] : 0;
        s += v[j];
    }
    sh[threadIdx.x] = s;
    __syncthreads();
    for (int o = 1; o < 256; o <<= 1) {
        int t = (threadIdx.x >= o) ? sh[threadIdx.x - o] : 0;
        __syncthreads();
        sh[threadIdx.x] += t;
        __syncthreads();
    }
    int run = bsum[blockIdx.x] + sh[threadIdx.x] - s;
#pragma unroll
    for (int j = 0; j < 4; j++) {
        int i = base + j;
        if (i < n) { off[i] = run; cursor[i] = run; }
        run += v[j];
    }
}

__global__ void edge_pass2(const int* __restrict__ src, const int* __restrict__ dst,
                           const float* __restrict__ w, const float* __restrict__ dis,
                           int* __restrict__ cursor,
                           int* __restrict__ esrc, float* __restrict__ enorm,
                           float* __restrict__ ewe, int E) {
    int i = blockIdx.x * blockDim.x + threadIdx.x;
    if (i >= E) return;
    int s = src[i], d = dst[i];
    float wt = w[i];
    float wc = (s == d) ? 0.0f : wt;
    float nm = -dis[s] * wc * dis[d];
    int pos = atomicAdd(&cursor[d], 1);
    esrc[pos]  = s;
    enorm[pos] = nm;
    ewe[pos]   = wc;
}

// warp-per-node CSR aggregation with fused sage-mean.
// Outputs bf16 hi/lo planes ONLY (consumers are tensor GEMMs).
__global__ void __launch_bounds__(256) aggregate(
        const float* __restrict__ xh, const int* __restrict__ off,
        const int* __restrict__ esrc, const float* __restrict__ enorm,
        const float* __restrict__ ewe,
        const float* __restrict__ loopw, const float* __restrict__ invcnt,
        __nv_bfloat16* __restrict__ txh, __nv_bfloat16* __restrict__ txl,
        __nv_bfloat16* __restrict__ sh,  __nv_bfloat16* __restrict__ sl, int N) {
    int warp = (blockIdx.x * blockDim.x + threadIdx.x) >> 5;
    int lane = threadIdx.x & 31;
    if (warp >= N) return;
    int beg = off[warp], end = off[warp + 1];
    const float4* xh4 = (const float4*)xh;
    float4 a1 = make_float4(0, 0, 0, 0);
    float4 a2 = make_float4(0, 0, 0, 0);
    for (int j = beg; j < end; j++) {
        int sn = __ldg(&esrc[j]);
        float nm = __ldg(&enorm[j]);
        float we = __ldg(&ewe[j]);
        float4 v = __ldg(&xh4[(size_t)sn * 32 + lane]);
        a1.x += nm * v.x; a1.y += nm * v.y; a1.z += nm * v.z; a1.w += nm * v.w;
        a2.x += we * v.x; a2.y += we * v.y; a2.z += we * v.z; a2.w += we * v.w;
    }
    float lw = __ldg(&loopw[warp]);
    float ic = __ldg(&invcnt[warp]);
    float4 xv = __ldg(&xh4[(size_t)warp * 32 + lane]);
    a2.x = (a2.x + lw * xv.x) * ic;
    a2.y = (a2.y + lw * xv.y) * ic;
    a2.z = (a2.z + lw * xv.z) * ic;
    a2.w = (a2.w + lw * xv.w) * ic;
    uint32_t h0, l0, h1, l1;
    int idx = warp * 32 + lane;   // uint2 index into planes
    split2(a1.x, a1.y, h0, l0);
    split2(a1.z, a1.w, h1, l1);
    ((uint2*)txh)[idx] = make_uint2(h0, h1);
    ((uint2*)txl)[idx] = make_uint2(l0, l1);
    split2(a2.x, a2.y, h0, l0);
    split2(a2.z, a2.w, h1, l1);
    ((uint2*)sh)[idx] = make_uint2(h0, h1);
    ((uint2*)sl)[idx] = make_uint2(l0, l1);
}

// weight pre-fusion: W = A@B (row-major), bias fold
__global__ void wfuse(const float* __restrict__ A, const float* __restrict__ B,
                      const float* __restrict__ bA, const float* __restrict__ bB,
                      float* __restrict__ W, float* __restrict__ bOut, int K2) {
    int c = threadIdx.x;
    if (blockIdx.x < H) {
        int row = blockIdx.x;
        float acc = 0.0f;
        for (int j = 0; j < H; j++) acc += __ldg(&A[row * H + j]) * __ldg(&B[j * K2 + c]);
        W[row * K2 + c] = acc;
    } else {
        float acc = bB[c];
        for (int j = 0; j < H; j++) acc += __ldg(&bA[j]) * __ldg(&B[j * K2 + c]);
        bOut[c] = acc;
    }
}

// prestage weight W[K][128] -> planes [n][K]: hi then lo
__global__ void prestage(const float* __restrict__ W, __nv_bfloat16* __restrict__ out, int K) {
    int total = 128 * K;
    for (int i = blockIdx.x * blockDim.x + threadIdx.x; i < total;
         i += gridDim.x * blockDim.x) {
        int n = i / K, k = i - n * K;
        float v = __ldg(&W[(size_t)k * 128 + n]);
        __nv_bfloat16 h = __float2bfloat16(v);
        out[i] = h;
        out[total + i] = __float2bfloat16(v - __bfloat162float(h));
    }
}

// ---------------- HMMA GEMM: C[M,128] = A0@W0 (+A1@W1) + bias ----------------
// split-bf16 3-product. A supplied as bf16 hi/lo planes [M][K].
// B planes [128][K] hi then lo. EPI: 0 none, 1 LReLU, 2 LReLU+addsrc.
// EM: 0 fp32 only, 1 fp32+planes, 2 planes only.
template<bool DUAL, int EPI, int EM>
__global__ void __launch_bounds__(256, 2) tgemm(
        const __nv_bfloat16* __restrict__ Ah0, const __nv_bfloat16* __restrict__ Al0,
        const __nv_bfloat16* __restrict__ Ah1, const __nv_bfloat16* __restrict__ Al1,
        const __nv_bfloat16* __restrict__ B0, const __nv_bfloat16* __restrict__ B1,
        const float* __restrict__ bias, const float* __restrict__ addsrc,
        float* __restrict__ Cf, __nv_bfloat16* __restrict__ Ch, __nv_bfloat16* __restrict__ Cl,
        int M, int K) {
    __shared__ __align__(16) __nv_bfloat16 sA[2][128 * 24];   // [hi/lo][row][24]
    __shared__ __align__(16) __nv_bfloat16 sB[2][128 * 24];

    int tid = threadIdx.x, lane = tid & 31, warp = tid >> 5;
    int warp_m = warp & 3, warp_n = warp >> 2;
    int brow = blockIdx.x * 128;

    uint32_t uA0 = smem_u32(sA[0]), uA1 = smem_u32(sA[1]);
    uint32_t uB0 = smem_u32(sB[0]), uB1 = smem_u32(sB[1]);

    // ldmatrix per-lane offsets
    int lr = lane & 7;
    int a_off = (((warp_m * 32) + ((lane >> 3) & 1) * 8 + lr) * 24 + (lane >> 4) * 8) * 2;
    int b_off = (((warp_n * 64) + ((lane >> 4) & 1) * 8 + lr) * 24 + ((lane >> 3) & 1) * 8) * 2;

    float acc[2][8][4];
#pragma unroll
    for (int mi = 0; mi < 2; mi++)
#pragma unroll
        for (int ni = 0; ni < 8; ni++)
#pragma unroll
            for (int c = 0; c < 4; c++) acc[mi][ni][c] = 0.0f;

    int crow = tid >> 1, half = tid & 1;
    int grow = brow + crow;
    bool rowok = grow < M;
    int nk = K >> 4;
    int nstream = DUAL ? 2 : 1;

    for (int s = 0; s < nstream; s++) {
        const __nv_bfloat16* Ah = s ? Ah1 : Ah0;
        const __nv_bfloat16* Al = s ? Al1 : Al0;
        const __nv_bfloat16* Bp = s ? B1 : B0;
        for (int kc = 0; kc < nk; kc++) {
            int k0 = kc << 4;
            __syncthreads();
            // stage A (hi/lo) and B (hi/lo) 16-K slabs
            {
                uint4 z = make_uint4(0, 0, 0, 0);
                uint4 vh = z, vl = z;
                if (rowok) {
                    vh = *(const uint4*)(Ah + (size_t)grow * K + k0 + half * 8);
                    vl = *(const uint4*)(Al + (size_t)grow * K + k0 + half * 8);
                }
                *(uint4*)(&sA[0][crow * 24 + half * 8]) = vh;
                *(uint4*)(&sA[1][crow * 24 + half * 8]) = vl;
                uint4 bh = *(const uint4*)(Bp + (size_t)crow * K + k0 + half * 8);
                uint4 bl = *(const uint4*)(Bp + (size_t)128 * K + (size_t)crow * K + k0 + half * 8);
                *(uint4*)(&sB[0][crow * 24 + half * 8]) = bh;
                *(uint4*)(&sB[1][crow * 24 + half * 8]) = bl;
            }
            __syncthreads();

            uint32_t afr[2][4], bfr[4][4];
            // B hi
#pragma unroll
            for (int nj = 0; nj < 4; nj++) ldm4(bfr[nj], uB0 + b_off + nj * 16 * 48);
            // A hi -> (Ahi,Bhi)
#pragma unroll
            for (int mi = 0; mi < 2; mi++) ldm4(afr[mi], uA0 + a_off + mi * 16 * 48);
#pragma unroll
            for (int mi = 0; mi < 2; mi++)
#pragma unroll
                for (int ni = 0; ni < 8; ni++)
                    mma16816(acc[mi][ni], afr[mi], bfr[ni >> 1][(ni & 1) * 2],
                             bfr[ni >> 1][(ni & 1) * 2 + 1]);
            // A lo -> (Alo,Bhi)
#pragma unroll
            for (int mi = 0; mi < 2; mi++) ldm4(afr[mi], uA1 + a_off + mi * 16 * 48);
#pragma unroll
            for (int mi = 0; mi < 2; mi++)
#pragma unroll
                for (int ni = 0; ni < 8; ni++)
                    mma16816(acc[mi][ni], afr[mi], bfr[ni >> 1][(ni & 1) * 2],
                             bfr[ni >> 1][(ni & 1) * 2 + 1]);
            // B lo + A hi -> (Ahi,Blo)
#pragma unroll
            for (int nj = 0; nj < 4; nj++) ldm4(bfr[nj], uB1 + b_off + nj * 16 * 48);
#pragma unroll
            for (int mi = 0; mi < 2; mi++) ldm4(afr[mi], uA0 + a_off + mi * 16 * 48);
#pragma unroll
            for (int mi = 0; mi < 2; mi++)
#pragma unroll
                for (int ni = 0; ni < 8; ni++)
                    mma16816(acc[mi][ni], afr[mi], bfr[ni >> 1][(ni & 1) * 2],
                             bfr[ni >> 1][(ni & 1) * 2 + 1]);
        }
    }

    // epilogue
    int g = lane >> 2, tg = lane & 3;
#pragma unroll
    for (int mi = 0; mi < 2; mi++) {
#pragma unroll
        for (int h = 0; h < 2; h++) {
            int row = brow + warp_m * 32 + mi * 16 + h * 8 + g;
            if (row >= M) continue;
#pragma unroll
            for (int ni = 0; ni < 8; ni++) {
                int col = warp_n * 64 + ni * 8 + tg * 2;
                float v0 = acc[mi][ni][h * 2 + 0] + __ldg(&bias[col]);
                float v1 = acc[mi][ni][h * 2 + 1] + __ldg(&bias[col + 1]);
                if (EPI >= 1) {
                    v0 = v0 > 0.0f ? v0 : NEG_SLOPE * v0;
                    v1 = v1 > 0.0f ? v1 : NEG_SLOPE * v1;
                }
                if (EPI == 2) {
                    float2 o = *(const float2*)(addsrc + (size_t)row * 128 + col);
                    v0 += o.x; v1 += o.y;
                }
                if (EM != 2)
                    *(float2*)(Cf + (size_t)row * 128 + col) = make_float2(v0, v1);
                if (EM >= 1) {
                    uint32_t hh, ll;
                    split2(v0, v1, hh, ll);
                    *(uint32_t*)(Ch + (size_t)row * 128 + col) = hh;
                    *(uint32_t*)(Cl + (size_t)row * 128 + col) = ll;
                }
            }
        }
    }
}

// ---------------- classifier + log_softmax (warp per row) ----------------
__global__ void __launch_bounds__(256) cls_kernel(
        const float* __restrict__ x, const float* __restrict__ W,
        const float* __restrict__ b, float* __restrict__ out, int M) {
    __shared__ float Wt[C_OUT][128];
    __shared__ float bs[C_OUT];
    for (int i = threadIdx.x; i < 128 * C_OUT; i += 256) {
        int k = i / C_OUT, c = i % C_OUT;
        Wt[c][k] = W[i];
    }
    if (threadIdx.x < C_OUT) bs[threadIdx.x] = b[threadIdx.x];
    __syncthreads();

    int warp = threadIdx.x >> 5, lane = threadIdx.x & 31;
    int row = blockIdx.x * 8 + warp;
    if (row >= M) return;

    float xr[4];
#pragma unroll
    for (int j = 0; j < 4; j++) xr[j] = x[(size_t)row * 128 + lane + 32 * j];

    float acc[C_OUT];
#pragma unroll
    for (int c = 0; c < C_OUT; c++) {
        float a = 0.0f;
#pragma unroll
        for (int j = 0; j < 4; j++) a += xr[j] * Wt[c][lane + 32 * j];
#pragma unroll
        for (int o = 16; o > 0; o >>= 1) a += __shfl_down_sync(0xFFFFFFFFu, a, o);
        acc[c] = a;
    }
    if (lane == 0) {
        float mx = -1e30f;
#pragma unroll
        for (int c = 0; c < C_OUT; c++) { acc[c] += bs[c]; mx = fmaxf(mx, acc[c]); }
        float se = 0.0f;
#pragma unroll
        for (int c = 0; c < C_OUT; c++) se += expf(acc[c] - mx);
        float l = mx + logf(se);
#pragma unroll
        for (int c = 0; c < C_OUT; c++) out[(size_t)row * C_OUT + c] = acc[c] - l;
    }
}

// ---------------- host ----------------
static void* symaddr(const void* sym) {
    void* p = nullptr;
    cudaGetSymbolAddress(&p, sym);
    return p;
}

extern "C" void kernel_launch(void* const* d_in, const int* in_sizes, int n_in,
                              void* d_out, int out_size) {
    const float* x   = (const float*)d_in[0];
    const int*   ei  = (const int*)d_in[1];
    const float* ew  = (const float*)d_in[2];
    const float* pre_w1 = (const float*)d_in[3];  const float* pre_b1 = (const float*)d_in[4];
    const float* cw0_1  = (const float*)d_in[5];  const float* cw1_1  = (const float*)d_in[6];
    const float* cb_1   = (const float*)d_in[7];
    const float* sw_1   = (const float*)d_in[8];  const float* sb_1   = (const float*)d_in[9];
    const float* lw_1   = (const float*)d_in[10]; const float* lb_1   = (const float*)d_in[11];
    const float* pre_w2 = (const float*)d_in[12]; const float* pre_b2 = (const float*)d_in[13];
    const float* cw0_2  = (const float*)d_in[14]; const float* cw1_2  = (const float*)d_in[15];
    const float* cb_2   = (const float*)d_in[16];
    const float* sw_2   = (const float*)d_in[17]; const float* sb_2   = (const float*)d_in[18];
    const float* lw_2   = (const float*)d_in[19]; const float* lb_2   = (const float*)d_in[20];
    const float* cls_w  = (const float*)d_in[21]; const float* cls_b  = (const float*)d_in[22];
    float* out = (float*)d_out;

    int E = in_sizes[2];
    int N = in_sizes[0] / F_IN;
    const int* src = ei;
    const int* dst = ei + E;

    float* xh    = (float*)symaddr(g_xh);
    float* o2    = (float*)symaddr(g_o2);
    float* tbuf  = (float*)symaddr(g_t);
    float* deg   = (float*)symaddr(g_deg);
    float* dis   = (float*)symaddr(g_dis);
    float* loopw = (float*)symaddr(g_loopw);
    float* invc  = (float*)symaddr(g_invcnt);
    float* cntf  = (float*)symaddr(g_cntf);
    int*   hist  = (int*)symaddr(g_hist);
    int*   off   = (int*)symaddr(g_off);
    int*   cur   = (int*)symaddr(g_cursor);
    int*   bsum  = (int*)symaddr(g_bsum);
    int*   esrc  = (int*)symaddr(g_esrc);
    float* enorm = (float*)symaddr(g_enorm);
    float* ewe   = (float*)symaddr(g_ewe);
    float* W12   = (float*)symaddr(g_W12);
    float* b12   = (float*)symaddr(g_b12);
    float* Wc    = (float*)symaddr(g_Wc);
    float* bc    = (float*)symaddr(g_bc);

    __nv_bfloat16* xe_h = (__nv_bfloat16*)symaddr(g_xe_h);
    __nv_bfloat16* xe_l = (__nv_bfloat16*)symaddr(g_xe_l);
    __nv_bfloat16* xh_h = (__nv_bfloat16*)symaddr(g_xh_h);
    __nv_bfloat16* xh_l = (__nv_bfloat16*)symaddr(g_xh_l);
    __nv_bfloat16* tx_h = (__nv_bfloat16*)symaddr(g_tx_h);
    __nv_bfloat16* tx_l = (__nv_bfloat16*)symaddr(g_tx_l);
    __nv_bfloat16* s_h  = (__nv_bfloat16*)symaddr(g_s_h);
    __nv_bfloat16* s_l  = (__nv_bfloat16*)symaddr(g_s_l);
    __nv_bfloat16* t_h  = (__nv_bfloat16*)symaddr(g_t_h);
    __nv_bfloat16* t_l  = (__nv_bfloat16*)symaddr(g_t_l);

    __nv_bfloat16* Bpre1  = (__nv_bfloat16*)symaddr(g_Bpre1);
    __nv_bfloat16* Bcw0_1 = (__nv_bfloat16*)symaddr(g_Bcw0_1);
    __nv_bfloat16* Bcw1_1 = (__nv_bfloat16*)symaddr(g_Bcw1_1);
    __nv_bfloat16* Bsw1   = (__nv_bfloat16*)symaddr(g_Bsw1);
    __nv_bfloat16* BW12   = (__nv_bfloat16*)symaddr(g_BW12);
    __nv_bfloat16* Bcw0_2 = (__nv_bfloat16*)symaddr(g_Bcw0_2);
    __nv_bfloat16* Bcw1_2 = (__nv_bfloat16*)symaddr(g_Bcw1_2);
    __nv_bfloat16* Bsw2   = (__nv_bfloat16*)symaddr(g_Bsw2);

    int eB = (E + 255) / 256;
    int nB = (N + 255) / 256;
    int nbScan = (N + 1023) / 1024;
    int gG = (N + 127) / 128;
    int aggB = (N * 32 + 255) / 256;

    // ---- weight fusion + prestaging ----
    wfuse<<<H + 1, H>>>(lw_1, pre_w2, lb_1, pre_b2, W12, b12, H);
    wfuse<<<H + 1, C_OUT>>>(lw_2, cls_w, lb_2, cls_b, Wc, bc, C_OUT);
    prestage<<<64, 256>>>(pre_w1, Bpre1, 512);
    prestage<<<16, 256>>>(cw0_1, Bcw0_1, 128);
    prestage<<<16, 256>>>(cw1_1, Bcw1_1, 128);
    prestage<<<16, 256>>>(sw_1,  Bsw1, 128);
    prestage<<<16, 256>>>(W12,   BW12, 128);
    prestage<<<16, 256>>>(cw0_2, Bcw0_2, 128);
    prestage<<<16, 256>>>(cw1_2, Bcw1_2, 128);
    prestage<<<16, 256>>>(sw_2,  Bsw2, 128);

    // ---- one-time input split ----
    int total4 = N * F_IN / 4;
    convert_split<<<(total4 + 255) / 256, 256>>>(x, xe_h, xe_l, total4);

    // ---- graph-structure preprocessing ----
    cudaMemsetAsync(deg,  0, (size_t)N * sizeof(float));
    cudaMemsetAsync(cntf, 0, (size_t)N * sizeof(float));
    cudaMemsetAsync(hist, 0, (size_t)N * sizeof(int));
    fill_ones<<<nB, 256>>>(loopw, N);
    edge_pass1<<<eB, 256>>>(src, dst, ew, deg, cntf, loopw, hist, E);
    node_prep<<<nB, 256>>>(deg, cntf, dis, invc, N);
    scan1<<<nbScan, 256>>>(hist, bsum, N);
    scan2<<<1, 32>>>(bsum, nbScan, off, N);
    scan3<<<nbScan, 256>>>(hist, bsum, off, cur, N);
    edge_pass2<<<eB, 256>>>(src, dst, ew, dis, cur, esrc, enorm, ewe, E);

    // ---- cell 1 (512 -> 128) ----
    tgemm<false, 0, 1><<<gG, 256>>>(xe_h, xe_l, nullptr, nullptr, Bpre1, nullptr,
                                    pre_b1, nullptr, xh, xh_h, xh_l, N, 512);
    aggregate<<<aggB, 256>>>(xh, off, esrc, enorm, ewe, loopw, invc,
                             tx_h, tx_l, s_h, s_l, N);
    tgemm<false, 1, 0><<<gG, 256>>>(s_h, s_l, nullptr, nullptr, Bsw1, nullptr,
                                    sb_1, nullptr, o2, nullptr, nullptr, N, 128);
    tgemm<true, 2, 2><<<gG, 256>>>(xh_h, xh_l, tx_h, tx_l, Bcw0_1, Bcw1_1,
                                   cb_1, o2, nullptr, t_h, t_l, N, 128);

    // ---- fused lin1+pre2 ----
    tgemm<false, 0, 1><<<gG, 256>>>(t_h, t_l, nullptr, nullptr, BW12, nullptr,
                                    b12, nullptr, xh, xh_h, xh_l, N, 128);

    // ---- cell 2 (128 -> 128) ----
    aggregate<<<aggB, 256>>>(xh, off, esrc, enorm, ewe, loopw, invc,
                             tx_h, tx_l, s_h, s_l, N);
    tgemm<false, 1, 0><<<gG, 256>>>(s_h, s_l, nullptr, nullptr, Bsw2, nullptr,
                                    sb_2, nullptr, o2, nullptr, nullptr, N, 128);
    tgemm<true, 2, 0><<<gG, 256>>>(xh_h, xh_l, tx_h, tx_l, Bcw0_2, Bcw1_2,
                                   cb_2, o2, tbuf, nullptr, nullptr, N, 128);

    // ---- fused lin2 + classifier + log_softmax ----
    cls_kernel<<<(N + 7) / 8, 256>>>(tbuf, Wc, bc, out, N);
}

// round 5
// speedup vs baseline: 1.6497x; 1.0681x over previous
#include <cuda_runtime.h>
#include <cuda_bf16.h>
#include <math.h>
#include <stdint.h>

// ---------------- problem constants ----------------
#define N_MAX 40000
#define E_MAX 640000
#define F_IN  512
#define H     128
#define C_OUT 40
#define NEG_SLOPE 0.01f

// ---------------- scratch (device globals; no runtime alloc) ----------------
__device__ float g_xh [N_MAX * H];     // fp32 (aggregate input)
__device__ float g_o2 [N_MAX * H];
__device__ float g_t  [N_MAX * H];     // cheb2 output (cls input)

// bf16 hi/lo planes for tensor-core A operands
__device__ __nv_bfloat16 g_xe_h[N_MAX * F_IN];
__device__ __nv_bfloat16 g_xe_l[N_MAX * F_IN];
__device__ __nv_bfloat16 g_xh_h[N_MAX * H];
__device__ __nv_bfloat16 g_xh_l[N_MAX * H];
__device__ __nv_bfloat16 g_tx_h[N_MAX * H];
__device__ __nv_bfloat16 g_tx_l[N_MAX * H];
__device__ __nv_bfloat16 g_s_h [N_MAX * H];
__device__ __nv_bfloat16 g_s_l [N_MAX * H];
__device__ __nv_bfloat16 g_t_h [N_MAX * H];
__device__ __nv_bfloat16 g_t_l [N_MAX * H];

__device__ float g_deg   [N_MAX];
__device__ float g_dis   [N_MAX];
__device__ float g_loopw [N_MAX];
__device__ float g_invcnt[N_MAX];
__device__ float g_cntf  [N_MAX];
__device__ int   g_hist  [N_MAX];
__device__ int   g_off   [N_MAX + 1];
__device__ int   g_cursor[N_MAX];
__device__ int   g_bsum  [64];
__device__ int   g_esrc  [E_MAX];
__device__ float g_enorm [E_MAX];
__device__ float g_ewe   [E_MAX];

__device__ float g_W12[H * H];
__device__ float g_b12[H];
__device__ float g_Wc [H * C_OUT];
__device__ float g_bc [C_OUT];

// prestaged weights as [n=128][K] bf16, hi plane then lo plane
__device__ __nv_bfloat16 g_Bpre1 [2 * 128 * 512];
__device__ __nv_bfloat16 g_Bcw0_1[2 * 128 * 128];
__device__ __nv_bfloat16 g_Bcw1_1[2 * 128 * 128];
__device__ __nv_bfloat16 g_Bsw1  [2 * 128 * 128];
__device__ __nv_bfloat16 g_BW12  [2 * 128 * 128];
__device__ __nv_bfloat16 g_Bcw0_2[2 * 128 * 128];
__device__ __nv_bfloat16 g_Bcw1_2[2 * 128 * 128];
__device__ __nv_bfloat16 g_Bsw2  [2 * 128 * 128];

// ---------------- helpers ----------------
__device__ __forceinline__ uint32_t smem_u32(const void* p) {
    uint32_t a;
    asm("{ .reg .u64 t; cvta.to.shared.u64 t, %1; cvt.u32.u64 %0, t; }"
        : "=r"(a) : "l"(p));
    return a;
}
__device__ __forceinline__ void split2(float a, float b, uint32_t& h, uint32_t& l) {
    asm("cvt.rn.bf16x2.f32 %0,%1,%2;" : "=r"(h) : "f"(b), "f"(a));
    float fa = __uint_as_float(h << 16);
    float fb = __uint_as_float(h & 0xFFFF0000u);
    float la = a - fa, lb = b - fb;
    asm("cvt.rn.bf16x2.f32 %0,%1,%2;" : "=r"(l) : "f"(lb), "f"(la));
}
__device__ __forceinline__ void ldm4(uint32_t* r, uint32_t addr) {
    asm volatile("ldmatrix.sync.aligned.m8n8.x4.shared.b16 {%0,%1,%2,%3},[%4];"
                 : "=r"(r[0]), "=r"(r[1]), "=r"(r[2]), "=r"(r[3]) : "r"(addr));
}
__device__ __forceinline__ void mma16816(float* d, const uint32_t* a, uint32_t b0, uint32_t b1) {
    asm volatile("mma.sync.aligned.m16n8k16.row.col.f32.bf16.bf16.f32 "
                 "{%0,%1,%2,%3},{%4,%5,%6,%7},{%8,%9},{%0,%1,%2,%3};"
                 : "+f"(d[0]), "+f"(d[1]), "+f"(d[2]), "+f"(d[3])
                 : "r"(a[0]), "r"(a[1]), "r"(a[2]), "r"(a[3]), "r"(b0), "r"(b1));
}
__device__ __forceinline__ void cp16(uint32_t dst, const void* src, int szbytes) {
    asm volatile("cp.async.cg.shared.global [%0],[%1],16,%2;"
                 :: "r"(dst), "l"(src), "r"(szbytes));
}
__device__ __forceinline__ void cp_commit_wait() {
    asm volatile("cp.async.commit_group;");
    asm volatile("cp.async.wait_group 0;");
}

// ---------------- small utility kernels ----------------
__global__ void fill_ones(float* p, int n) {
    int i = blockIdx.x * blockDim.x + threadIdx.x;
    if (i < n) p[i] = 1.0f;
}

__global__ void convert_split(const float* __restrict__ in,
                              __nv_bfloat16* __restrict__ hi,
                              __nv_bfloat16* __restrict__ lo, int total4) {
    int i = blockIdx.x * blockDim.x + threadIdx.x;
    if (i >= total4) return;
    float4 v = __ldg(&((const float4*)in)[i]);
    uint32_t h0, l0, h1, l1;
    split2(v.x, v.y, h0, l0);
    split2(v.z, v.w, h1, l1);
    ((uint2*)hi)[i] = make_uint2(h0, h1);
    ((uint2*)lo)[i] = make_uint2(l0, l1);
}

__global__ void edge_pass1(const int* __restrict__ src, const int* __restrict__ dst,
                           const float* __restrict__ w,
                           float* __restrict__ deg, float* __restrict__ cntf,
                           float* __restrict__ loopw, int* __restrict__ hist, int E) {
    int i = blockIdx.x * blockDim.x + threadIdx.x;
    if (i >= E) return;
    int s = src[i], d = dst[i];
    float wt = w[i];
    if (s == d) {
        loopw[s] = wt;
    } else {
        atomicAdd(&deg[s], wt);
        atomicAdd(&cntf[d], 1.0f);
    }
    atomicAdd(&hist[d], 1);
}

__global__ void node_prep(const float* __restrict__ deg, const float* __restrict__ cntf,
                          float* __restrict__ dis, float* __restrict__ invcnt, int N) {
    int i = blockIdx.x * blockDim.x + threadIdx.x;
    if (i >= N) return;
    float dg = deg[i];
    dis[i]    = (dg > 0.0f) ? rsqrtf(dg) : 0.0f;
    invcnt[i] = 1.0f / (cntf[i] + 1.0f);
}

__global__ void scan1(const int* __restrict__ hist, int* __restrict__ bsum, int n) {
    __shared__ int sh[256];
    int base = blockIdx.x * 1024;
    int s = 0;
#pragma unroll
    for (int j = 0; j < 4; j++) {
        int i = base + threadIdx.x + j * 256;
        s += (i < n) ? hist[i] : 0;
    }
    sh[threadIdx.x] = s;
    __syncthreads();
    for (int o = 128; o > 0; o >>= 1) {
        if (threadIdx.x < o) sh[threadIdx.x] += sh[threadIdx.x + o];
        __syncthreads();
    }
    if (threadIdx.x == 0) bsum[blockIdx.x] = sh[0];
}
__global__ void scan2(int* __restrict__ bsum, int nb, int* __restrict__ off, int n) {
    if (threadIdx.x == 0) {
        int run = 0;
        for (int i = 0; i < nb; i++) { int v = bsum[i]; bsum[i] = run; run += v; }
        off[n] = run;
    }
}
__global__ void scan3(const int* __restrict__ hist, const int* __restrict__ bsum,
                      int* __restrict__ off, int* __restrict__ cursor, int n) {
    __shared__ int sh[256];
    int base = blockIdx.x * 1024 + threadIdx.x * 4;
    int v[4]; int s = 0;
#pragma unroll
    for (int j = 0; j < 4; j++) {
        int i = base + j;
        v[j] = (i < n) ? hist[i] : 0;
        s += v[j];
    }
    sh[threadIdx.x] = s;
    __syncthreads();
    for (int o = 1; o < 256; o <<= 1) {
        int t = (threadIdx.x >= o) ? sh[threadIdx.x - o] : 0;
        __syncthreads();
        sh[threadIdx.x] += t;
        __syncthreads();
    }
    int run = bsum[blockIdx.x] + sh[threadIdx.x] - s;
#pragma unroll
    for (int j = 0; j < 4; j++) {
        int i = base + j;
        if (i < n) { off[i] = run; cursor[i] = run; }
        run += v[j];
    }
}

__global__ void edge_pass2(const int* __restrict__ src, const int* __restrict__ dst,
                           const float* __restrict__ w, const float* __restrict__ dis,
                           int* __restrict__ cursor,
                           int* __restrict__ esrc, float* __restrict__ enorm,
                           float* __restrict__ ewe, int E) {
    int i = blockIdx.x * blockDim.x + threadIdx.x;
    if (i >= E) return;
    int s = src[i], d = dst[i];
    float wt = w[i];
    float wc = (s == d) ? 0.0f : wt;
    float nm = -dis[s] * wc * dis[d];
    int pos = atomicAdd(&cursor[d], 1);
    esrc[pos]  = s;
    enorm[pos] = nm;
    ewe[pos]   = wc;
}

// warp-per-node CSR aggregation with fused sage-mean; emits bf16 hi/lo planes
__global__ void __launch_bounds__(256) aggregate(
        const float* __restrict__ xh, const int* __restrict__ off,
        const int* __restrict__ esrc, const float* __restrict__ enorm,
        const float* __restrict__ ewe,
        const float* __restrict__ loopw, const float* __restrict__ invcnt,
        __nv_bfloat16* __restrict__ txh, __nv_bfloat16* __restrict__ txl,
        __nv_bfloat16* __restrict__ sh,  __nv_bfloat16* __restrict__ sl, int N) {
    int warp = (blockIdx.x * blockDim.x + threadIdx.x) >> 5;
    int lane = threadIdx.x & 31;
    if (warp >= N) return;
    int beg = off[warp], end = off[warp + 1];
    const float4* xh4 = (const float4*)xh;
    float4 a1 = make_float4(0, 0, 0, 0);
    float4 a2 = make_float4(0, 0, 0, 0);
    for (int j = beg; j < end; j++) {
        int sn = __ldg(&esrc[j]);
        float nm = __ldg(&enorm[j]);
        float we = __ldg(&ewe[j]);
        float4 v = __ldg(&xh4[(size_t)sn * 32 + lane]);
        a1.x += nm * v.x; a1.y += nm * v.y; a1.z += nm * v.z; a1.w += nm * v.w;
        a2.x += we * v.x; a2.y += we * v.y; a2.z += we * v.z; a2.w += we * v.w;
    }
    float lw = __ldg(&loopw[warp]);
    float ic = __ldg(&invcnt[warp]);
    float4 xv = __ldg(&xh4[(size_t)warp * 32 + lane]);
    a2.x = (a2.x + lw * xv.x) * ic;
    a2.y = (a2.y + lw * xv.y) * ic;
    a2.z = (a2.z + lw * xv.z) * ic;
    a2.w = (a2.w + lw * xv.w) * ic;
    uint32_t h0, l0, h1, l1;
    int idx = warp * 32 + lane;
    split2(a1.x, a1.y, h0, l0);
    split2(a1.z, a1.w, h1, l1);
    ((uint2*)txh)[idx] = make_uint2(h0, h1);
    ((uint2*)txl)[idx] = make_uint2(l0, l1);
    split2(a2.x, a2.y, h0, l0);
    split2(a2.z, a2.w, h1, l1);
    ((uint2*)sh)[idx] = make_uint2(h0, h1);
    ((uint2*)sl)[idx] = make_uint2(l0, l1);
}

// weight pre-fusion: W = A@B (row-major), bias fold
__global__ void wfuse(const float* __restrict__ A, const float* __restrict__ B,
                      const float* __restrict__ bA, const float* __restrict__ bB,
                      float* __restrict__ W, float* __restrict__ bOut, int K2) {
    int c = threadIdx.x;
    if (blockIdx.x < H) {
        int row = blockIdx.x;
        float acc = 0.0f;
        for (int j = 0; j < H; j++) acc += __ldg(&A[row * H + j]) * __ldg(&B[j * K2 + c]);
        W[row * K2 + c] = acc;
    } else {
        float acc = bB[c];
        for (int j = 0; j < H; j++) acc += __ldg(&bA[j]) * __ldg(&B[j * K2 + c]);
        bOut[c] = acc;
    }
}

// prestage weight W[K][128] -> planes [n][K]: hi then lo
__global__ void prestage(const float* __restrict__ W, __nv_bfloat16* __restrict__ out, int K) {
    int total = 128 * K;
    for (int i = blockIdx.x * blockDim.x + threadIdx.x; i < total;
         i += gridDim.x * blockDim.x) {
        int n = i / K, k = i - n * K;
        float v = __ldg(&W[(size_t)k * 128 + n]);
        __nv_bfloat16 h = __float2bfloat16(v);
        out[i] = h;
        out[total + i] = __float2bfloat16(v - __bfloat162float(h));
    }
}

// ---------------- HMMA GEMM: C[M,128] = A0@W0 (+A1@W1) + bias ----------------
// split-bf16 3-product, BK=32, cp.async staging, fragment reuse.
// EPI: 0 none, 1 LReLU, 2 LReLU+addsrc.  EM: 0 fp32, 1 fp32+planes, 2 planes only.
#define TG_STRIDE 40    // halves per row (32 K + 8 pad)
template<bool DUAL, int EPI, int EM>
__global__ void __launch_bounds__(256, 2) tgemm(
        const __nv_bfloat16* __restrict__ Ah0, const __nv_bfloat16* __restrict__ Al0,
        const __nv_bfloat16* __restrict__ Ah1, const __nv_bfloat16* __restrict__ Al1,
        const __nv_bfloat16* __restrict__ B0, const __nv_bfloat16* __restrict__ B1,
        const float* __restrict__ bias, const float* __restrict__ addsrc,
        float* __restrict__ Cf, __nv_bfloat16* __restrict__ Ch, __nv_bfloat16* __restrict__ Cl,
        int M, int K) {
    __shared__ __align__(16) __nv_bfloat16 sAh[128 * TG_STRIDE];
    __shared__ __align__(16) __nv_bfloat16 sAl[128 * TG_STRIDE];
    __shared__ __align__(16) __nv_bfloat16 sBh[128 * TG_STRIDE];
    __shared__ __align__(16) __nv_bfloat16 sBl[128 * TG_STRIDE];

    int tid = threadIdx.x, lane = tid & 31, warp = tid >> 5;
    int warp_m = warp & 3, warp_n = warp >> 2;
    int brow = blockIdx.x * 128;

    uint32_t uAh = smem_u32(sAh), uAl = smem_u32(sAl);
    uint32_t uBh = smem_u32(sBh), uBl = smem_u32(sBl);

    // ldmatrix per-lane base offsets (bytes), k-step ks adds ks*32 bytes
    int lr = lane & 7;
    int a_off = ((warp_m * 32 + ((lane >> 3) & 1) * 8 + lr) * TG_STRIDE + (lane >> 4) * 8) * 2;
    int b_off = ((warp_n * 64 + ((lane >> 4) & 1) * 8 + lr) * TG_STRIDE + ((lane >> 3) & 1) * 8) * 2;

    float acc[2][8][4];
#pragma unroll
    for (int mi = 0; mi < 2; mi++)
#pragma unroll
        for (int ni = 0; ni < 8; ni++)
#pragma unroll
            for (int c = 0; c < 4; c++) acc[mi][ni][c] = 0.0f;

    // staging role: r = row, half = which 16-K half
    int r = tid >> 1, half = tid & 1;
    int grow = brow + r;
    bool rowok = grow < M;
    int growc = rowok ? grow : (M - 1);
    int asz = rowok ? 16 : 0;
    uint32_t s_a = r * (TG_STRIDE * 2) + half * 32;   // byte offset in smem row
    int nk = K >> 5;
    int nstream = DUAL ? 2 : 1;

    for (int s = 0; s < nstream; s++) {
        const __nv_bfloat16* Ah = s ? Ah1 : Ah0;
        const __nv_bfloat16* Al = s ? Al1 : Al0;
        const __nv_bfloat16* Bp = s ? B1 : B0;
        for (int kc = 0; kc < nk; kc++) {
            int k0 = kc << 5;
            if (s | kc) __syncthreads();    // protect smem from overwrite
            {
                const char* gah = (const char*)(Ah + (size_t)growc * K + k0 + half * 16);
                const char* gal = (const char*)(Al + (size_t)growc * K + k0 + half * 16);
                const char* gbh = (const char*)(Bp + (size_t)r * K + k0 + half * 16);
                const char* gbl = (const char*)(Bp + (size_t)128 * K + (size_t)r * K + k0 + half * 16);
                cp16(uAh + s_a,      gah,      asz);
                cp16(uAh + s_a + 16, gah + 16, asz);
                cp16(uAl + s_a,      gal,      asz);
                cp16(uAl + s_a + 16, gal + 16, asz);
                cp16(uBh + s_a,      gbh,      16);
                cp16(uBh + s_a + 16, gbh + 16, 16);
                cp16(uBl + s_a,      gbl,      16);
                cp16(uBl + s_a + 16, gbl + 16, 16);
                cp_commit_wait();
            }
            __syncthreads();

#pragma unroll
            for (int ks = 0; ks < 2; ks++) {
                int ko = ks * 32;   // byte offset for this k16 step
                uint32_t afh[2][4], afl[2][4], bfr[4][4];
#pragma unroll
                for (int nj = 0; nj < 4; nj++)
                    ldm4(bfr[nj], uBh + b_off + ko + nj * 16 * TG_STRIDE * 2);
#pragma unroll
                for (int mi = 0; mi < 2; mi++) {
                    ldm4(afh[mi], uAh + a_off + ko + mi * 16 * TG_STRIDE * 2);
                    ldm4(afl[mi], uAl + a_off + ko + mi * 16 * TG_STRIDE * 2);
                }
#pragma unroll
                for (int mi = 0; mi < 2; mi++)
#pragma unroll
                    for (int ni = 0; ni < 8; ni++)
                        mma16816(acc[mi][ni], afh[mi], bfr[ni >> 1][(ni & 1) * 2],
                                 bfr[ni >> 1][(ni & 1) * 2 + 1]);
#pragma unroll
                for (int mi = 0; mi < 2; mi++)
#pragma unroll
                    for (int ni = 0; ni < 8; ni++)
                        mma16816(acc[mi][ni], afl[mi], bfr[ni >> 1][(ni & 1) * 2],
                                 bfr[ni >> 1][(ni & 1) * 2 + 1]);
#pragma unroll
                for (int nj = 0; nj < 4; nj++)
                    ldm4(bfr[nj], uBl + b_off + ko + nj * 16 * TG_STRIDE * 2);
#pragma unroll
                for (int mi = 0; mi < 2; mi++)
#pragma unroll
                    for (int ni = 0; ni < 8; ni++)
                        mma16816(acc[mi][ni], afh[mi], bfr[ni >> 1][(ni & 1) * 2],
                                 bfr[ni >> 1][(ni & 1) * 2 + 1]);
            }
        }
    }

    // epilogue
    int g = lane >> 2, tg = lane & 3;
#pragma unroll
    for (int mi = 0; mi < 2; mi++) {
#pragma unroll
        for (int h = 0; h < 2; h++) {
            int row = brow + warp_m * 32 + mi * 16 + h * 8 + g;
            if (row >= M) continue;
#pragma unroll
            for (int ni = 0; ni < 8; ni++) {
                int col = warp_n * 64 + ni * 8 + tg * 2;
                float v0 = acc[mi][ni][h * 2 + 0] + __ldg(&bias[col]);
                float v1 = acc[mi][ni][h * 2 + 1] + __ldg(&bias[col + 1]);
                if (EPI >= 1) {
                    v0 = v0 > 0.0f ? v0 : NEG_SLOPE * v0;
                    v1 = v1 > 0.0f ? v1 : NEG_SLOPE * v1;
                }
                if (EPI == 2) {
                    float2 o = *(const float2*)(addsrc + (size_t)row * 128 + col);
                    v0 += o.x; v1 += o.y;
                }
                if (EM != 2)
                    *(float2*)(Cf + (size_t)row * 128 + col) = make_float2(v0, v1);
                if (EM >= 1) {
                    uint32_t hh, ll;
                    split2(v0, v1, hh, ll);
                    *(uint32_t*)(Ch + (size_t)row * 128 + col) = hh;
                    *(uint32_t*)(Cl + (size_t)row * 128 + col) = ll;
                }
            }
        }
    }
}

// ---------------- classifier + log_softmax (warp per row) ----------------
__global__ void __launch_bounds__(256) cls_kernel(
        const float* __restrict__ x, const float* __restrict__ W,
        const float* __restrict__ b, float* __restrict__ out, int M) {
    __shared__ float Wt[C_OUT][128];
    __shared__ float bs[C_OUT];
    for (int i = threadIdx.x; i < 128 * C_OUT; i += 256) {
        int k = i / C_OUT, c = i % C_OUT;
        Wt[c][k] = W[i];
    }
    if (threadIdx.x < C_OUT) bs[threadIdx.x] = b[threadIdx.x];
    __syncthreads();

    int warp = threadIdx.x >> 5, lane = threadIdx.x & 31;
    int row = blockIdx.x * 8 + warp;
    if (row >= M) return;

    float xr[4];
#pragma unroll
    for (int j = 0; j < 4; j++) xr[j] = x[(size_t)row * 128 + lane + 32 * j];

    float acc[C_OUT];
#pragma unroll
    for (int c = 0; c < C_OUT; c++) {
        float a = 0.0f;
#pragma unroll
        for (int j = 0; j < 4; j++) a += xr[j] * Wt[c][lane + 32 * j];
#pragma unroll
        for (int o = 16; o > 0; o >>= 1) a += __shfl_down_sync(0xFFFFFFFFu, a, o);
        acc[c] = a;
    }
    if (lane == 0) {
        float mx = -1e30f;
#pragma unroll
        for (int c = 0; c < C_OUT; c++) { acc[c] += bs[c]; mx = fmaxf(mx, acc[c]); }
        float se = 0.0f;
#pragma unroll
        for (int c = 0; c < C_OUT; c++) se += expf(acc[c] - mx);
        float l = mx + logf(se);
#pragma unroll
        for (int c = 0; c < C_OUT; c++) out[(size_t)row * C_OUT + c] = acc[c] - l;
    }
}

// ---------------- host ----------------
static void* symaddr(const void* sym) {
    void* p = nullptr;
    cudaGetSymbolAddress(&p, sym);
    return p;
}

extern "C" void kernel_launch(void* const* d_in, const int* in_sizes, int n_in,
                              void* d_out, int out_size) {
    const float* x   = (const float*)d_in[0];
    const int*   ei  = (const int*)d_in[1];
    const float* ew  = (const float*)d_in[2];
    const float* pre_w1 = (const float*)d_in[3];  const float* pre_b1 = (const float*)d_in[4];
    const float* cw0_1  = (const float*)d_in[5];  const float* cw1_1  = (const float*)d_in[6];
    const float* cb_1   = (const float*)d_in[7];
    const float* sw_1   = (const float*)d_in[8];  const float* sb_1   = (const float*)d_in[9];
    const float* lw_1   = (const float*)d_in[10]; const float* lb_1   = (const float*)d_in[11];
    const float* pre_w2 = (const float*)d_in[12]; const float* pre_b2 = (const float*)d_in[13];
    const float* cw0_2  = (const float*)d_in[14]; const float* cw1_2  = (const float*)d_in[15];
    const float* cb_2   = (const float*)d_in[16];
    const float* sw_2   = (const float*)d_in[17]; const float* sb_2   = (const float*)d_in[18];
    const float* lw_2   = (const float*)d_in[19]; const float* lb_2   = (const float*)d_in[20];
    const float* cls_w  = (const float*)d_in[21]; const float* cls_b  = (const float*)d_in[22];
    float* out = (float*)d_out;

    int E = in_sizes[2];
    int N = in_sizes[0] / F_IN;
    const int* src = ei;
    const int* dst = ei + E;

    float* xh    = (float*)symaddr(g_xh);
    float* o2    = (float*)symaddr(g_o2);
    float* tbuf  = (float*)symaddr(g_t);
    float* deg   = (float*)symaddr(g_deg);
    float* dis   = (float*)symaddr(g_dis);
    float* loopw = (float*)symaddr(g_loopw);
    float* invc  = (float*)symaddr(g_invcnt);
    float* cntf  = (float*)symaddr(g_cntf);
    int*   hist  = (int*)symaddr(g_hist);
    int*   off   = (int*)symaddr(g_off);
    int*   cur   = (int*)symaddr(g_cursor);
    int*   bsum  = (int*)symaddr(g_bsum);
    int*   esrc  = (int*)symaddr(g_esrc);
    float* enorm = (float*)symaddr(g_enorm);
    float* ewe   = (float*)symaddr(g_ewe);
    float* W12   = (float*)symaddr(g_W12);
    float* b12   = (float*)symaddr(g_b12);
    float* Wc    = (float*)symaddr(g_Wc);
    float* bc    = (float*)symaddr(g_bc);

    __nv_bfloat16* xe_h = (__nv_bfloat16*)symaddr(g_xe_h);
    __nv_bfloat16* xe_l = (__nv_bfloat16*)symaddr(g_xe_l);
    __nv_bfloat16* xh_h = (__nv_bfloat16*)symaddr(g_xh_h);
    __nv_bfloat16* xh_l = (__nv_bfloat16*)symaddr(g_xh_l);
    __nv_bfloat16* tx_h = (__nv_bfloat16*)symaddr(g_tx_h);
    __nv_bfloat16* tx_l = (__nv_bfloat16*)symaddr(g_tx_l);
    __nv_bfloat16* s_h  = (__nv_bfloat16*)symaddr(g_s_h);
    __nv_bfloat16* s_l  = (__nv_bfloat16*)symaddr(g_s_l);
    __nv_bfloat16* t_h  = (__nv_bfloat16*)symaddr(g_t_h);
    __nv_bfloat16* t_l  = (__nv_bfloat16*)symaddr(g_t_l);

    __nv_bfloat16* Bpre1  = (__nv_bfloat16*)symaddr(g_Bpre1);
    __nv_bfloat16* Bcw0_1 = (__nv_bfloat16*)symaddr(g_Bcw0_1);
    __nv_bfloat16* Bcw1_1 = (__nv_bfloat16*)symaddr(g_Bcw1_1);
    __nv_bfloat16* Bsw1   = (__nv_bfloat16*)symaddr(g_Bsw1);
    __nv_bfloat16* BW12   = (__nv_bfloat16*)symaddr(g_BW12);
    __nv_bfloat16* Bcw0_2 = (__nv_bfloat16*)symaddr(g_Bcw0_2);
    __nv_bfloat16* Bcw1_2 = (__nv_bfloat16*)symaddr(g_Bcw1_2);
    __nv_bfloat16* Bsw2   = (__nv_bfloat16*)symaddr(g_Bsw2);

    int eB = (E + 255) / 256;
    int nB = (N + 255) / 256;
    int nbScan = (N + 1023) / 1024;
    int gG = (N + 127) / 128;
    int aggB = (N * 32 + 255) / 256;

    // ---- weight fusion + prestaging ----
    wfuse<<<H + 1, H>>>(lw_1, pre_w2, lb_1, pre_b2, W12, b12, H);
    wfuse<<<H + 1, C_OUT>>>(lw_2, cls_w, lb_2, cls_b, Wc, bc, C_OUT);
    prestage<<<64, 256>>>(pre_w1, Bpre1, 512);
    prestage<<<16, 256>>>(cw0_1, Bcw0_1, 128);
    prestage<<<16, 256>>>(cw1_1, Bcw1_1, 128);
    prestage<<<16, 256>>>(sw_1,  Bsw1, 128);
    prestage<<<16, 256>>>(W12,   BW12, 128);
    prestage<<<16, 256>>>(cw0_2, Bcw0_2, 128);
    prestage<<<16, 256>>>(cw1_2, Bcw1_2, 128);
    prestage<<<16, 256>>>(sw_2,  Bsw2, 128);

    // ---- one-time input split ----
    int total4 = N * F_IN / 4;
    convert_split<<<(total4 + 255) / 256, 256>>>(x, xe_h, xe_l, total4);

    // ---- graph-structure preprocessing ----
    cudaMemsetAsync(deg,  0, (size_t)N * sizeof(float));
    cudaMemsetAsync(cntf, 0, (size_t)N * sizeof(float));
    cudaMemsetAsync(hist, 0, (size_t)N * sizeof(int));
    fill_ones<<<nB, 256>>>(loopw, N);
    edge_pass1<<<eB, 256>>>(src, dst, ew, deg, cntf, loopw, hist, E);
    node_prep<<<nB, 256>>>(deg, cntf, dis, invc, N);
    scan1<<<nbScan, 256>>>(hist, bsum, N);
    scan2<<<1, 32>>>(bsum, nbScan, off, N);
    scan3<<<nbScan, 256>>>(hist, bsum, off, cur, N);
    edge_pass2<<<eB, 256>>>(src, dst, ew, dis, cur, esrc, enorm, ewe, E);

    // ---- cell 1 (512 -> 128) ----
    tgemm<false, 0, 1><<<gG, 256>>>(xe_h, xe_l, nullptr, nullptr, Bpre1, nullptr,
                                    pre_b1, nullptr, xh, xh_h, xh_l, N, 512);
    aggregate<<<aggB, 256>>>(xh, off, esrc, enorm, ewe, loopw, invc,
                             tx_h, tx_l, s_h, s_l, N);
    tgemm<false, 1, 0><<<gG, 256>>>(s_h, s_l, nullptr, nullptr, Bsw1, nullptr,
                                    sb_1, nullptr, o2, nullptr, nullptr, N, 128);
    tgemm<true, 2, 2><<<gG, 256>>>(xh_h, xh_l, tx_h, tx_l, Bcw0_1, Bcw1_1,
                                   cb_1, o2, nullptr, t_h, t_l, N, 128);

    // ---- fused lin1+pre2 ----
    tgemm<false, 0, 1><<<gG, 256>>>(t_h, t_l, nullptr, nullptr, BW12, nullptr,
                                    b12, nullptr, xh, xh_h, xh_l, N, 128);

    // ---- cell 2 (128 -> 128) ----
    aggregate<<<aggB, 256>>>(xh, off, esrc, enorm, ewe, loopw, invc,
                             tx_h, tx_l, s_h, s_l, N);
    tgemm<false, 1, 0><<<gG, 256>>>(s_h, s_l, nullptr, nullptr, Bsw2, nullptr,
                                    sb_2, nullptr, o2, nullptr, nullptr, N, 128);
    tgemm<true, 2, 0><<<gG, 256>>>(xh_h, xh_l, tx_h, tx_l, Bcw0_2, Bcw1_2,
                                   cb_2, o2, tbuf, nullptr, nullptr, N, 128);

    // ---- fused lin2 + classifier + log_softmax ----
    cls_kernel<<<(N + 7) / 8, 256>>>(tbuf, Wc, bc, out, N);
}

// round 6
// speedup vs baseline: 1.7771x; 1.0772x over previous
#include <cuda_runtime.h>
#include <cuda_bf16.h>
#include <math.h>
#include <stdint.h>

// ---------------- problem constants ----------------
#define N_MAX 40000
#define E_MAX 640000
#define F_IN  512
#define H     128
#define C_OUT 40
#define NEG_SLOPE 0.01f

// ---------------- scratch (device globals; no runtime alloc) ----------------
__device__ float g_xh [N_MAX * H];
__device__ float g_o2 [N_MAX * H];
__device__ float g_t  [N_MAX * H];

__device__ __nv_bfloat16 g_xe_h[N_MAX * F_IN];
__device__ __nv_bfloat16 g_xe_l[N_MAX * F_IN];
__device__ __nv_bfloat16 g_xh_h[N_MAX * H];
__device__ __nv_bfloat16 g_xh_l[N_MAX * H];
__device__ __nv_bfloat16 g_tx_h[N_MAX * H];
__device__ __nv_bfloat16 g_tx_l[N_MAX * H];
__device__ __nv_bfloat16 g_s_h [N_MAX * H];
__device__ __nv_bfloat16 g_s_l [N_MAX * H];
__device__ __nv_bfloat16 g_t_h [N_MAX * H];
__device__ __nv_bfloat16 g_t_l [N_MAX * H];

__device__ float g_deg   [N_MAX];
__device__ float g_dis   [N_MAX];
__device__ float g_loopw [N_MAX];
__device__ float g_invcnt[N_MAX];
__device__ float g_cntf  [N_MAX];
__device__ int   g_hist  [N_MAX];
__device__ int   g_off   [N_MAX + 1];
__device__ int   g_cursor[N_MAX];
__device__ int   g_bsum  [64];
__device__ int   g_esrc  [E_MAX];
__device__ float g_enorm [E_MAX];
__device__ float g_ewe   [E_MAX];

__device__ float g_W12[H * H];
__device__ float g_b12[H];
__device__ float g_Wc [H * C_OUT];
__device__ float g_bc [C_OUT];

// prestaged weights as [n=128][K] bf16, hi plane then lo plane
__device__ __nv_bfloat16 g_Bpre1 [2 * 128 * 512];
__device__ __nv_bfloat16 g_Bcw0_1[2 * 128 * 128];
__device__ __nv_bfloat16 g_Bcw1_1[2 * 128 * 128];
__device__ __nv_bfloat16 g_Bsw1  [2 * 128 * 128];
__device__ __nv_bfloat16 g_BW12  [2 * 128 * 128];
__device__ __nv_bfloat16 g_Bcw0_2[2 * 128 * 128];
__device__ __nv_bfloat16 g_Bcw1_2[2 * 128 * 128];
__device__ __nv_bfloat16 g_Bsw2  [2 * 128 * 128];

// ---------------- helpers ----------------
__device__ __forceinline__ uint32_t smem_u32(const void* p) {
    uint32_t a;
    asm("{ .reg .u64 t; cvta.to.shared.u64 t, %1; cvt.u32.u64 %0, t; }"
        : "=r"(a) : "l"(p));
    return a;
}
__device__ __forceinline__ void split2(float a, float b, uint32_t& h, uint32_t& l) {
    asm("cvt.rn.bf16x2.f32 %0,%1,%2;" : "=r"(h) : "f"(b), "f"(a));
    float fa = __uint_as_float(h << 16);
    float fb = __uint_as_float(h & 0xFFFF0000u);
    float la = a - fa, lb = b - fb;
    asm("cvt.rn.bf16x2.f32 %0,%1,%2;" : "=r"(l) : "f"(lb), "f"(la));
}
__device__ __forceinline__ void ldm4(uint32_t* r, uint32_t addr) {
    asm volatile("ldmatrix.sync.aligned.m8n8.x4.shared.b16 {%0,%1,%2,%3},[%4];"
                 : "=r"(r[0]), "=r"(r[1]), "=r"(r[2]), "=r"(r[3]) : "r"(addr));
}
__device__ __forceinline__ void mma16816(float* d, const uint32_t* a, uint32_t b0, uint32_t b1) {
    asm volatile("mma.sync.aligned.m16n8k16.row.col.f32.bf16.bf16.f32 "
                 "{%0,%1,%2,%3},{%4,%5,%6,%7},{%8,%9},{%0,%1,%2,%3};"
                 : "+f"(d[0]), "+f"(d[1]), "+f"(d[2]), "+f"(d[3])
                 : "r"(a[0]), "r"(a[1]), "r"(a[2]), "r"(a[3]), "r"(b0), "r"(b1));
}
__device__ __forceinline__ void cp16(uint32_t dst, const void* src, int szbytes) {
    asm volatile("cp.async.cg.shared.global [%0],[%1],16,%2;"
                 :: "r"(dst), "l"(src), "r"(szbytes));
}
template<int NN> __device__ __forceinline__ void cp_wait() {
    asm volatile("cp.async.wait_group %0;" :: "n"(NN));
}

// ---------------- small utility kernels ----------------
__global__ void init_nodes(float* loopw, float* deg, float* cntf, int* hist, int n) {
    int i = blockIdx.x * blockDim.x + threadIdx.x;
    if (i < n) { loopw[i] = 1.0f; deg[i] = 0.0f; cntf[i] = 0.0f; hist[i] = 0; }
}

__global__ void convert_split(const float* __restrict__ in,
                              __nv_bfloat16* __restrict__ hi,
                              __nv_bfloat16* __restrict__ lo, int total4) {
    int i = blockIdx.x * blockDim.x + threadIdx.x;
    if (i >= total4) return;
    float4 v = __ldg(&((const float4*)in)[i]);
    uint32_t h0, l0, h1, l1;
    split2(v.x, v.y, h0, l0);
    split2(v.z, v.w, h1, l1);
    ((uint2*)hi)[i] = make_uint2(h0, h1);
    ((uint2*)lo)[i] = make_uint2(l0, l1);
}

__global__ void edge_pass1(const int* __restrict__ src, const int* __restrict__ dst,
                           const float* __restrict__ w,
                           float* __restrict__ deg, float* __restrict__ cntf,
                           float* __restrict__ loopw, int* __restrict__ hist, int E) {
    int i = blockIdx.x * blockDim.x + threadIdx.x;
    if (i >= E) return;
    int s = src[i], d = dst[i];
    float wt = w[i];
    if (s == d) {
        loopw[s] = wt;
    } else {
        atomicAdd(&deg[s], wt);
        atomicAdd(&cntf[d], 1.0f);
    }
    atomicAdd(&hist[d], 1);
}

__global__ void node_prep(const float* __restrict__ deg, const float* __restrict__ cntf,
                          float* __restrict__ dis, float* __restrict__ invcnt, int N) {
    int i = blockIdx.x * blockDim.x + threadIdx.x;
    if (i >= N) return;
    float dg = deg[i];
    dis[i]    = (dg > 0.0f) ? rsqrtf(dg) : 0.0f;
    invcnt[i] = 1.0f / (cntf[i] + 1.0f);
}

__global__ void scan1(const int* __restrict__ hist, int* __restrict__ bsum, int n) {
    __shared__ int sh[256];
    int base = blockIdx.x * 1024;
    int s = 0;
#pragma unroll
    for (int j = 0; j < 4; j++) {
        int i = base + threadIdx.x + j * 256;
        s += (i < n) ? hist[i] : 0;
    }
    sh[threadIdx.x] = s;
    __syncthreads();
    for (int o = 128; o > 0; o >>= 1) {
        if (threadIdx.x < o) sh[threadIdx.x] += sh[threadIdx.x + o];
        __syncthreads();
    }
    if (threadIdx.x == 0) bsum[blockIdx.x] = sh[0];
}
__global__ void scan2(int* __restrict__ bsum, int nb, int* __restrict__ off, int n) {
    if (threadIdx.x == 0) {
        int run = 0;
        for (int i = 0; i < nb; i++) { int v = bsum[i]; bsum[i] = run; run += v; }
        off[n] = run;
    }
}
__global__ void scan3(const int* __restrict__ hist, const int* __restrict__ bsum,
                      int* __restrict__ off, int* __restrict__ cursor, int n) {
    __shared__ int sh[256];
    int base = blockIdx.x * 1024 + threadIdx.x * 4;
    int v[4]; int s = 0;
#pragma unroll
    for (int j = 0; j < 4; j++) {
        int i = base + j;
        v[j] = (i < n) ? hist[i] : 0;
        s += v[j];
    }
    sh[threadIdx.x] = s;
    __syncthreads();
    for (int o = 1; o < 256; o <<= 1) {
        int t = (threadIdx.x >= o) ? sh[threadIdx.x - o] : 0;
        __syncthreads();
        sh[threadIdx.x] += t;
        __syncthreads();
    }
    int run = bsum[blockIdx.x] + sh[threadIdx.x] - s;
#pragma unroll
    for (int j = 0; j < 4; j++) {
        int i = base + j;
        if (i < n) { off[i] = run; cursor[i] = run; }
        run += v[j];
    }
}

__global__ void edge_pass2(const int* __restrict__ src, const int* __restrict__ dst,
                           const float* __restrict__ w, const float* __restrict__ dis,
                           int* __restrict__ cursor,
                           int* __restrict__ esrc, float* __restrict__ enorm,
                           float* __restrict__ ewe, int E) {
    int i = blockIdx.x * blockDim.x + threadIdx.x;
    if (i >= E) return;
    int s = src[i], d = dst[i];
    float wt = w[i];
    float wc = (s == d) ? 0.0f : wt;
    float nm = -dis[s] * wc * dis[d];
    int pos = atomicAdd(&cursor[d], 1);
    esrc[pos]  = s;
    enorm[pos] = nm;
    ewe[pos]   = wc;
}

// warp-per-node CSR aggregation with fused sage-mean; emits bf16 hi/lo planes
__global__ void __launch_bounds__(256) aggregate(
        const float* __restrict__ xh, const int* __restrict__ off,
        const int* __restrict__ esrc, const float* __restrict__ enorm,
        const float* __restrict__ ewe,
        const float* __restrict__ loopw, const float* __restrict__ invcnt,
        __nv_bfloat16* __restrict__ txh, __nv_bfloat16* __restrict__ txl,
        __nv_bfloat16* __restrict__ sh,  __nv_bfloat16* __restrict__ sl, int N) {
    int warp = (blockIdx.x * blockDim.x + threadIdx.x) >> 5;
    int lane = threadIdx.x & 31;
    if (warp >= N) return;
    int beg = off[warp], end = off[warp + 1];
    const float4* xh4 = (const float4*)xh;
    float4 a1 = make_float4(0, 0, 0, 0);
    float4 a2 = make_float4(0, 0, 0, 0);
    int j = beg;
    for (; j + 4 <= end; j += 4) {
        int   s0 = __ldg(&esrc[j]),     s1 = __ldg(&esrc[j + 1]);
        int   s2 = __ldg(&esrc[j + 2]), s3 = __ldg(&esrc[j + 3]);
        float n0 = __ldg(&enorm[j]),     n1 = __ldg(&enorm[j + 1]);
        float n2 = __ldg(&enorm[j + 2]), n3 = __ldg(&enorm[j + 3]);
        float w0 = __ldg(&ewe[j]),       w1 = __ldg(&ewe[j + 1]);
        float w2 = __ldg(&ewe[j + 2]),   w3 = __ldg(&ewe[j + 3]);
        float4 v0 = __ldg(&xh4[(size_t)s0 * 32 + lane]);
        float4 v1 = __ldg(&xh4[(size_t)s1 * 32 + lane]);
        float4 v2 = __ldg(&xh4[(size_t)s2 * 32 + lane]);
        float4 v3 = __ldg(&xh4[(size_t)s3 * 32 + lane]);
        a1.x += n0 * v0.x + n1 * v1.x + n2 * v2.x + n3 * v3.x;
        a1.y += n0 * v0.y + n1 * v1.y + n2 * v2.y + n3 * v3.y;
        a1.z += n0 * v0.z + n1 * v1.z + n2 * v2.z + n3 * v3.z;
        a1.w += n0 * v0.w + n1 * v1.w + n2 * v2.w + n3 * v3.w;
        a2.x += w0 * v0.x + w1 * v1.x + w2 * v2.x + w3 * v3.x;
        a2.y += w0 * v0.y + w1 * v1.y + w2 * v2.y + w3 * v3.y;
        a2.z += w0 * v0.z + w1 * v1.z + w2 * v2.z + w3 * v3.z;
        a2.w += w0 * v0.w + w1 * v1.w + w2 * v2.w + w3 * v3.w;
    }
    for (; j < end; j++) {
        int sn = __ldg(&esrc[j]);
        float nm = __ldg(&enorm[j]);
        float we = __ldg(&ewe[j]);
        float4 v = __ldg(&xh4[(size_t)sn * 32 + lane]);
        a1.x += nm * v.x; a1.y += nm * v.y; a1.z += nm * v.z; a1.w += nm * v.w;
        a2.x += we * v.x; a2.y += we * v.y; a2.z += we * v.z; a2.w += we * v.w;
    }
    float lw = __ldg(&loopw[warp]);
    float ic = __ldg(&invcnt[warp]);
    float4 xv = __ldg(&xh4[(size_t)warp * 32 + lane]);
    a2.x = (a2.x + lw * xv.x) * ic;
    a2.y = (a2.y + lw * xv.y) * ic;
    a2.z = (a2.z + lw * xv.z) * ic;
    a2.w = (a2.w + lw * xv.w) * ic;
    uint32_t h0, l0, h1, l1;
    int idx = warp * 32 + lane;
    split2(a1.x, a1.y, h0, l0);
    split2(a1.z, a1.w, h1, l1);
    ((uint2*)txh)[idx] = make_uint2(h0, h1);
    ((uint2*)txl)[idx] = make_uint2(l0, l1);
    split2(a2.x, a2.y, h0, l0);
    split2(a2.z, a2.w, h1, l1);
    ((uint2*)sh)[idx] = make_uint2(h0, h1);
    ((uint2*)sl)[idx] = make_uint2(l0, l1);
}

// weight pre-fusion: W = A@B (row-major), bias fold
__global__ void wfuse(const float* __restrict__ A, const float* __restrict__ B,
                      const float* __restrict__ bA, const float* __restrict__ bB,
                      float* __restrict__ W, float* __restrict__ bOut, int K2) {
    int c = threadIdx.x;
    if (blockIdx.x < H) {
        int row = blockIdx.x;
        float acc = 0.0f;
        for (int j = 0; j < H; j++) acc += __ldg(&A[row * H + j]) * __ldg(&B[j * K2 + c]);
        W[row * K2 + c] = acc;
    } else {
        float acc = bB[c];
        for (int j = 0; j < H; j++) acc += __ldg(&bA[j]) * __ldg(&B[j * K2 + c]);
        bOut[c] = acc;
    }
}

// prestage one weight W[K][128] -> planes [n][K]: hi then lo (kshift = log2 K)
__device__ __forceinline__ void prestage_one(const float* __restrict__ W,
                                             __nv_bfloat16* __restrict__ out,
                                             int K, int kshift, int tid, int nthreads) {
    int total = 128 * K;
    for (int i = tid; i < total; i += nthreads) {
        int n = i >> kshift, k = i & (K - 1);
        float v = __ldg(&W[(size_t)k * 128 + n]);
        __nv_bfloat16 h = __float2bfloat16(v);
        out[i] = h;
        out[total + i] = __float2bfloat16(v - __bfloat162float(h));
    }
}

// all 7 H x H weights in one launch: grid = 7 * 16 blocks
__global__ void prestage_all(
        const float* W0, const float* W1, const float* W2, const float* W3,
        const float* W4, const float* W5, const float* W6,
        __nv_bfloat16* O0, __nv_bfloat16* O1, __nv_bfloat16* O2, __nv_bfloat16* O3,
        __nv_bfloat16* O4, __nv_bfloat16* O5, __nv_bfloat16* O6) {
    int wsel = blockIdx.x >> 4;
    int bi = blockIdx.x & 15;
    const float* W; __nv_bfloat16* O;
    switch (wsel) {
        case 0: W = W0; O = O0; break;
        case 1: W = W1; O = O1; break;
        case 2: W = W2; O = O2; break;
        case 3: W = W3; O = O3; break;
        case 4: W = W4; O = O4; break;
        case 5: W = W5; O = O5; break;
        default: W = W6; O = O6; break;
    }
    prestage_one(W, O, 128, 7, bi * 256 + threadIdx.x, 16 * 256);
}

__global__ void prestage_big(const float* __restrict__ W, __nv_bfloat16* __restrict__ out) {
    prestage_one(W, out, 512, 9, blockIdx.x * 256 + threadIdx.x, gridDim.x * 256);
}

// ---------------- HMMA GEMM, 2-stage cp.async pipeline ----------------
#define TG_STRIDE 40
#define ARR_B 10240           // bytes per (array, stage)
#define STAGE_B 40960         // 4 arrays
#define TG_SMEM (2 * STAGE_B) // 81920

template<bool DUAL, int EPI, int EM>
__global__ void __launch_bounds__(256, 2) tgemm(
        const __nv_bfloat16* __restrict__ Ah0, const __nv_bfloat16* __restrict__ Al0,
        const __nv_bfloat16* __restrict__ Ah1, const __nv_bfloat16* __restrict__ Al1,
        const __nv_bfloat16* __restrict__ B0, const __nv_bfloat16* __restrict__ B1,
        const float* __restrict__ bias, const float* __restrict__ addsrc,
        float* __restrict__ Cf, __nv_bfloat16* __restrict__ Ch, __nv_bfloat16* __restrict__ Cl,
        int M, int K) {
    extern __shared__ __align__(16) char dsm[];
    uint32_t base = smem_u32(dsm);

    int tid = threadIdx.x, lane = tid & 31, warp = tid >> 5;
    int warp_m = warp & 3, warp_n = warp >> 2;
    int brow = blockIdx.x * 128;

    int lr = lane & 7;
    int a_off = ((warp_m * 32 + ((lane >> 3) & 1) * 8 + lr) * TG_STRIDE + (lane >> 4) * 8) * 2;
    int b_off = ((warp_n * 64 + ((lane >> 4) & 1) * 8 + lr) * TG_STRIDE + ((lane >> 3) & 1) * 8) * 2;

    float acc[2][8][4];
#pragma unroll
    for (int mi = 0; mi < 2; mi++)
#pragma unroll
        for (int ni = 0; ni < 8; ni++)
#pragma unroll
            for (int c = 0; c < 4; c++) acc[mi][ni][c] = 0.0f;

    int r = tid >> 1, half = tid & 1;
    int grow = brow + r;
    bool rowok = grow < M;
    int growc = rowok ? grow : (M - 1);
    int asz = rowok ? 16 : 0;
    uint32_t s_a = r * (TG_STRIDE * 2) + half * 32;
    int cpa = K >> 5;
    int total = DUAL ? cpa * 2 : cpa;

    auto issue = [&](int c, int stage) {
        int st = (DUAL && c >= cpa) ? 1 : 0;
        int ci = c - (st ? cpa : 0);
        const __nv_bfloat16* Ah = st ? Ah1 : Ah0;
        const __nv_bfloat16* Al = st ? Al1 : Al0;
        const __nv_bfloat16* Bp = st ? B1 : B0;
        int k0 = ci << 5;
        uint32_t sb = base + stage * STAGE_B + s_a;
        const char* gah = (const char*)(Ah + (size_t)growc * K + k0 + half * 16);
        const char* gal = (const char*)(Al + (size_t)growc * K + k0 + half * 16);
        const char* gbh = (const char*)(Bp + (size_t)r * K + k0 + half * 16);
        const char* gbl = (const char*)(Bp + (size_t)128 * K + (size_t)r * K + k0 + half * 16);
        cp16(sb,                gah,      asz);
        cp16(sb + 16,           gah + 16, asz);
        cp16(sb + ARR_B,        gal,      asz);
        cp16(sb + ARR_B + 16,   gal + 16, asz);
        cp16(sb + 2 * ARR_B,      gbh,      16);
        cp16(sb + 2 * ARR_B + 16, gbh + 16, 16);
        cp16(sb + 3 * ARR_B,      gbl,      16);
        cp16(sb + 3 * ARR_B + 16, gbl + 16, 16);
        asm volatile("cp.async.commit_group;");
    };

    issue(0, 0);
    for (int c = 0; c < total; c++) {
        int cur = c & 1;
        if (c + 1 < total) { issue(c + 1, cur ^ 1); cp_wait<1>(); }
        else               { cp_wait<0>(); }
        __syncthreads();

        uint32_t uAh = base + cur * STAGE_B;
        uint32_t uAl = uAh + ARR_B;
        uint32_t uBh = uAh + 2 * ARR_B;
        uint32_t uBl = uAh + 3 * ARR_B;
#pragma unroll
        for (int ks = 0; ks < 2; ks++) {
            int ko = ks * 32;
            uint32_t afh[2][4], afl[2][4], bfr[4][4];
#pragma unroll
            for (int nj = 0; nj < 4; nj++)
                ldm4(bfr[nj], uBh + b_off + ko + nj * 16 * TG_STRIDE * 2);
#pragma unroll
            for (int mi = 0; mi < 2; mi++) {
                ldm4(afh[mi], uAh + a_off + ko + mi * 16 * TG_STRIDE * 2);
                ldm4(afl[mi], uAl + a_off + ko + mi * 16 * TG_STRIDE * 2);
            }
#pragma unroll
            for (int mi = 0; mi < 2; mi++)
#pragma unroll
                for (int ni = 0; ni < 8; ni++)
                    mma16816(acc[mi][ni], afh[mi], bfr[ni >> 1][(ni & 1) * 2],
                             bfr[ni >> 1][(ni & 1) * 2 + 1]);
#pragma unroll
            for (int mi = 0; mi < 2; mi++)
#pragma unroll
                for (int ni = 0; ni < 8; ni++)
                    mma16816(acc[mi][ni], afl[mi], bfr[ni >> 1][(ni & 1) * 2],
                             bfr[ni >> 1][(ni & 1) * 2 + 1]);
#pragma unroll
            for (int nj = 0; nj < 4; nj++)
                ldm4(bfr[nj], uBl + b_off + ko + nj * 16 * TG_STRIDE * 2);
#pragma unroll
            for (int mi = 0; mi < 2; mi++)
#pragma unroll
                for (int ni = 0; ni < 8; ni++)
                    mma16816(acc[mi][ni], afh[mi], bfr[ni >> 1][(ni & 1) * 2],
                             bfr[ni >> 1][(ni & 1) * 2 + 1]);
        }
        __syncthreads();
    }

    // epilogue
    int g = lane >> 2, tg = lane & 3;
#pragma unroll
    for (int mi = 0; mi < 2; mi++) {
#pragma unroll
        for (int h = 0; h < 2; h++) {
            int row = brow + warp_m * 32 + mi * 16 + h * 8 + g;
            if (row >= M) continue;
#pragma unroll
            for (int ni = 0; ni < 8; ni++) {
                int col = warp_n * 64 + ni * 8 + tg * 2;
                float v0 = acc[mi][ni][h * 2 + 0] + __ldg(&bias[col]);
                float v1 = acc[mi][ni][h * 2 + 1] + __ldg(&bias[col + 1]);
                if (EPI >= 1) {
                    v0 = v0 > 0.0f ? v0 : NEG_SLOPE * v0;
                    v1 = v1 > 0.0f ? v1 : NEG_SLOPE * v1;
                }
                if (EPI == 2) {
                    float2 o = *(const float2*)(addsrc + (size_t)row * 128 + col);
                    v0 += o.x; v1 += o.y;
                }
                if (EM != 2)
                    *(float2*)(Cf + (size_t)row * 128 + col) = make_float2(v0, v1);
                if (EM >= 1) {
                    uint32_t hh, ll;
                    split2(v0, v1, hh, ll);
                    *(uint32_t*)(Ch + (size_t)row * 128 + col) = hh;
                    *(uint32_t*)(Cl + (size_t)row * 128 + col) = ll;
                }
            }
        }
    }
}

// ---------------- classifier + log_softmax (warp per row) ----------------
__global__ void __launch_bounds__(256) cls_kernel(
        const float* __restrict__ x, const float* __restrict__ W,
        const float* __restrict__ b, float* __restrict__ out, int M) {
    __shared__ float Wt[C_OUT][128];
    __shared__ float bs[C_OUT];
    for (int i = threadIdx.x; i < 128 * C_OUT; i += 256) {
        int k = i / C_OUT, c = i % C_OUT;
        Wt[c][k] = W[i];
    }
    if (threadIdx.x < C_OUT) bs[threadIdx.x] = b[threadIdx.x];
    __syncthreads();

    int warp = threadIdx.x >> 5, lane = threadIdx.x & 31;
    int row = blockIdx.x * 8 + warp;
    if (row >= M) return;

    float xr[4];
#pragma unroll
    for (int j = 0; j < 4; j++) xr[j] = x[(size_t)row * 128 + lane + 32 * j];

    float acc[C_OUT];
#pragma unroll
    for (int c = 0; c < C_OUT; c++) {
        float a = 0.0f;
#pragma unroll
        for (int j = 0; j < 4; j++) a += xr[j] * Wt[c][lane + 32 * j];
#pragma unroll
        for (int o = 16; o > 0; o >>= 1) a += __shfl_down_sync(0xFFFFFFFFu, a, o);
        acc[c] = a;
    }
    if (lane == 0) {
        float mx = -1e30f;
#pragma unroll
        for (int c = 0; c < C_OUT; c++) { acc[c] += bs[c]; mx = fmaxf(mx, acc[c]); }
        float se = 0.0f;
#pragma unroll
        for (int c = 0; c < C_OUT; c++) se += expf(acc[c] - mx);
        float l = mx + logf(se);
#pragma unroll
        for (int c = 0; c < C_OUT; c++) out[(size_t)row * C_OUT + c] = acc[c] - l;
    }
}

// ---------------- host ----------------
static void* symaddr(const void* sym) {
    void* p = nullptr;
    cudaGetSymbolAddress(&p, sym);
    return p;
}

extern "C" void kernel_launch(void* const* d_in, const int* in_sizes, int n_in,
                              void* d_out, int out_size) {
    const float* x   = (const float*)d_in[0];
    const int*   ei  = (const int*)d_in[1];
    const float* ew  = (const float*)d_in[2];
    const float* pre_w1 = (const float*)d_in[3];  const float* pre_b1 = (const float*)d_in[4];
    const float* cw0_1  = (const float*)d_in[5];  const float* cw1_1  = (const float*)d_in[6];
    const float* cb_1   = (const float*)d_in[7];
    const float* sw_1   = (const float*)d_in[8];  const float* sb_1   = (const float*)d_in[9];
    const float* lw_1   = (const float*)d_in[10]; const float* lb_1   = (const float*)d_in[11];
    const float* pre_w2 = (const float*)d_in[12]; const float* pre_b2 = (const float*)d_in[13];
    const float* cw0_2  = (const float*)d_in[14]; const float* cw1_2  = (const float*)d_in[15];
    const float* cb_2   = (const float*)d_in[16];
    const float* sw_2   = (const float*)d_in[17]; const float* sb_2   = (const float*)d_in[18];
    const float* lw_2   = (const float*)d_in[19]; const float* lb_2   = (const float*)d_in[20];
    const float* cls_w  = (const float*)d_in[21]; const float* cls_b  = (const float*)d_in[22];
    float* out = (float*)d_out;

    int E = in_sizes[2];
    int N = in_sizes[0] / F_IN;
    const int* src = ei;
    const int* dst = ei + E;

    float* xh    = (float*)symaddr(g_xh);
    float* o2    = (float*)symaddr(g_o2);
    float* tbuf  = (float*)symaddr(g_t);
    float* deg   = (float*)symaddr(g_deg);
    float* dis   = (float*)symaddr(g_dis);
    float* loopw = (float*)symaddr(g_loopw);
    float* invc  = (float*)symaddr(g_invcnt);
    float* cntf  = (float*)symaddr(g_cntf);
    int*   hist  = (int*)symaddr(g_hist);
    int*   off   = (int*)symaddr(g_off);
    int*   cur   = (int*)symaddr(g_cursor);
    int*   bsum  = (int*)symaddr(g_bsum);
    int*   esrc  = (int*)symaddr(g_esrc);
    float* enorm = (float*)symaddr(g_enorm);
    float* ewe   = (float*)symaddr(g_ewe);
    float* W12   = (float*)symaddr(g_W12);
    float* b12   = (float*)symaddr(g_b12);
    float* Wc    = (float*)symaddr(g_Wc);
    float* bc    = (float*)symaddr(g_bc);

    __nv_bfloat16* xe_h = (__nv_bfloat16*)symaddr(g_xe_h);
    __nv_bfloat16* xe_l = (__nv_bfloat16*)symaddr(g_xe_l);
    __nv_bfloat16* xh_h = (__nv_bfloat16*)symaddr(g_xh_h);
    __nv_bfloat16* xh_l = (__nv_bfloat16*)symaddr(g_xh_l);
    __nv_bfloat16* tx_h = (__nv_bfloat16*)symaddr(g_tx_h);
    __nv_bfloat16* tx_l = (__nv_bfloat16*)symaddr(g_tx_l);
    __nv_bfloat16* s_h  = (__nv_bfloat16*)symaddr(g_s_h);
    __nv_bfloat16* s_l  = (__nv_bfloat16*)symaddr(g_s_l);
    __nv_bfloat16* t_h  = (__nv_bfloat16*)symaddr(g_t_h);
    __nv_bfloat16* t_l  = (__nv_bfloat16*)symaddr(g_t_l);

    __nv_bfloat16* Bpre1  = (__nv_bfloat16*)symaddr(g_Bpre1);
    __nv_bfloat16* Bcw0_1 = (__nv_bfloat16*)symaddr(g_Bcw0_1);
    __nv_bfloat16* Bcw1_1 = (__nv_bfloat16*)symaddr(g_Bcw1_1);
    __nv_bfloat16* Bsw1   = (__nv_bfloat16*)symaddr(g_Bsw1);
    __nv_bfloat16* BW12   = (__nv_bfloat16*)symaddr(g_BW12);
    __nv_bfloat16* Bcw0_2 = (__nv_bfloat16*)symaddr(g_Bcw0_2);
    __nv_bfloat16* Bcw1_2 = (__nv_bfloat16*)symaddr(g_Bcw1_2);
    __nv_bfloat16* Bsw2   = (__nv_bfloat16*)symaddr(g_Bsw2);

    // opt-in to 80KB dynamic smem for the 4 tgemm instantiations
    cudaFuncSetAttribute(tgemm<false, 0, 1>, cudaFuncAttributeMaxDynamicSharedMemorySize, TG_SMEM);
    cudaFuncSetAttribute(tgemm<false, 1, 0>, cudaFuncAttributeMaxDynamicSharedMemorySize, TG_SMEM);
    cudaFuncSetAttribute(tgemm<true, 2, 2>,  cudaFuncAttributeMaxDynamicSharedMemorySize, TG_SMEM);
    cudaFuncSetAttribute(tgemm<true, 2, 0>,  cudaFuncAttributeMaxDynamicSharedMemorySize, TG_SMEM);

    int eB = (E + 255) / 256;
    int nB = (N + 255) / 256;
    int nbScan = (N + 1023) / 1024;
    int gG = (N + 127) / 128;
    int aggB = (N * 32 + 255) / 256;

    // ---- weight fusion + prestaging ----
    wfuse<<<H + 1, H>>>(lw_1, pre_w2, lb_1, pre_b2, W12, b12, H);
    wfuse<<<H + 1, C_OUT>>>(lw_2, cls_w, lb_2, cls_b, Wc, bc, C_OUT);
    prestage_big<<<64, 256>>>(pre_w1, Bpre1);
    prestage_all<<<7 * 16, 256>>>(cw0_1, cw1_1, sw_1, W12, cw0_2, cw1_2, sw_2,
                                  Bcw0_1, Bcw1_1, Bsw1, BW12, Bcw0_2, Bcw1_2, Bsw2);

    // ---- one-time input split ----
    int total4 = N * F_IN / 4;
    convert_split<<<(total4 + 255) / 256, 256>>>(x, xe_h, xe_l, total4);

    // ---- graph-structure preprocessing ----
    init_nodes<<<nB, 256>>>(loopw, deg, cntf, hist, N);
    edge_pass1<<<eB, 256>>>(src, dst, ew, deg, cntf, loopw, hist, E);
    node_prep<<<nB, 256>>>(deg, cntf, dis, invc, N);
    scan1<<<nbScan, 256>>>(hist, bsum, N);
    scan2<<<1, 32>>>(bsum, nbScan, off, N);
    scan3<<<nbScan, 256>>>(hist, bsum, off, cur, N);
    edge_pass2<<<eB, 256>>>(src, dst, ew, dis, cur, esrc, enorm, ewe, E);

    // ---- cell 1 (512 -> 128) ----
    tgemm<false, 0, 1><<<gG, 256, TG_SMEM>>>(xe_h, xe_l, nullptr, nullptr, Bpre1, nullptr,
                                             pre_b1, nullptr, xh, xh_h, xh_l, N, 512);
    aggregate<<<aggB, 256>>>(xh, off, esrc, enorm, ewe, loopw, invc,
                             tx_h, tx_l, s_h, s_l, N);
    tgemm<false, 1, 0><<<gG, 256, TG_SMEM>>>(s_h, s_l, nullptr, nullptr, Bsw1, nullptr,
                                             sb_1, nullptr, o2, nullptr, nullptr, N, 128);
    tgemm<true, 2, 2><<<gG, 256, TG_SMEM>>>(xh_h, xh_l, tx_h, tx_l, Bcw0_1, Bcw1_1,
                                            cb_1, o2, nullptr, t_h, t_l, N, 128);

    // ---- fused lin1+pre2 ----
    tgemm<false, 0, 1><<<gG, 256, TG_SMEM>>>(t_h, t_l, nullptr, nullptr, BW12, nullptr,
                                             b12, nullptr, xh, xh_h, xh_l, N, 128);

    // ---- cell 2 (128 -> 128) ----
    aggregate<<<aggB, 256>>>(xh, off, esrc, enorm, ewe, loopw, invc,
                             tx_h, tx_l, s_h, s_l, N);
    tgemm<false, 1, 0><<<gG, 256, TG_SMEM>>>(s_h, s_l, nullptr, nullptr, Bsw2, nullptr,
                                             sb_2, nullptr, o2, nullptr, nullptr, N, 128);
    tgemm<true, 2, 0><<<gG, 256, TG_SMEM>>>(xh_h, xh_l, tx_h, tx_l, Bcw0_2, Bcw1_2,
                                            cb_2, o2, tbuf, nullptr, nullptr, N, 128);

    // ---- fused lin2 + classifier + log_softmax ----
    cls_kernel<<<(N + 7) / 8, 256>>>(tbuf, Wc, bc, out, N);
}

// round 7
// speedup vs baseline: 1.8282x; 1.0287x over previous
#include <cuda_runtime.h>
#include <cuda_bf16.h>
#include <math.h>
#include <stdint.h>

// ---------------- problem constants ----------------
#define N_MAX 40000
#define E_MAX 640000
#define F_IN  512
#define H     128
#define C_OUT 40
#define NEG_SLOPE 0.01f

// ---------------- scratch (device globals; no runtime alloc) ----------------
__device__ float g_xh [N_MAX * H];
__device__ float g_o2 [N_MAX * H];
__device__ float g_t  [N_MAX * H];

__device__ __nv_bfloat16 g_xh_h[N_MAX * H];
__device__ __nv_bfloat16 g_xh_l[N_MAX * H];
__device__ __nv_bfloat16 g_tx_h[N_MAX * H];
__device__ __nv_bfloat16 g_tx_l[N_MAX * H];
__device__ __nv_bfloat16 g_s_h [N_MAX * H];
__device__ __nv_bfloat16 g_s_l [N_MAX * H];
__device__ __nv_bfloat16 g_t_h [N_MAX * H];
__device__ __nv_bfloat16 g_t_l [N_MAX * H];

__device__ float g_deg   [N_MAX];
__device__ float g_dis   [N_MAX];
__device__ float g_loopw [N_MAX];
__device__ float g_invcnt[N_MAX];
__device__ float g_cntf  [N_MAX];
__device__ int   g_hist  [N_MAX];
__device__ int   g_off   [N_MAX + 1];
__device__ int   g_cursor[N_MAX];
__device__ int   g_bsum  [64];
__device__ int   g_esrc  [E_MAX];
__device__ float g_enorm [E_MAX];
__device__ float g_ewe   [E_MAX];

__device__ float g_W12[H * H];
__device__ float g_b12[H];
__device__ float g_Wc [H * C_OUT];
__device__ float g_bc [C_OUT];

// prestaged weights as [n=128][K] bf16, hi plane then lo plane
__device__ __nv_bfloat16 g_Bpre1 [2 * 128 * 512];
__device__ __nv_bfloat16 g_Bcw0_1[2 * 128 * 128];
__device__ __nv_bfloat16 g_Bcw1_1[2 * 128 * 128];
__device__ __nv_bfloat16 g_Bsw1  [2 * 128 * 128];
__device__ __nv_bfloat16 g_BW12  [2 * 128 * 128];
__device__ __nv_bfloat16 g_Bcw0_2[2 * 128 * 128];
__device__ __nv_bfloat16 g_Bcw1_2[2 * 128 * 128];
__device__ __nv_bfloat16 g_Bsw2  [2 * 128 * 128];

// ---------------- helpers ----------------
__device__ __forceinline__ uint32_t smem_u32(const void* p) {
    uint32_t a;
    asm("{ .reg .u64 t; cvta.to.shared.u64 t, %1; cvt.u32.u64 %0, t; }"
        : "=r"(a) : "l"(p));
    return a;
}
__device__ __forceinline__ void split2(float a, float b, uint32_t& h, uint32_t& l) {
    asm("cvt.rn.bf16x2.f32 %0,%1,%2;" : "=r"(h) : "f"(b), "f"(a));
    float fa = __uint_as_float(h << 16);
    float fb = __uint_as_float(h & 0xFFFF0000u);
    float la = a - fa, lb = b - fb;
    asm("cvt.rn.bf16x2.f32 %0,%1,%2;" : "=r"(l) : "f"(lb), "f"(la));
}
__device__ __forceinline__ void ldm4(uint32_t* r, uint32_t addr) {
    asm volatile("ldmatrix.sync.aligned.m8n8.x4.shared.b16 {%0,%1,%2,%3},[%4];"
                 : "=r"(r[0]), "=r"(r[1]), "=r"(r[2]), "=r"(r[3]) : "r"(addr));
}
__device__ __forceinline__ void mma16816(float* d, const uint32_t* a, uint32_t b0, uint32_t b1) {
    asm volatile("mma.sync.aligned.m16n8k16.row.col.f32.bf16.bf16.f32 "
                 "{%0,%1,%2,%3},{%4,%5,%6,%7},{%8,%9},{%0,%1,%2,%3};"
                 : "+f"(d[0]), "+f"(d[1]), "+f"(d[2]), "+f"(d[3])
                 : "r"(a[0]), "r"(a[1]), "r"(a[2]), "r"(a[3]), "r"(b0), "r"(b1));
}
__device__ __forceinline__ void cp16(uint32_t dst, const void* src, int szbytes) {
    asm volatile("cp.async.cg.shared.global [%0],[%1],16,%2;"
                 :: "r"(dst), "l"(src), "r"(szbytes));
}
template<int NN> __device__ __forceinline__ void cp_wait() {
    asm volatile("cp.async.wait_group %0;" :: "n"(NN));
}

// ---------------- small utility kernels ----------------
__global__ void init_nodes(float* loopw, float* deg, float* cntf, int* hist, int n) {
    int i = blockIdx.x * blockDim.x + threadIdx.x;
    if (i < n) { loopw[i] = 1.0f; deg[i] = 0.0f; cntf[i] = 0.0f; hist[i] = 0; }
}

__global__ void edge_pass1(const int* __restrict__ src, const int* __restrict__ dst,
                           const float* __restrict__ w,
                           float* __restrict__ deg, float* __restrict__ cntf,
                           float* __restrict__ loopw, int* __restrict__ hist, int E) {
    int i = blockIdx.x * blockDim.x + threadIdx.x;
    if (i >= E) return;
    int s = src[i], d = dst[i];
    float wt = w[i];
    if (s == d) {
        loopw[s] = wt;
    } else {
        atomicAdd(&deg[s], wt);
        atomicAdd(&cntf[d], 1.0f);
    }
    atomicAdd(&hist[d], 1);
}

__global__ void node_prep(const float* __restrict__ deg, const float* __restrict__ cntf,
                          float* __restrict__ dis, float* __restrict__ invcnt, int N) {
    int i = blockIdx.x * blockDim.x + threadIdx.x;
    if (i >= N) return;
    float dg = deg[i];
    dis[i]    = (dg > 0.0f) ? rsqrtf(dg) : 0.0f;
    invcnt[i] = 1.0f / (cntf[i] + 1.0f);
}

__global__ void scan1(const int* __restrict__ hist, int* __restrict__ bsum, int n) {
    __shared__ int sh[256];
    int base = blockIdx.x * 1024;
    int s = 0;
#pragma unroll
    for (int j = 0; j < 4; j++) {
        int i = base + threadIdx.x + j * 256;
        s += (i < n) ? hist[i] : 0;
    }
    sh[threadIdx.x] = s;
    __syncthreads();
    for (int o = 128; o > 0; o >>= 1) {
        if (threadIdx.x < o) sh[threadIdx.x] += sh[threadIdx.x + o];
        __syncthreads();
    }
    if (threadIdx.x == 0) bsum[blockIdx.x] = sh[0];
}
__global__ void scan2(int* __restrict__ bsum, int nb, int* __restrict__ off, int n) {
    if (threadIdx.x == 0) {
        int run = 0;
        for (int i = 0; i < nb; i++) { int v = bsum[i]; bsum[i] = run; run += v; }
        off[n] = run;
    }
}
__global__ void scan3(const int* __restrict__ hist, const int* __restrict__ bsum,
                      int* __restrict__ off, int* __restrict__ cursor, int n) {
    __shared__ int sh[256];
    int base = blockIdx.x * 1024 + threadIdx.x * 4;
    int v[4]; int s = 0;
#pragma unroll
    for (int j = 0; j < 4; j++) {
        int i = base + j;
        v[j] = (i < n) ? hist[i] : 0;
        s += v[j];
    }
    sh[threadIdx.x] = s;
    __syncthreads();
    for (int o = 1; o < 256; o <<= 1) {
        int t = (threadIdx.x >= o) ? sh[threadIdx.x - o] : 0;
        __syncthreads();
        sh[threadIdx.x] += t;
        __syncthreads();
    }
    int run = bsum[blockIdx.x] + sh[threadIdx.x] - s;
#pragma unroll
    for (int j = 0; j < 4; j++) {
        int i = base + j;
        if (i < n) { off[i] = run; cursor[i] = run; }
        run += v[j];
    }
}

__global__ void edge_pass2(const int* __restrict__ src, const int* __restrict__ dst,
                           const float* __restrict__ w, const float* __restrict__ dis,
                           int* __restrict__ cursor,
                           int* __restrict__ esrc, float* __restrict__ enorm,
                           float* __restrict__ ewe, int E) {
    int i = blockIdx.x * blockDim.x + threadIdx.x;
    if (i >= E) return;
    int s = src[i], d = dst[i];
    float wt = w[i];
    float wc = (s == d) ? 0.0f : wt;
    float nm = -dis[s] * wc * dis[d];
    int pos = atomicAdd(&cursor[d], 1);
    esrc[pos]  = s;
    enorm[pos] = nm;
    ewe[pos]   = wc;
}

// warp-per-node CSR aggregation with fused sage-mean; emits bf16 hi/lo planes
__global__ void __launch_bounds__(256) aggregate(
        const float* __restrict__ xh, const int* __restrict__ off,
        const int* __restrict__ esrc, const float* __restrict__ enorm,
        const float* __restrict__ ewe,
        const float* __restrict__ loopw, const float* __restrict__ invcnt,
        __nv_bfloat16* __restrict__ txh, __nv_bfloat16* __restrict__ txl,
        __nv_bfloat16* __restrict__ sh,  __nv_bfloat16* __restrict__ sl, int N) {
    int warp = (blockIdx.x * blockDim.x + threadIdx.x) >> 5;
    int lane = threadIdx.x & 31;
    if (warp >= N) return;
    int beg = off[warp], end = off[warp + 1];
    const float4* xh4 = (const float4*)xh;
    float4 a1 = make_float4(0, 0, 0, 0);
    float4 a2 = make_float4(0, 0, 0, 0);
    int j = beg;
    for (; j + 4 <= end; j += 4) {
        int   s0 = __ldg(&esrc[j]),     s1 = __ldg(&esrc[j + 1]);
        int   s2 = __ldg(&esrc[j + 2]), s3 = __ldg(&esrc[j + 3]);
        float n0 = __ldg(&enorm[j]),     n1 = __ldg(&enorm[j + 1]);
        float n2 = __ldg(&enorm[j + 2]), n3 = __ldg(&enorm[j + 3]);
        float w0 = __ldg(&ewe[j]),       w1 = __ldg(&ewe[j + 1]);
        float w2 = __ldg(&ewe[j + 2]),   w3 = __ldg(&ewe[j + 3]);
        float4 v0 = __ldg(&xh4[(size_t)s0 * 32 + lane]);
        float4 v1 = __ldg(&xh4[(size_t)s1 * 32 + lane]);
        float4 v2 = __ldg(&xh4[(size_t)s2 * 32 + lane]);
        float4 v3 = __ldg(&xh4[(size_t)s3 * 32 + lane]);
        a1.x += n0 * v0.x + n1 * v1.x + n2 * v2.x + n3 * v3.x;
        a1.y += n0 * v0.y + n1 * v1.y + n2 * v2.y + n3 * v3.y;
        a1.z += n0 * v0.z + n1 * v1.z + n2 * v2.z + n3 * v3.z;
        a1.w += n0 * v0.w + n1 * v1.w + n2 * v2.w + n3 * v3.w;
        a2.x += w0 * v0.x + w1 * v1.x + w2 * v2.x + w3 * v3.x;
        a2.y += w0 * v0.y + w1 * v1.y + w2 * v2.y + w3 * v3.y;
        a2.z += w0 * v0.z + w1 * v1.z + w2 * v2.z + w3 * v3.z;
        a2.w += w0 * v0.w + w1 * v1.w + w2 * v2.w + w3 * v3.w;
    }
    for (; j < end; j++) {
        int sn = __ldg(&esrc[j]);
        float nm = __ldg(&enorm[j]);
        float we = __ldg(&ewe[j]);
        float4 v = __ldg(&xh4[(size_t)sn * 32 + lane]);
        a1.x += nm * v.x; a1.y += nm * v.y; a1.z += nm * v.z; a1.w += nm * v.w;
        a2.x += we * v.x; a2.y += we * v.y; a2.z += we * v.z; a2.w += we * v.w;
    }
    float lw = __ldg(&loopw[warp]);
    float ic = __ldg(&invcnt[warp]);
    float4 xv = __ldg(&xh4[(size_t)warp * 32 + lane]);
    a2.x = (a2.x + lw * xv.x) * ic;
    a2.y = (a2.y + lw * xv.y) * ic;
    a2.z = (a2.z + lw * xv.z) * ic;
    a2.w = (a2.w + lw * xv.w) * ic;
    uint32_t h0, l0, h1, l1;
    int idx = warp * 32 + lane;
    split2(a1.x, a1.y, h0, l0);
    split2(a1.z, a1.w, h1, l1);
    ((uint2*)txh)[idx] = make_uint2(h0, h1);
    ((uint2*)txl)[idx] = make_uint2(l0, l1);
    split2(a2.x, a2.y, h0, l0);
    split2(a2.z, a2.w, h1, l1);
    ((uint2*)sh)[idx] = make_uint2(h0, h1);
    ((uint2*)sl)[idx] = make_uint2(l0, l1);
}

// weight pre-fusion: W = A@B (row-major), bias fold
__global__ void wfuse(const float* __restrict__ A, const float* __restrict__ B,
                      const float* __restrict__ bA, const float* __restrict__ bB,
                      float* __restrict__ W, float* __restrict__ bOut, int K2) {
    int c = threadIdx.x;
    if (blockIdx.x < H) {
        int row = blockIdx.x;
        float acc = 0.0f;
        for (int j = 0; j < H; j++) acc += __ldg(&A[row * H + j]) * __ldg(&B[j * K2 + c]);
        W[row * K2 + c] = acc;
    } else {
        float acc = bB[c];
        for (int j = 0; j < H; j++) acc += __ldg(&bA[j]) * __ldg(&B[j * K2 + c]);
        bOut[c] = acc;
    }
}

// prestage one weight W[K][128] -> planes [n][K]: hi then lo
__device__ __forceinline__ void prestage_one(const float* __restrict__ W,
                                             __nv_bfloat16* __restrict__ out,
                                             int K, int kshift, int tid, int nthreads) {
    int total = 128 * K;
    for (int i = tid; i < total; i += nthreads) {
        int n = i >> kshift, k = i & (K - 1);
        float v = __ldg(&W[(size_t)k * 128 + n]);
        __nv_bfloat16 h = __float2bfloat16(v);
        out[i] = h;
        out[total + i] = __float2bfloat16(v - __bfloat162float(h));
    }
}

__global__ void prestage_all(
        const float* W0, const float* W1, const float* W2, const float* W3,
        const float* W4, const float* W5, const float* W6,
        __nv_bfloat16* O0, __nv_bfloat16* O1, __nv_bfloat16* O2, __nv_bfloat16* O3,
        __nv_bfloat16* O4, __nv_bfloat16* O5, __nv_bfloat16* O6) {
    int wsel = blockIdx.x >> 4;
    int bi = blockIdx.x & 15;
    const float* W; __nv_bfloat16* O;
    switch (wsel) {
        case 0: W = W0; O = O0; break;
        case 1: W = W1; O = O1; break;
        case 2: W = W2; O = O2; break;
        case 3: W = W3; O = O3; break;
        case 4: W = W4; O = O4; break;
        case 5: W = W5; O = O5; break;
        default: W = W6; O = O6; break;
    }
    prestage_one(W, O, 128, 7, bi * 256 + threadIdx.x, 16 * 256);
}

__global__ void prestage_big(const float* __restrict__ W, __nv_bfloat16* __restrict__ out) {
    prestage_one(W, out, 512, 9, blockIdx.x * 256 + threadIdx.x, gridDim.x * 256);
}

// ---------------- HMMA GEMM (planes input), 2-stage cp.async pipeline ----------------
#define TG_STRIDE 40
#define ARR_B 10240
#define STAGE_B 40960
#define TG_SMEM (2 * STAGE_B)

template<bool DUAL, int EPI, int EM>
__global__ void __launch_bounds__(256, 2) tgemm(
        const __nv_bfloat16* __restrict__ Ah0, const __nv_bfloat16* __restrict__ Al0,
        const __nv_bfloat16* __restrict__ Ah1, const __nv_bfloat16* __restrict__ Al1,
        const __nv_bfloat16* __restrict__ B0, const __nv_bfloat16* __restrict__ B1,
        const float* __restrict__ bias, const float* __restrict__ addsrc,
        float* __restrict__ Cf, __nv_bfloat16* __restrict__ Ch, __nv_bfloat16* __restrict__ Cl,
        int M, int K) {
    extern __shared__ __align__(16) char dsm[];
    uint32_t base = smem_u32(dsm);

    int tid = threadIdx.x, lane = tid & 31, warp = tid >> 5;
    int warp_m = warp & 3, warp_n = warp >> 2;
    int brow = blockIdx.x * 128;

    int lr = lane & 7;
    int a_off = ((warp_m * 32 + ((lane >> 3) & 1) * 8 + lr) * TG_STRIDE + (lane >> 4) * 8) * 2;
    int b_off = ((warp_n * 64 + ((lane >> 4) & 1) * 8 + lr) * TG_STRIDE + ((lane >> 3) & 1) * 8) * 2;

    float acc[2][8][4];
#pragma unroll
    for (int mi = 0; mi < 2; mi++)
#pragma unroll
        for (int ni = 0; ni < 8; ni++)
#pragma unroll
            for (int c = 0; c < 4; c++) acc[mi][ni][c] = 0.0f;

    int r = tid >> 1, half = tid & 1;
    int grow = brow + r;
    bool rowok = grow < M;
    int growc = rowok ? grow : (M - 1);
    int asz = rowok ? 16 : 0;
    uint32_t s_a = r * (TG_STRIDE * 2) + half * 32;
    int cpa = K >> 5;
    int total = DUAL ? cpa * 2 : cpa;

    auto issue = [&](int c, int stage) {
        int st = (DUAL && c >= cpa) ? 1 : 0;
        int ci = c - (st ? cpa : 0);
        const __nv_bfloat16* Ah = st ? Ah1 : Ah0;
        const __nv_bfloat16* Al = st ? Al1 : Al0;
        const __nv_bfloat16* Bp = st ? B1 : B0;
        int k0 = ci << 5;
        uint32_t sb = base + stage * STAGE_B + s_a;
        const char* gah = (const char*)(Ah + (size_t)growc * K + k0 + half * 16);
        const char* gal = (const char*)(Al + (size_t)growc * K + k0 + half * 16);
        const char* gbh = (const char*)(Bp + (size_t)r * K + k0 + half * 16);
        const char* gbl = (const char*)(Bp + (size_t)128 * K + (size_t)r * K + k0 + half * 16);
        cp16(sb,                gah,      asz);
        cp16(sb + 16,           gah + 16, asz);
        cp16(sb + ARR_B,        gal,      asz);
        cp16(sb + ARR_B + 16,   gal + 16, asz);
        cp16(sb + 2 * ARR_B,      gbh,      16);
        cp16(sb + 2 * ARR_B + 16, gbh + 16, 16);
        cp16(sb + 3 * ARR_B,      gbl,      16);
        cp16(sb + 3 * ARR_B + 16, gbl + 16, 16);
        asm volatile("cp.async.commit_group;");
    };

    issue(0, 0);
    for (int c = 0; c < total; c++) {
        int cur = c & 1;
        if (c + 1 < total) { issue(c + 1, cur ^ 1); cp_wait<1>(); }
        else               { cp_wait<0>(); }
        __syncthreads();

        uint32_t uAh = base + cur * STAGE_B;
        uint32_t uAl = uAh + ARR_B;
        uint32_t uBh = uAh + 2 * ARR_B;
        uint32_t uBl = uAh + 3 * ARR_B;
#pragma unroll
        for (int ks = 0; ks < 2; ks++) {
            int ko = ks * 32;
            uint32_t afh[2][4], afl[2][4], bfr[4][4];
#pragma unroll
            for (int nj = 0; nj < 4; nj++)
                ldm4(bfr[nj], uBh + b_off + ko + nj * 16 * TG_STRIDE * 2);
#pragma unroll
            for (int mi = 0; mi < 2; mi++) {
                ldm4(afh[mi], uAh + a_off + ko + mi * 16 * TG_STRIDE * 2);
                ldm4(afl[mi], uAl + a_off + ko + mi * 16 * TG_STRIDE * 2);
            }
#pragma unroll
            for (int mi = 0; mi < 2; mi++)
#pragma unroll
                for (int ni = 0; ni < 8; ni++)
                    mma16816(acc[mi][ni], afh[mi], bfr[ni >> 1][(ni & 1) * 2],
                             bfr[ni >> 1][(ni & 1) * 2 + 1]);
#pragma unroll
            for (int mi = 0; mi < 2; mi++)
#pragma unroll
                for (int ni = 0; ni < 8; ni++)
                    mma16816(acc[mi][ni], afl[mi], bfr[ni >> 1][(ni & 1) * 2],
                             bfr[ni >> 1][(ni & 1) * 2 + 1]);
#pragma unroll
            for (int nj = 0; nj < 4; nj++)
                ldm4(bfr[nj], uBl + b_off + ko + nj * 16 * TG_STRIDE * 2);
#pragma unroll
            for (int mi = 0; mi < 2; mi++)
#pragma unroll
                for (int ni = 0; ni < 8; ni++)
                    mma16816(acc[mi][ni], afh[mi], bfr[ni >> 1][(ni & 1) * 2],
                             bfr[ni >> 1][(ni & 1) * 2 + 1]);
        }
        __syncthreads();
    }

    int g = lane >> 2, tg = lane & 3;
#pragma unroll
    for (int mi = 0; mi < 2; mi++) {
#pragma unroll
        for (int h = 0; h < 2; h++) {
            int row = brow + warp_m * 32 + mi * 16 + h * 8 + g;
            if (row >= M) continue;
#pragma unroll
            for (int ni = 0; ni < 8; ni++) {
                int col = warp_n * 64 + ni * 8 + tg * 2;
                float v0 = acc[mi][ni][h * 2 + 0] + __ldg(&bias[col]);
                float v1 = acc[mi][ni][h * 2 + 1] + __ldg(&bias[col + 1]);
                if (EPI >= 1) {
                    v0 = v0 > 0.0f ? v0 : NEG_SLOPE * v0;
                    v1 = v1 > 0.0f ? v1 : NEG_SLOPE * v1;
                }
                if (EPI == 2) {
                    float2 o = *(const float2*)(addsrc + (size_t)row * 128 + col);
                    v0 += o.x; v1 += o.y;
                }
                if (EM != 2)
                    *(float2*)(Cf + (size_t)row * 128 + col) = make_float2(v0, v1);
                if (EM >= 1) {
                    uint32_t hh, ll;
                    split2(v0, v1, hh, ll);
                    *(uint32_t*)(Ch + (size_t)row * 128 + col) = hh;
                    *(uint32_t*)(Cl + (size_t)row * 128 + col) = ll;
                }
            }
        }
    }
}

// ---------------- HMMA GEMM with in-kernel fp32->split conversion (K=512) ----------
// smem: Af32 2x16K | (Bh+Bl) 2x20K | Ah 10K | Al 10K  = 92KB
#define CV_AF(s) ((s) * 16384)
#define CV_BH(s) (32768 + (s) * 20480)
#define CV_BL(s) (32768 + (s) * 20480 + 10240)
#define CV_AH 73728
#define CV_AL (73728 + 10240)
#define CV_SMEM 94208

__global__ void __launch_bounds__(256, 2) tgemm_conv(
        const float* __restrict__ Af, const __nv_bfloat16* __restrict__ B0,
        const float* __restrict__ bias,
        float* __restrict__ Cf, __nv_bfloat16* __restrict__ Ch, __nv_bfloat16* __restrict__ Cl,
        int M, int K) {
    extern __shared__ __align__(16) char dsm[];
    uint32_t base = smem_u32(dsm);

    int tid = threadIdx.x, lane = tid & 31, warp = tid >> 5;
    int warp_m = warp & 3, warp_n = warp >> 2;
    int brow = blockIdx.x * 128;

    int lr = lane & 7;
    int a_off = ((warp_m * 32 + ((lane >> 3) & 1) * 8 + lr) * TG_STRIDE + (lane >> 4) * 8) * 2;
    int b_off = ((warp_n * 64 + ((lane >> 4) & 1) * 8 + lr) * TG_STRIDE + ((lane >> 3) & 1) * 8) * 2;

    float acc[2][8][4];
#pragma unroll
    for (int mi = 0; mi < 2; mi++)
#pragma unroll
        for (int ni = 0; ni < 8; ni++)
#pragma unroll
            for (int c = 0; c < 4; c++) acc[mi][ni][c] = 0.0f;

    int r = tid >> 1, half = tid & 1;
    int grow = brow + r;
    bool rowok = grow < M;
    int growc = rowok ? grow : (M - 1);
    int asz = rowok ? 16 : 0;
    uint32_t s_b = r * (TG_STRIDE * 2) + half * 32;   // bf16 row offset (bytes)
    uint32_t s_f = r * 128 + half * 64;               // fp32 row offset (bytes)
    int nk = K >> 5;

    auto issue = [&](int c, int stage) {
        int k0 = c << 5;
        const char* ga  = (const char*)(Af + (size_t)growc * K + k0 + half * 16);
        const char* gbh = (const char*)(B0 + (size_t)r * K + k0 + half * 16);
        const char* gbl = (const char*)(B0 + (size_t)128 * K + (size_t)r * K + k0 + half * 16);
        uint32_t af = base + CV_AF(stage) + s_f;
        cp16(af,      ga,      asz);
        cp16(af + 16, ga + 16, asz);
        cp16(af + 32, ga + 32, asz);
        cp16(af + 48, ga + 48, asz);
        uint32_t bh = base + CV_BH(stage) + s_b;
        uint32_t bl = base + CV_BL(stage) + s_b;
        cp16(bh,      gbh,      16);
        cp16(bh + 16, gbh + 16, 16);
        cp16(bl,      gbl,      16);
        cp16(bl + 16, gbl + 16, 16);
        asm volatile("cp.async.commit_group;");
    };

    issue(0, 0);
    for (int c = 0; c < nk; c++) {
        int cur = c & 1;
        if (c + 1 < nk) { issue(c + 1, cur ^ 1); cp_wait<1>(); }
        else            { cp_wait<0>(); }
        __syncthreads();   // Af32/B[cur] visible; prior MMAs (which read AH/AL) done

        // convert this thread's 16 fp32 -> hi/lo bf16 planes in smem
        {
            const float4* ap = (const float4*)(dsm + CV_AF(cur) + s_f);
            float4 f0 = ap[0], f1 = ap[1], f2 = ap[2], f3 = ap[3];
            uint32_t h[8], l[8];
            split2(f0.x, f0.y, h[0], l[0]); split2(f0.z, f0.w, h[1], l[1]);
            split2(f1.x, f1.y, h[2], l[2]); split2(f1.z, f1.w, h[3], l[3]);
            split2(f2.x, f2.y, h[4], l[4]); split2(f2.z, f2.w, h[5], l[5]);
            split2(f3.x, f3.y, h[6], l[6]); split2(f3.z, f3.w, h[7], l[7]);
            uint4* hp = (uint4*)(dsm + CV_AH + s_b);
            uint4* lp = (uint4*)(dsm + CV_AL + s_b);
            hp[0] = make_uint4(h[0], h[1], h[2], h[3]);
            hp[1] = make_uint4(h[4], h[5], h[6], h[7]);
            lp[0] = make_uint4(l[0], l[1], l[2], l[3]);
            lp[1] = make_uint4(l[4], l[5], l[6], l[7]);
        }
        __syncthreads();

        uint32_t uAh = base + CV_AH;
        uint32_t uAl = base + CV_AL;
        uint32_t uBh = base + CV_BH(cur);
        uint32_t uBl = base + CV_BL(cur);
#pragma unroll
        for (int ks = 0; ks < 2; ks++) {
            int ko = ks * 32;
            uint32_t afh[2][4], afl[2][4], bfr[4][4];
#pragma unroll
            for (int nj = 0; nj < 4; nj++)
                ldm4(bfr[nj], uBh + b_off + ko + nj * 16 * TG_STRIDE * 2);
#pragma unroll
            for (int mi = 0; mi < 2; mi++) {
                ldm4(afh[mi], uAh + a_off + ko + mi * 16 * TG_STRIDE * 2);
                ldm4(afl[mi], uAl + a_off + ko + mi * 16 * TG_STRIDE * 2);
            }
#pragma unroll
            for (int mi = 0; mi < 2; mi++)
#pragma unroll
                for (int ni = 0; ni < 8; ni++)
                    mma16816(acc[mi][ni], afh[mi], bfr[ni >> 1][(ni & 1) * 2],
                             bfr[ni >> 1][(ni & 1) * 2 + 1]);
#pragma unroll
            for (int mi = 0; mi < 2; mi++)
#pragma unroll
                for (int ni = 0; ni < 8; ni++)
                    mma16816(acc[mi][ni], afl[mi], bfr[ni >> 1][(ni & 1) * 2],
                             bfr[ni >> 1][(ni & 1) * 2 + 1]);
#pragma unroll
            for (int nj = 0; nj < 4; nj++)
                ldm4(bfr[nj], uBl + b_off + ko + nj * 16 * TG_STRIDE * 2);
#pragma unroll
            for (int mi = 0; mi < 2; mi++)
#pragma unroll
                for (int ni = 0; ni < 8; ni++)
                    mma16816(acc[mi][ni], afh[mi], bfr[ni >> 1][(ni & 1) * 2],
                             bfr[ni >> 1][(ni & 1) * 2 + 1]);
        }
        __syncthreads();   // MMAs done before next convert overwrites AH/AL
    }

    int g = lane >> 2, tg = lane & 3;
#pragma unroll
    for (int mi = 0; mi < 2; mi++) {
#pragma unroll
        for (int h = 0; h < 2; h++) {
            int row = brow + warp_m * 32 + mi * 16 + h * 8 + g;
            if (row >= M) continue;
#pragma unroll
            for (int ni = 0; ni < 8; ni++) {
                int col = warp_n * 64 + ni * 8 + tg * 2;
                float v0 = acc[mi][ni][h * 2 + 0] + __ldg(&bias[col]);
                float v1 = acc[mi][ni][h * 2 + 1] + __ldg(&bias[col + 1]);
                *(float2*)(Cf + (size_t)row * 128 + col) = make_float2(v0, v1);
                uint32_t hh, ll;
                split2(v0, v1, hh, ll);
                *(uint32_t*)(Ch + (size_t)row * 128 + col) = hh;
                *(uint32_t*)(Cl + (size_t)row * 128 + col) = ll;
            }
        }
    }
}

// ---------------- classifier + log_softmax (warp per row) ----------------
__global__ void __launch_bounds__(256) cls_kernel(
        const float* __restrict__ x, const float* __restrict__ W,
        const float* __restrict__ b, float* __restrict__ out, int M) {
    __shared__ float Wt[C_OUT][128];
    __shared__ float bs[C_OUT];
    for (int i = threadIdx.x; i < 128 * C_OUT; i += 256) {
        int k = i / C_OUT, c = i % C_OUT;
        Wt[c][k] = W[i];
    }
    if (threadIdx.x < C_OUT) bs[threadIdx.x] = b[threadIdx.x];
    __syncthreads();

    int warp = threadIdx.x >> 5, lane = threadIdx.x & 31;
    int row = blockIdx.x * 8 + warp;
    if (row >= M) return;

    float xr[4];
#pragma unroll
    for (int j = 0; j < 4; j++) xr[j] = x[(size_t)row * 128 + lane + 32 * j];

    float acc[C_OUT];
#pragma unroll
    for (int c = 0; c < C_OUT; c++) {
        float a = 0.0f;
#pragma unroll
        for (int j = 0; j < 4; j++) a += xr[j] * Wt[c][lane + 32 * j];
#pragma unroll
        for (int o = 16; o > 0; o >>= 1) a += __shfl_down_sync(0xFFFFFFFFu, a, o);
        acc[c] = a;
    }
    if (lane == 0) {
        float mx = -1e30f;
#pragma unroll
        for (int c = 0; c < C_OUT; c++) { acc[c] += bs[c]; mx = fmaxf(mx, acc[c]); }
        float se = 0.0f;
#pragma unroll
        for (int c = 0; c < C_OUT; c++) se += expf(acc[c] - mx);
        float l = mx + logf(se);
#pragma unroll
        for (int c = 0; c < C_OUT; c++) out[(size_t)row * C_OUT + c] = acc[c] - l;
    }
}

// ---------------- host ----------------
static void* symaddr(const void* sym) {
    void* p = nullptr;
    cudaGetSymbolAddress(&p, sym);
    return p;
}

extern "C" void kernel_launch(void* const* d_in, const int* in_sizes, int n_in,
                              void* d_out, int out_size) {
    const float* x   = (const float*)d_in[0];
    const int*   ei  = (const int*)d_in[1];
    const float* ew  = (const float*)d_in[2];
    const float* pre_w1 = (const float*)d_in[3];  const float* pre_b1 = (const float*)d_in[4];
    const float* cw0_1  = (const float*)d_in[5];  const float* cw1_1  = (const float*)d_in[6];
    const float* cb_1   = (const float*)d_in[7];
    const float* sw_1   = (const float*)d_in[8];  const float* sb_1   = (const float*)d_in[9];
    const float* lw_1   = (const float*)d_in[10]; const float* lb_1   = (const float*)d_in[11];
    const float* pre_w2 = (const float*)d_in[12]; const float* pre_b2 = (const float*)d_in[13];
    const float* cw0_2  = (const float*)d_in[14]; const float* cw1_2  = (const float*)d_in[15];
    const float* cb_2   = (const float*)d_in[16];
    const float* sw_2   = (const float*)d_in[17]; const float* sb_2   = (const float*)d_in[18];
    const float* lw_2   = (const float*)d_in[19]; const float* lb_2   = (const float*)d_in[20];
    const float* cls_w  = (const float*)d_in[21]; const float* cls_b  = (const float*)d_in[22];
    float* out = (float*)d_out;

    int E = in_sizes[2];
    int N = in_sizes[0] / F_IN;
    const int* src = ei;
    const int* dst = ei + E;

    float* xh    = (float*)symaddr(g_xh);
    float* o2    = (float*)symaddr(g_o2);
    float* tbuf  = (float*)symaddr(g_t);
    float* deg   = (float*)symaddr(g_deg);
    float* dis   = (float*)symaddr(g_dis);
    float* loopw = (float*)symaddr(g_loopw);
    float* invc  = (float*)symaddr(g_invcnt);
    float* cntf  = (float*)symaddr(g_cntf);
    int*   hist  = (int*)symaddr(g_hist);
    int*   off   = (int*)symaddr(g_off);
    int*   cur   = (int*)symaddr(g_cursor);
    int*   bsum  = (int*)symaddr(g_bsum);
    int*   esrc  = (int*)symaddr(g_esrc);
    float* enorm = (float*)symaddr(g_enorm);
    float* ewe   = (float*)symaddr(g_ewe);
    float* W12   = (float*)symaddr(g_W12);
    float* b12   = (float*)symaddr(g_b12);
    float* Wc    = (float*)symaddr(g_Wc);
    float* bc    = (float*)symaddr(g_bc);

    __nv_bfloat16* xh_h = (__nv_bfloat16*)symaddr(g_xh_h);
    __nv_bfloat16* xh_l = (__nv_bfloat16*)symaddr(g_xh_l);
    __nv_bfloat16* tx_h = (__nv_bfloat16*)symaddr(g_tx_h);
    __nv_bfloat16* tx_l = (__nv_bfloat16*)symaddr(g_tx_l);
    __nv_bfloat16* s_h  = (__nv_bfloat16*)symaddr(g_s_h);
    __nv_bfloat16* s_l  = (__nv_bfloat16*)symaddr(g_s_l);
    __nv_bfloat16* t_h  = (__nv_bfloat16*)symaddr(g_t_h);
    __nv_bfloat16* t_l  = (__nv_bfloat16*)symaddr(g_t_l);

    __nv_bfloat16* Bpre1  = (__nv_bfloat16*)symaddr(g_Bpre1);
    __nv_bfloat16* Bcw0_1 = (__nv_bfloat16*)symaddr(g_Bcw0_1);
    __nv_bfloat16* Bcw1_1 = (__nv_bfloat16*)symaddr(g_Bcw1_1);
    __nv_bfloat16* Bsw1   = (__nv_bfloat16*)symaddr(g_Bsw1);
    __nv_bfloat16* BW12   = (__nv_bfloat16*)symaddr(g_BW12);
    __nv_bfloat16* Bcw0_2 = (__nv_bfloat16*)symaddr(g_Bcw0_2);
    __nv_bfloat16* Bcw1_2 = (__nv_bfloat16*)symaddr(g_Bcw1_2);
    __nv_bfloat16* Bsw2   = (__nv_bfloat16*)symaddr(g_Bsw2);

    cudaFuncSetAttribute(tgemm<false, 1, 0>, cudaFuncAttributeMaxDynamicSharedMemorySize, TG_SMEM);
    cudaFuncSetAttribute(tgemm<false, 0, 1>, cudaFuncAttributeMaxDynamicSharedMemorySize, TG_SMEM);
    cudaFuncSetAttribute(tgemm<true, 2, 2>,  cudaFuncAttributeMaxDynamicSharedMemorySize, TG_SMEM);
    cudaFuncSetAttribute(tgemm<true, 2, 0>,  cudaFuncAttributeMaxDynamicSharedMemorySize, TG_SMEM);
    cudaFuncSetAttribute(tgemm_conv,         cudaFuncAttributeMaxDynamicSharedMemorySize, CV_SMEM);

    int eB = (E + 255) / 256;
    int nB = (N + 255) / 256;
    int nbScan = (N + 1023) / 1024;
    int gG = (N + 127) / 128;
    int aggB = (N * 32 + 255) / 256;

    // launches #1-#3
    wfuse<<<H + 1, H>>>(lw_1, pre_w2, lb_1, pre_b2, W12, b12, H);
    wfuse<<<H + 1, C_OUT>>>(lw_2, cls_w, lb_2, cls_b, Wc, bc, C_OUT);
    prestage_big<<<64, 256>>>(pre_w1, Bpre1);

    // launch #4: the K=512 GEMM (ncu captures the 4th launch)
    tgemm_conv<<<gG, 256, CV_SMEM>>>(x, Bpre1, pre_b1, xh, xh_h, xh_l, N, 512);

    prestage_all<<<7 * 16, 256>>>(cw0_1, cw1_1, sw_1, W12, cw0_2, cw1_2, sw_2,
                                  Bcw0_1, Bcw1_1, Bsw1, BW12, Bcw0_2, Bcw1_2, Bsw2);

    // ---- graph-structure preprocessing ----
    init_nodes<<<nB, 256>>>(loopw, deg, cntf, hist, N);
    edge_pass1<<<eB, 256>>>(src, dst, ew, deg, cntf, loopw, hist, E);
    node_prep<<<nB, 256>>>(deg, cntf, dis, invc, N);
    scan1<<<nbScan, 256>>>(hist, bsum, N);
    scan2<<<1, 32>>>(bsum, nbScan, off, N);
    scan3<<<nbScan, 256>>>(hist, bsum, off, cur, N);
    edge_pass2<<<eB, 256>>>(src, dst, ew, dis, cur, esrc, enorm, ewe, E);

    // ---- cell 1 ----
    aggregate<<<aggB, 256>>>(xh, off, esrc, enorm, ewe, loopw, invc,
                             tx_h, tx_l, s_h, s_l, N);
    tgemm<false, 1, 0><<<gG, 256, TG_SMEM>>>(s_h, s_l, nullptr, nullptr, Bsw1, nullptr,
                                             sb_1, nullptr, o2, nullptr, nullptr, N, 128);
    tgemm<true, 2, 2><<<gG, 256, TG_SMEM>>>(xh_h, xh_l, tx_h, tx_l, Bcw0_1, Bcw1_1,
                                            cb_1, o2, nullptr, t_h, t_l, N, 128);

    // ---- fused lin1+pre2 ----
    tgemm<false, 0, 1><<<gG, 256, TG_SMEM>>>(t_h, t_l, nullptr, nullptr, BW12, nullptr,
                                             b12, nullptr, xh, xh_h, xh_l, N, 128);

    // ---- cell 2 ----
    aggregate<<<aggB, 256>>>(xh, off, esrc, enorm, ewe, loopw, invc,
                             tx_h, tx_l, s_h, s_l, N);
    tgemm<false, 1, 0><<<gG, 256, TG_SMEM>>>(s_h, s_l, nullptr, nullptr, Bsw2, nullptr,
                                             sb_2, nullptr, o2, nullptr, nullptr, N, 128);
    tgemm<true, 2, 0><<<gG, 256, TG_SMEM>>>(xh_h, xh_l, tx_h, tx_l, Bcw0_2, Bcw1_2,
                                            cb_2, o2, tbuf, nullptr, nullptr, N, 128);

    // ---- fused lin2 + classifier + log_softmax ----
    cls_kernel<<<(N + 7) / 8, 256>>>(tbuf, Wc, bc, out, N);
}

// round 8
// speedup vs baseline: 1.9817x; 1.0839x over previous
#include <cuda_runtime.h>
#include <cuda_bf16.h>
#include <math.h>
#include <stdint.h>

// ---------------- problem constants ----------------
#define N_MAX 40000
#define E_MAX 640000
#define F_IN  512
#define H     128
#define C_OUT 40
#define NEG_SLOPE 0.01f

// ---------------- scratch (device globals; no runtime alloc) ----------------
__device__ float g_xh [N_MAX * H];
__device__ float g_o2 [N_MAX * H];
__device__ float g_t  [N_MAX * H];

__device__ __nv_bfloat16 g_xh_h[N_MAX * H];
__device__ __nv_bfloat16 g_xh_l[N_MAX * H];
__device__ __nv_bfloat16 g_tx_h[N_MAX * H];
__device__ __nv_bfloat16 g_tx_l[N_MAX * H];
__device__ __nv_bfloat16 g_s_h [N_MAX * H];
__device__ __nv_bfloat16 g_s_l [N_MAX * H];
__device__ __nv_bfloat16 g_t_h [N_MAX * H];
__device__ __nv_bfloat16 g_t_l [N_MAX * H];

__device__ float g_deg   [N_MAX];
__device__ float g_dis   [N_MAX];
__device__ float g_loopw [N_MAX];
__device__ float g_invcnt[N_MAX];
__device__ int   g_nloop [N_MAX];
__device__ int   g_hist  [N_MAX];
__device__ int   g_off   [N_MAX + 1];
__device__ int   g_cursor[N_MAX];
__device__ int   g_bsum  [64];
__device__ int   g_esrc  [E_MAX];
__device__ float g_enorm [E_MAX];
__device__ float g_ewe   [E_MAX];

__device__ float g_W12[H * H];
__device__ float g_b12[H];
__device__ float g_Wc [H * C_OUT];
__device__ float g_bc [C_OUT];

// prestaged weights as [n=128][K] bf16, hi plane then lo plane
__device__ __nv_bfloat16 g_Bpre1 [2 * 128 * 512];
__device__ __nv_bfloat16 g_Bcw0_1[2 * 128 * 128];
__device__ __nv_bfloat16 g_Bcw1_1[2 * 128 * 128];
__device__ __nv_bfloat16 g_Bsw1  [2 * 128 * 128];
__device__ __nv_bfloat16 g_BW12  [2 * 128 * 128];
__device__ __nv_bfloat16 g_Bcw0_2[2 * 128 * 128];
__device__ __nv_bfloat16 g_Bcw1_2[2 * 128 * 128];
__device__ __nv_bfloat16 g_Bsw2  [2 * 128 * 128];

// ---------------- helpers ----------------
__device__ __forceinline__ uint32_t smem_u32(const void* p) {
    uint32_t a;
    asm("{ .reg .u64 t; cvta.to.shared.u64 t, %1; cvt.u32.u64 %0, t; }"
        : "=r"(a) : "l"(p));
    return a;
}
__device__ __forceinline__ void split2(float a, float b, uint32_t& h, uint32_t& l) {
    asm("cvt.rn.bf16x2.f32 %0,%1,%2;" : "=r"(h) : "f"(b), "f"(a));
    float fa = __uint_as_float(h << 16);
    float fb = __uint_as_float(h & 0xFFFF0000u);
    float la = a - fa, lb = b - fb;
    asm("cvt.rn.bf16x2.f32 %0,%1,%2;" : "=r"(l) : "f"(lb), "f"(la));
}
__device__ __forceinline__ void ldm4(uint32_t* r, uint32_t addr) {
    asm volatile("ldmatrix.sync.aligned.m8n8.x4.shared.b16 {%0,%1,%2,%3},[%4];"
                 : "=r"(r[0]), "=r"(r[1]), "=r"(r[2]), "=r"(r[3]) : "r"(addr));
}
__device__ __forceinline__ void mma16816(float* d, const uint32_t* a, uint32_t b0, uint32_t b1) {
    asm volatile("mma.sync.aligned.m16n8k16.row.col.f32.bf16.bf16.f32 "
                 "{%0,%1,%2,%3},{%4,%5,%6,%7},{%8,%9},{%0,%1,%2,%3};"
                 : "+f"(d[0]), "+f"(d[1]), "+f"(d[2]), "+f"(d[3])
                 : "r"(a[0]), "r"(a[1]), "r"(a[2]), "r"(a[3]), "r"(b0), "r"(b1));
}
__device__ __forceinline__ void cp16(uint32_t dst, const void* src, int szbytes) {
    asm volatile("cp.async.cg.shared.global [%0],[%1],16,%2;"
                 :: "r"(dst), "l"(src), "r"(szbytes));
}
template<int NN> __device__ __forceinline__ void cp_wait() {
    asm volatile("cp.async.wait_group %0;" :: "n"(NN));
}

// ---------------- preprocessing kernels ----------------
__global__ void init_nodes(float* loopw, float* deg, int* nloop, int* hist, int n) {
    int i = blockIdx.x * blockDim.x + threadIdx.x;
    if (i < n) { loopw[i] = 1.0f; deg[i] = 0.0f; nloop[i] = 0; hist[i] = 0; }
}

__global__ void edge_pass1(const int* __restrict__ src, const int* __restrict__ dst,
                           const float* __restrict__ w,
                           float* __restrict__ deg, int* __restrict__ nloop,
                           float* __restrict__ loopw, int* __restrict__ hist, int E) {
    int i = blockIdx.x * blockDim.x + threadIdx.x;
    if (i >= E) return;
    int s = src[i], d = dst[i];
    float wt = w[i];
    if (s == d) {
        loopw[s] = wt;
        atomicAdd(&nloop[s], 1);
    } else {
        atomicAdd(&deg[s], wt);
    }
    atomicAdd(&hist[d], 1);
}

// scan phase 1 + node_prep fused
__global__ void scan1(const int* __restrict__ hist, int* __restrict__ bsum,
                      const float* __restrict__ deg, const int* __restrict__ nloop,
                      float* __restrict__ dis, float* __restrict__ invcnt, int n) {
    __shared__ int sh[256];
    int base = blockIdx.x * 1024;
    int s = 0;
#pragma unroll
    for (int j = 0; j < 4; j++) {
        int i = base + threadIdx.x + j * 256;
        if (i < n) {
            int h = hist[i];
            s += h;
            float dg = deg[i];
            dis[i]    = (dg > 0.0f) ? rsqrtf(dg) : 0.0f;
            invcnt[i] = 1.0f / ((float)(h - nloop[i]) + 1.0f);
        }
    }
    sh[threadIdx.x] = s;
    __syncthreads();
    for (int o = 128; o > 0; o >>= 1) {
        if (threadIdx.x < o) sh[threadIdx.x] += sh[threadIdx.x + o];
        __syncthreads();
    }
    if (threadIdx.x == 0) bsum[blockIdx.x] = sh[0];
}
__global__ void scan2(int* __restrict__ bsum, int nb, int* __restrict__ off, int n) {
    if (threadIdx.x == 0) {
        int run = 0;
        for (int i = 0; i < nb; i++) { int v = bsum[i]; bsum[i] = run; run += v; }
        off[n] = run;
    }
}
__global__ void scan3(const int* __restrict__ hist, const int* __restrict__ bsum,
                      int* __restrict__ off, int* __restrict__ cursor, int n) {
    __shared__ int sh[256];
    int base = blockIdx.x * 1024 + threadIdx.x * 4;
    int v[4]; int s = 0;
#pragma unroll
    for (int j = 0; j < 4; j++) {
        int i = base + j;
        v[j] = (i < n) ? hist[i] : 0;
        s += v[j];
    }
    sh[threadIdx.x] = s;
    __syncthreads();
    for (int o = 1; o < 256; o <<= 1) {
        int t = (threadIdx.x >= o) ? sh[threadIdx.x - o] : 0;
        __syncthreads();
        sh[threadIdx.x] += t;
        __syncthreads();
    }
    int run = bsum[blockIdx.x] + sh[threadIdx.x] - s;
#pragma unroll
    for (int j = 0; j < 4; j++) {
        int i = base + j;
        if (i < n) { off[i] = run; cursor[i] = run; }
        run += v[j];
    }
}

__global__ void edge_pass2(const int* __restrict__ src, const int* __restrict__ dst,
                           const float* __restrict__ w, const float* __restrict__ dis,
                           int* __restrict__ cursor,
                           int* __restrict__ esrc, float* __restrict__ enorm,
                           float* __restrict__ ewe, int E) {
    int i = blockIdx.x * blockDim.x + threadIdx.x;
    if (i >= E) return;
    int s = src[i], d = dst[i];
    float wt = w[i];
    float wc = (s == d) ? 0.0f : wt;
    float nm = -dis[s] * wc * dis[d];
    int pos = atomicAdd(&cursor[d], 1);
    esrc[pos]  = s;
    enorm[pos] = nm;
    ewe[pos]   = wc;
}

// warp-per-node CSR aggregation with fused sage-mean; emits bf16 hi/lo planes
__global__ void __launch_bounds__(256) aggregate(
        const float* __restrict__ xh, const int* __restrict__ off,
        const int* __restrict__ esrc, const float* __restrict__ enorm,
        const float* __restrict__ ewe,
        const float* __restrict__ loopw, const float* __restrict__ invcnt,
        __nv_bfloat16* __restrict__ txh, __nv_bfloat16* __restrict__ txl,
        __nv_bfloat16* __restrict__ sh,  __nv_bfloat16* __restrict__ sl, int N) {
    int warp = (blockIdx.x * blockDim.x + threadIdx.x) >> 5;
    int lane = threadIdx.x & 31;
    if (warp >= N) return;
    int beg = off[warp], end = off[warp + 1];
    const float4* xh4 = (const float4*)xh;
    float4 a1 = make_float4(0, 0, 0, 0);
    float4 a2 = make_float4(0, 0, 0, 0);
    int j = beg;
    for (; j + 4 <= end; j += 4) {
        int   s0 = __ldg(&esrc[j]),     s1 = __ldg(&esrc[j + 1]);
        int   s2 = __ldg(&esrc[j + 2]), s3 = __ldg(&esrc[j + 3]);
        float n0 = __ldg(&enorm[j]),     n1 = __ldg(&enorm[j + 1]);
        float n2 = __ldg(&enorm[j + 2]), n3 = __ldg(&enorm[j + 3]);
        float w0 = __ldg(&ewe[j]),       w1 = __ldg(&ewe[j + 1]);
        float w2 = __ldg(&ewe[j + 2]),   w3 = __ldg(&ewe[j + 3]);
        float4 v0 = __ldg(&xh4[(size_t)s0 * 32 + lane]);
        float4 v1 = __ldg(&xh4[(size_t)s1 * 32 + lane]);
        float4 v2 = __ldg(&xh4[(size_t)s2 * 32 + lane]);
        float4 v3 = __ldg(&xh4[(size_t)s3 * 32 + lane]);
        a1.x += n0 * v0.x + n1 * v1.x + n2 * v2.x + n3 * v3.x;
        a1.y += n0 * v0.y + n1 * v1.y + n2 * v2.y + n3 * v3.y;
        a1.z += n0 * v0.z + n1 * v1.z + n2 * v2.z + n3 * v3.z;
        a1.w += n0 * v0.w + n1 * v1.w + n2 * v2.w + n3 * v3.w;
        a2.x += w0 * v0.x + w1 * v1.x + w2 * v2.x + w3 * v3.x;
        a2.y += w0 * v0.y + w1 * v1.y + w2 * v2.y + w3 * v3.y;
        a2.z += w0 * v0.z + w1 * v1.z + w2 * v2.z + w3 * v3.z;
        a2.w += w0 * v0.w + w1 * v1.w + w2 * v2.w + w3 * v3.w;
    }
    for (; j < end; j++) {
        int sn = __ldg(&esrc[j]);
        float nm = __ldg(&enorm[j]);
        float we = __ldg(&ewe[j]);
        float4 v = __ldg(&xh4[(size_t)sn * 32 + lane]);
        a1.x += nm * v.x; a1.y += nm * v.y; a1.z += nm * v.z; a1.w += nm * v.w;
        a2.x += we * v.x; a2.y += we * v.y; a2.z += we * v.z; a2.w += we * v.w;
    }
    float lw = __ldg(&loopw[warp]);
    float ic = __ldg(&invcnt[warp]);
    float4 xv = __ldg(&xh4[(size_t)warp * 32 + lane]);
    a2.x = (a2.x + lw * xv.x) * ic;
    a2.y = (a2.y + lw * xv.y) * ic;
    a2.z = (a2.z + lw * xv.z) * ic;
    a2.w = (a2.w + lw * xv.w) * ic;
    uint32_t h0, l0, h1, l1;
    int idx = warp * 32 + lane;
    split2(a1.x, a1.y, h0, l0);
    split2(a1.z, a1.w, h1, l1);
    ((uint2*)txh)[idx] = make_uint2(h0, h1);
    ((uint2*)txl)[idx] = make_uint2(l0, l1);
    split2(a2.x, a2.y, h0, l0);
    split2(a2.z, a2.w, h1, l1);
    ((uint2*)sh)[idx] = make_uint2(h0, h1);
    ((uint2*)sl)[idx] = make_uint2(l0, l1);
}

// ---------------- setup kernels ----------------
__device__ __forceinline__ void wfuse_body(
        const float* __restrict__ A, const float* __restrict__ B,
        const float* __restrict__ bA, const float* __restrict__ bB,
        float* __restrict__ W, float* __restrict__ bOut, int K2, int blk) {
    int c = threadIdx.x;
    if (c >= K2) return;
    if (blk < H) {
        float acc = 0.0f;
        for (int j = 0; j < H; j++) acc += __ldg(&A[blk * H + j]) * __ldg(&B[j * K2 + c]);
        W[blk * K2 + c] = acc;
    } else {
        float acc = bB[c];
        for (int j = 0; j < H; j++) acc += __ldg(&bA[j]) * __ldg(&B[j * K2 + c]);
        bOut[c] = acc;
    }
}

__device__ __forceinline__ void prestage_one(const float* __restrict__ W,
                                             __nv_bfloat16* __restrict__ out,
                                             int K, int kshift, int tid, int nthreads) {
    int total = 128 * K;
    for (int i = tid; i < total; i += nthreads) {
        int n = i >> kshift, k = i & (K - 1);
        float v = __ldg(&W[(size_t)k * 128 + n]);
        __nv_bfloat16 h = __float2bfloat16(v);
        out[i] = h;
        out[total + i] = __float2bfloat16(v - __bfloat162float(h));
    }
}

// setup1: wfuse(lw1@pw2) + wfuse(lw2@cls) + prestage(pre_w1). grid = 129+129+64
__global__ void setup1(
        const float* lw1, const float* pw2, const float* lb1, const float* pb2,
        const float* lw2, const float* clsw, const float* lb2, const float* clsb,
        const float* pw1,
        float* W12, float* b12, float* Wc, float* bc, __nv_bfloat16* Bpre1) {
    int b = blockIdx.x;
    if (b < 129) {
        wfuse_body(lw1, pw2, lb1, pb2, W12, b12, H, b);
    } else if (b < 258) {
        wfuse_body(lw2, clsw, lb2, clsb, Wc, bc, C_OUT, b - 129);
    } else {
        prestage_one(pw1, Bpre1, 512, 9, (b - 258) * 256 + threadIdx.x, 64 * 256);
    }
}

// setup2: all 7 HxH weights (needs W12 from setup1)
__global__ void prestage_all(
        const float* W0, const float* W1, const float* W2, const float* W3,
        const float* W4, const float* W5, const float* W6,
        __nv_bfloat16* O0, __nv_bfloat16* O1, __nv_bfloat16* O2, __nv_bfloat16* O3,
        __nv_bfloat16* O4, __nv_bfloat16* O5, __nv_bfloat16* O6) {
    int wsel = blockIdx.x >> 4;
    int bi = blockIdx.x & 15;
    const float* W; __nv_bfloat16* O;
    switch (wsel) {
        case 0: W = W0; O = O0; break;
        case 1: W = W1; O = O1; break;
        case 2: W = W2; O = O2; break;
        case 3: W = W3; O = O3; break;
        case 4: W = W4; O = O4; break;
        case 5: W = W5; O = O5; break;
        default: W = W6; O = O6; break;
    }
    prestage_one(W, O, 128, 7, bi * 256 + threadIdx.x, 16 * 256);
}

// ---------------- HMMA GEMM (planes input), 2-stage cp.async, 1 sync/chunk ---------
#define TG_STRIDE 40
#define ARR_B 10240
#define STAGE_B 40960
#define TG_SMEM (2 * STAGE_B)

template<bool DUAL, int EPI, int EM>
__global__ void __launch_bounds__(256, 2) tgemm(
        const __nv_bfloat16* __restrict__ Ah0, const __nv_bfloat16* __restrict__ Al0,
        const __nv_bfloat16* __restrict__ Ah1, const __nv_bfloat16* __restrict__ Al1,
        const __nv_bfloat16* __restrict__ B0, const __nv_bfloat16* __restrict__ B1,
        const float* __restrict__ bias, const float* __restrict__ addsrc,
        float* __restrict__ Cf, __nv_bfloat16* __restrict__ Ch, __nv_bfloat16* __restrict__ Cl,
        int M, int K) {
    extern __shared__ __align__(16) char dsm[];
    uint32_t base = smem_u32(dsm);

    int tid = threadIdx.x, lane = tid & 31, warp = tid >> 5;
    int warp_m = warp & 3, warp_n = warp >> 2;
    int brow = blockIdx.x * 128;

    int lr = lane & 7;
    int a_off = ((warp_m * 32 + ((lane >> 3) & 1) * 8 + lr) * TG_STRIDE + (lane >> 4) * 8) * 2;
    int b_off = ((warp_n * 64 + ((lane >> 4) & 1) * 8 + lr) * TG_STRIDE + ((lane >> 3) & 1) * 8) * 2;

    float acc[2][8][4];
#pragma unroll
    for (int mi = 0; mi < 2; mi++)
#pragma unroll
        for (int ni = 0; ni < 8; ni++)
#pragma unroll
            for (int c = 0; c < 4; c++) acc[mi][ni][c] = 0.0f;

    int r = tid >> 1, half = tid & 1;
    int grow = brow + r;
    bool rowok = grow < M;
    int growc = rowok ? grow : (M - 1);
    int asz = rowok ? 16 : 0;
    uint32_t s_a = r * (TG_STRIDE * 2) + half * 32;
    int cpa = K >> 5;
    int total = DUAL ? cpa * 2 : cpa;

    auto issue = [&](int c, int stage) {
        int st = (DUAL && c >= cpa) ? 1 : 0;
        int ci = c - (st ? cpa : 0);
        const __nv_bfloat16* Ah = st ? Ah1 : Ah0;
        const __nv_bfloat16* Al = st ? Al1 : Al0;
        const __nv_bfloat16* Bp = st ? B1 : B0;
        int k0 = ci << 5;
        uint32_t sb = base + stage * STAGE_B + s_a;
        const char* gah = (const char*)(Ah + (size_t)growc * K + k0 + half * 16);
        const char* gal = (const char*)(Al + (size_t)growc * K + k0 + half * 16);
        const char* gbh = (const char*)(Bp + (size_t)r * K + k0 + half * 16);
        const char* gbl = (const char*)(Bp + (size_t)128 * K + (size_t)r * K + k0 + half * 16);
        cp16(sb,                gah,      asz);
        cp16(sb + 16,           gah + 16, asz);
        cp16(sb + ARR_B,        gal,      asz);
        cp16(sb + ARR_B + 16,   gal + 16, asz);
        cp16(sb + 2 * ARR_B,      gbh,      16);
        cp16(sb + 2 * ARR_B + 16, gbh + 16, 16);
        cp16(sb + 3 * ARR_B,      gbl,      16);
        cp16(sb + 3 * ARR_B + 16, gbl + 16, 16);
        asm volatile("cp.async.commit_group;");
    };

    issue(0, 0);
    for (int c = 0; c < total; c++) {
        int cur = c & 1;
        cp_wait<0>();
        __syncthreads();               // stage cur visible; all warps past prior compute
        if (c + 1 < total) issue(c + 1, cur ^ 1);

        uint32_t uAh = base + cur * STAGE_B;
        uint32_t uAl = uAh + ARR_B;
        uint32_t uBh = uAh + 2 * ARR_B;
        uint32_t uBl = uAh + 3 * ARR_B;
#pragma unroll
        for (int ks = 0; ks < 2; ks++) {
            int ko = ks * 32;
            uint32_t afh[2][4], afl[2][4], bfr[4][4];
#pragma unroll
            for (int nj = 0; nj < 4; nj++)
                ldm4(bfr[nj], uBh + b_off + ko + nj * 16 * TG_STRIDE * 2);
#pragma unroll
            for (int mi = 0; mi < 2; mi++) {
                ldm4(afh[mi], uAh + a_off + ko + mi * 16 * TG_STRIDE * 2);
                ldm4(afl[mi], uAl + a_off + ko + mi * 16 * TG_STRIDE * 2);
            }
#pragma unroll
            for (int mi = 0; mi < 2; mi++)
#pragma unroll
                for (int ni = 0; ni < 8; ni++)
                    mma16816(acc[mi][ni], afh[mi], bfr[ni >> 1][(ni & 1) * 2],
                             bfr[ni >> 1][(ni & 1) * 2 + 1]);
#pragma unroll
            for (int mi = 0; mi < 2; mi++)
#pragma unroll
                for (int ni = 0; ni < 8; ni++)
                    mma16816(acc[mi][ni], afl[mi], bfr[ni >> 1][(ni & 1) * 2],
                             bfr[ni >> 1][(ni & 1) * 2 + 1]);
#pragma unroll
            for (int nj = 0; nj < 4; nj++)
                ldm4(bfr[nj], uBl + b_off + ko + nj * 16 * TG_STRIDE * 2);
#pragma unroll
            for (int mi = 0; mi < 2; mi++)
#pragma unroll
                for (int ni = 0; ni < 8; ni++)
                    mma16816(acc[mi][ni], afh[mi], bfr[ni >> 1][(ni & 1) * 2],
                             bfr[ni >> 1][(ni & 1) * 2 + 1]);
        }
    }

    int g = lane >> 2, tg = lane & 3;
#pragma unroll
    for (int mi = 0; mi < 2; mi++) {
#pragma unroll
        for (int h = 0; h < 2; h++) {
            int row = brow + warp_m * 32 + mi * 16 + h * 8 + g;
            if (row >= M) continue;
#pragma unroll
            for (int ni = 0; ni < 8; ni++) {
                int col = warp_n * 64 + ni * 8 + tg * 2;
                float v0 = acc[mi][ni][h * 2 + 0] + __ldg(&bias[col]);
                float v1 = acc[mi][ni][h * 2 + 1] + __ldg(&bias[col + 1]);
                if (EPI >= 1) {
                    v0 = v0 > 0.0f ? v0 : NEG_SLOPE * v0;
                    v1 = v1 > 0.0f ? v1 : NEG_SLOPE * v1;
                }
                if (EPI == 2) {
                    float2 o = *(const float2*)(addsrc + (size_t)row * 128 + col);
                    v0 += o.x; v1 += o.y;
                }
                if (EM != 2)
                    *(float2*)(Cf + (size_t)row * 128 + col) = make_float2(v0, v1);
                if (EM >= 1) {
                    uint32_t hh, ll;
                    split2(v0, v1, hh, ll);
                    *(uint32_t*)(Ch + (size_t)row * 128 + col) = hh;
                    *(uint32_t*)(Cl + (size_t)row * 128 + col) = ll;
                }
            }
        }
    }
}

// ---------------- HMMA GEMM with in-kernel fp32->split conversion (K=512) ----------
#define CV_AF(s) ((s) * 16384)
#define CV_BH(s) (32768 + (s) * 20480)
#define CV_BL(s) (32768 + (s) * 20480 + 10240)
#define CV_AH 73728
#define CV_AL (73728 + 10240)
#define CV_SMEM 94208

__global__ void __launch_bounds__(256, 2) tgemm_conv(
        const float* __restrict__ Af, const __nv_bfloat16* __restrict__ B0,
        const float* __restrict__ bias,
        float* __restrict__ Cf, __nv_bfloat16* __restrict__ Ch, __nv_bfloat16* __restrict__ Cl,
        int M, int K) {
    extern __shared__ __align__(16) char dsm[];
    uint32_t base = smem_u32(dsm);

    int tid = threadIdx.x, lane = tid & 31, warp = tid >> 5;
    int warp_m = warp & 3, warp_n = warp >> 2;
    int brow = blockIdx.x * 128;

    int lr = lane & 7;
    int a_off = ((warp_m * 32 + ((lane >> 3) & 1) * 8 + lr) * TG_STRIDE + (lane >> 4) * 8) * 2;
    int b_off = ((warp_n * 64 + ((lane >> 4) & 1) * 8 + lr) * TG_STRIDE + ((lane >> 3) & 1) * 8) * 2;

    float acc[2][8][4];
#pragma unroll
    for (int mi = 0; mi < 2; mi++)
#pragma unroll
        for (int ni = 0; ni < 8; ni++)
#pragma unroll
            for (int c = 0; c < 4; c++) acc[mi][ni][c] = 0.0f;

    int r = tid >> 1, half = tid & 1;
    int grow = brow + r;
    bool rowok = grow < M;
    int growc = rowok ? grow : (M - 1);
    int asz = rowok ? 16 : 0;
    uint32_t s_b = r * (TG_STRIDE * 2) + half * 32;
    uint32_t s_f = r * 128 + half * 64;
    int nk = K >> 5;

    auto issue = [&](int c, int stage) {
        int k0 = c << 5;
        const char* ga  = (const char*)(Af + (size_t)growc * K + k0 + half * 16);
        const char* gbh = (const char*)(B0 + (size_t)r * K + k0 + half * 16);
        const char* gbl = (const char*)(B0 + (size_t)128 * K + (size_t)r * K + k0 + half * 16);
        uint32_t af = base + CV_AF(stage) + s_f;
        cp16(af,      ga,      asz);
        cp16(af + 16, ga + 16, asz);
        cp16(af + 32, ga + 32, asz);
        cp16(af + 48, ga + 48, asz);
        uint32_t bh = base + CV_BH(stage) + s_b;
        uint32_t bl = base + CV_BL(stage) + s_b;
        cp16(bh,      gbh,      16);
        cp16(bh + 16, gbh + 16, 16);
        cp16(bl,      gbl,      16);
        cp16(bl + 16, gbl + 16, 16);
        asm volatile("cp.async.commit_group;");
    };

    issue(0, 0);
    for (int c = 0; c < nk; c++) {
        int cur = c & 1;
        cp_wait<0>();
        __syncthreads();               // stage cur visible; prior compute done (AH/AL free)
        if (c + 1 < nk) issue(c + 1, cur ^ 1);

        {
            const float4* ap = (const float4*)(dsm + CV_AF(cur) + s_f);
            float4 f0 = ap[0], f1 = ap[1], f2 = ap[2], f3 = ap[3];
            uint32_t h[8], l[8];
            split2(f0.x, f0.y, h[0], l[0]); split2(f0.z, f0.w, h[1], l[1]);
            split2(f1.x, f1.y, h[2], l[2]); split2(f1.z, f1.w, h[3], l[3]);
            split2(f2.x, f2.y, h[4], l[4]); split2(f2.z, f2.w, h[5], l[5]);
            split2(f3.x, f3.y, h[6], l[6]); split2(f3.z, f3.w, h[7], l[7]);
            uint4* hp = (uint4*)(dsm + CV_AH + s_b);
            uint4* lp = (uint4*)(dsm + CV_AL + s_b);
            hp[0] = make_uint4(h[0], h[1], h[2], h[3]);
            hp[1] = make_uint4(h[4], h[5], h[6], h[7]);
            lp[0] = make_uint4(l[0], l[1], l[2], l[3]);
            lp[1] = make_uint4(l[4], l[5], l[6], l[7]);
        }
        __syncthreads();               // converted planes visible

        uint32_t uAh = base + CV_AH;
        uint32_t uAl = base + CV_AL;
        uint32_t uBh = base + CV_BH(cur);
        uint32_t uBl = base + CV_BL(cur);
#pragma unroll
        for (int ks = 0; ks < 2; ks++) {
            int ko = ks * 32;
            uint32_t afh[2][4], afl[2][4], bfr[4][4];
#pragma unroll
            for (int nj = 0; nj < 4; nj++)
                ldm4(bfr[nj], uBh + b_off + ko + nj * 16 * TG_STRIDE * 2);
#pragma unroll
            for (int mi = 0; mi < 2; mi++) {
                ldm4(afh[mi], uAh + a_off + ko + mi * 16 * TG_STRIDE * 2);
                ldm4(afl[mi], uAl + a_off + ko + mi * 16 * TG_STRIDE * 2);
            }
#pragma unroll
            for (int mi = 0; mi < 2; mi++)
#pragma unroll
                for (int ni = 0; ni < 8; ni++)
                    mma16816(acc[mi][ni], afh[mi], bfr[ni >> 1][(ni & 1) * 2],
                             bfr[ni >> 1][(ni & 1) * 2 + 1]);
#pragma unroll
            for (int mi = 0; mi < 2; mi++)
#pragma unroll
                for (int ni = 0; ni < 8; ni++)
                    mma16816(acc[mi][ni], afl[mi], bfr[ni >> 1][(ni & 1) * 2],
                             bfr[ni >> 1][(ni & 1) * 2 + 1]);
#pragma unroll
            for (int nj = 0; nj < 4; nj++)
                ldm4(bfr[nj], uBl + b_off + ko + nj * 16 * TG_STRIDE * 2);
#pragma unroll
            for (int mi = 0; mi < 2; mi++)
#pragma unroll
                for (int ni = 0; ni < 8; ni++)
                    mma16816(acc[mi][ni], afh[mi], bfr[ni >> 1][(ni & 1) * 2],
                             bfr[ni >> 1][(ni & 1) * 2 + 1]);
        }
    }

    int g = lane >> 2, tg = lane & 3;
#pragma unroll
    for (int mi = 0; mi < 2; mi++) {
#pragma unroll
        for (int h = 0; h < 2; h++) {
            int row = brow + warp_m * 32 + mi * 16 + h * 8 + g;
            if (row >= M) continue;
#pragma unroll
            for (int ni = 0; ni < 8; ni++) {
                int col = warp_n * 64 + ni * 8 + tg * 2;
                float v0 = acc[mi][ni][h * 2 + 0] + __ldg(&bias[col]);
                float v1 = acc[mi][ni][h * 2 + 1] + __ldg(&bias[col + 1]);
                *(float2*)(Cf + (size_t)row * 128 + col) = make_float2(v0, v1);
                uint32_t hh, ll;
                split2(v0, v1, hh, ll);
                *(uint32_t*)(Ch + (size_t)row * 128 + col) = hh;
                *(uint32_t*)(Cl + (size_t)row * 128 + col) = ll;
            }
        }
    }
}

// ---------------- classifier + log_softmax (warp per row) ----------------
__global__ void __launch_bounds__(256) cls_kernel(
        const float* __restrict__ x, const float* __restrict__ W,
        const float* __restrict__ b, float* __restrict__ out, int M) {
    __shared__ float Wt[C_OUT][128];
    __shared__ float bs[C_OUT];
    for (int i = threadIdx.x; i < 128 * C_OUT; i += 256) {
        int k = i / C_OUT, c = i % C_OUT;
        Wt[c][k] = W[i];
    }
    if (threadIdx.x < C_OUT) bs[threadIdx.x] = b[threadIdx.x];
    __syncthreads();

    int warp = threadIdx.x >> 5, lane = threadIdx.x & 31;
    int row = blockIdx.x * 8 + warp;
    if (row >= M) return;

    float xr[4];
#pragma unroll
    for (int j = 0; j < 4; j++) xr[j] = x[(size_t)row * 128 + lane + 32 * j];

    float acc[C_OUT];
#pragma unroll
    for (int c = 0; c < C_OUT; c++) {
        float a = 0.0f;
#pragma unroll
        for (int j = 0; j < 4; j++) a += xr[j] * Wt[c][lane + 32 * j];
#pragma unroll
        for (int o = 16; o > 0; o >>= 1) a += __shfl_down_sync(0xFFFFFFFFu, a, o);
        acc[c] = a;
    }
    if (lane == 0) {
        float mx = -1e30f;
#pragma unroll
        for (int c = 0; c < C_OUT; c++) { acc[c] += bs[c]; mx = fmaxf(mx, acc[c]); }
        float se = 0.0f;
#pragma unroll
        for (int c = 0; c < C_OUT; c++) se += expf(acc[c] - mx);
        float l = mx + logf(se);
#pragma unroll
        for (int c = 0; c < C_OUT; c++) out[(size_t)row * C_OUT + c] = acc[c] - l;
    }
}

// ---------------- host ----------------
static void* symaddr(const void* sym) {
    void* p = nullptr;
    cudaGetSymbolAddress(&p, sym);
    return p;
}

extern "C" void kernel_launch(void* const* d_in, const int* in_sizes, int n_in,
                              void* d_out, int out_size) {
    const float* x   = (const float*)d_in[0];
    const int*   ei  = (const int*)d_in[1];
    const float* ew  = (const float*)d_in[2];
    const float* pre_w1 = (const float*)d_in[3];  const float* pre_b1 = (const float*)d_in[4];
    const float* cw0_1  = (const float*)d_in[5];  const float* cw1_1  = (const float*)d_in[6];
    const float* cb_1   = (const float*)d_in[7];
    const float* sw_1   = (const float*)d_in[8];  const float* sb_1   = (const float*)d_in[9];
    const float* lw_1   = (const float*)d_in[10]; const float* lb_1   = (const float*)d_in[11];
    const float* pre_w2 = (const float*)d_in[12]; const float* pre_b2 = (const float*)d_in[13];
    const float* cw0_2  = (const float*)d_in[14]; const float* cw1_2  = (const float*)d_in[15];
    const float* cb_2   = (const float*)d_in[16];
    const float* sw_2   = (const float*)d_in[17]; const float* sb_2   = (const float*)d_in[18];
    const float* lw_2   = (const float*)d_in[19]; const float* lb_2   = (const float*)d_in[20];
    const float* cls_w  = (const float*)d_in[21]; const float* cls_b  = (const float*)d_in[22];
    float* out = (float*)d_out;

    int E = in_sizes[2];
    int N = in_sizes[0] / F_IN;
    const int* src = ei;
    const int* dst = ei + E;

    float* xh    = (float*)symaddr(g_xh);
    float* o2    = (float*)symaddr(g_o2);
    float* tbuf  = (float*)symaddr(g_t);
    float* deg   = (float*)symaddr(g_deg);
    float* dis   = (float*)symaddr(g_dis);
    float* loopw = (float*)symaddr(g_loopw);
    float* invc  = (float*)symaddr(g_invcnt);
    int*   nloop = (int*)symaddr(g_nloop);
    int*   hist  = (int*)symaddr(g_hist);
    int*   off   = (int*)symaddr(g_off);
    int*   cur   = (int*)symaddr(g_cursor);
    int*   bsum  = (int*)symaddr(g_bsum);
    int*   esrc  = (int*)symaddr(g_esrc);
    float* enorm = (float*)symaddr(g_enorm);
    float* ewe   = (float*)symaddr(g_ewe);
    float* W12   = (float*)symaddr(g_W12);
    float* b12   = (float*)symaddr(g_b12);
    float* Wc    = (float*)symaddr(g_Wc);
    float* bc    = (float*)symaddr(g_bc);

    __nv_bfloat16* xh_h = (__nv_bfloat16*)symaddr(g_xh_h);
    __nv_bfloat16* xh_l = (__nv_bfloat16*)symaddr(g_xh_l);
    __nv_bfloat16* tx_h = (__nv_bfloat16*)symaddr(g_tx_h);
    __nv_bfloat16* tx_l = (__nv_bfloat16*)symaddr(g_tx_l);
    __nv_bfloat16* s_h  = (__nv_bfloat16*)symaddr(g_s_h);
    __nv_bfloat16* s_l  = (__nv_bfloat16*)symaddr(g_s_l);
    __nv_bfloat16* t_h  = (__nv_bfloat16*)symaddr(g_t_h);
    __nv_bfloat16* t_l  = (__nv_bfloat16*)symaddr(g_t_l);

    __nv_bfloat16* Bpre1  = (__nv_bfloat16*)symaddr(g_Bpre1);
    __nv_bfloat16* Bcw0_1 = (__nv_bfloat16*)symaddr(g_Bcw0_1);
    __nv_bfloat16* Bcw1_1 = (__nv_bfloat16*)symaddr(g_Bcw1_1);
    __nv_bfloat16* Bsw1   = (__nv_bfloat16*)symaddr(g_Bsw1);
    __nv_bfloat16* BW12   = (__nv_bfloat16*)symaddr(g_BW12);
    __nv_bfloat16* Bcw0_2 = (__nv_bfloat16*)symaddr(g_Bcw0_2);
    __nv_bfloat16* Bcw1_2 = (__nv_bfloat16*)symaddr(g_Bcw1_2);
    __nv_bfloat16* Bsw2   = (__nv_bfloat16*)symaddr(g_Bsw2);

    cudaFuncSetAttribute(tgemm<false, 1, 0>, cudaFuncAttributeMaxDynamicSharedMemorySize, TG_SMEM);
    cudaFuncSetAttribute(tgemm<false, 0, 1>, cudaFuncAttributeMaxDynamicSharedMemorySize, TG_SMEM);
    cudaFuncSetAttribute(tgemm<true, 2, 2>,  cudaFuncAttributeMaxDynamicSharedMemorySize, TG_SMEM);
    cudaFuncSetAttribute(tgemm<true, 2, 0>,  cudaFuncAttributeMaxDynamicSharedMemorySize, TG_SMEM);
    cudaFuncSetAttribute(tgemm_conv,         cudaFuncAttributeMaxDynamicSharedMemorySize, CV_SMEM);

    int eB = (E + 255) / 256;
    int nB = (N + 255) / 256;
    int nbScan = (N + 1023) / 1024;
    int gG = (N + 127) / 128;
    int aggB = (N * 32 + 255) / 256;

    // ---- fork: preprocessing chain on side stream, GEMM prep on main ----
    cudaStream_t s2;
    cudaStreamCreateWithFlags(&s2, cudaStreamNonBlocking);
    cudaEvent_t evA, evB;
    cudaEventCreateWithFlags(&evA, cudaEventDisableTiming);
    cudaEventCreateWithFlags(&evB, cudaEventDisableTiming);
    cudaEventRecord(evA, 0);
    cudaStreamWaitEvent(s2, evA, 0);

    // main stream: setup1 (#1)
    setup1<<<322, 256>>>(lw_1, pre_w2, lb_1, pre_b2, lw_2, cls_w, lb_2, cls_b,
                         pre_w1, W12, b12, Wc, bc, Bpre1);
    // side stream: (#2, #3)
    init_nodes<<<nB, 256, 0, s2>>>(loopw, deg, nloop, hist, N);
    edge_pass1<<<eB, 256, 0, s2>>>(src, dst, ew, deg, nloop, loopw, hist, E);
    // main stream: K=512 GEMM (#4 — ncu capture slot)
    tgemm_conv<<<gG, 256, CV_SMEM>>>(x, Bpre1, pre_b1, xh, xh_h, xh_l, N, 512);
    // main stream: prestage HxH weights (needs W12)
    prestage_all<<<7 * 16, 256>>>(cw0_1, cw1_1, sw_1, W12, cw0_2, cw1_2, sw_2,
                                  Bcw0_1, Bcw1_1, Bsw1, BW12, Bcw0_2, Bcw1_2, Bsw2);
    // side stream: rest of preprocessing
    scan1<<<nbScan, 256, 0, s2>>>(hist, bsum, deg, nloop, dis, invc, N);
    scan2<<<1, 32, 0, s2>>>(bsum, nbScan, off, N);
    scan3<<<nbScan, 256, 0, s2>>>(hist, bsum, off, cur, N);
    edge_pass2<<<eB, 256, 0, s2>>>(src, dst, ew, dis, cur, esrc, enorm, ewe, E);
    cudaEventRecord(evB, s2);
    cudaStreamWaitEvent(0, evB, 0);

    // ---- cell 1 ----
    aggregate<<<aggB, 256>>>(xh, off, esrc, enorm, ewe, loopw, invc,
                             tx_h, tx_l, s_h, s_l, N);
    tgemm<false, 1, 0><<<gG, 256, TG_SMEM>>>(s_h, s_l, nullptr, nullptr, Bsw1, nullptr,
                                             sb_1, nullptr, o2, nullptr, nullptr, N, 128);
    tgemm<true, 2, 2><<<gG, 256, TG_SMEM>>>(xh_h, xh_l, tx_h, tx_l, Bcw0_1, Bcw1_1,
                                            cb_1, o2, nullptr, t_h, t_l, N, 128);

    // ---- fused lin1+pre2 ----
    tgemm<false, 0, 1><<<gG, 256, TG_SMEM>>>(t_h, t_l, nullptr, nullptr, BW12, nullptr,
                                             b12, nullptr, xh, xh_h, xh_l, N, 128);

    // ---- cell 2 ----
    aggregate<<<aggB, 256>>>(xh, off, esrc, enorm, ewe, loopw, invc,
                             tx_h, tx_l, s_h, s_l, N);
    tgemm<false, 1, 0><<<gG, 256, TG_SMEM>>>(s_h, s_l, nullptr, nullptr, Bsw2, nullptr,
                                             sb_2, nullptr, o2, nullptr, nullptr, N, 128);
    tgemm<true, 2, 0><<<gG, 256, TG_SMEM>>>(xh_h, xh_l, tx_h, tx_l, Bcw0_2, Bcw1_2,
                                            cb_2, o2, tbuf, nullptr, nullptr, N, 128);

    // ---- fused lin2 + classifier + log_softmax ----
    cls_kernel<<<(N + 7) / 8, 256>>>(tbuf, Wc, bc, out, N);
}

// round 9
// speedup vs baseline: 2.0844x; 1.0519x over previous
#include <cuda_runtime.h>
#include <cuda_bf16.h>
#include <math.h>
#include <stdint.h>

// ---------------- problem constants ----------------
#define N_MAX 40000
#define E_MAX 640000
#define F_IN  512
#define H     128
#define C_OUT 40
#define NEG_SLOPE 0.01f

// ---------------- scratch (device globals; no runtime alloc) ----------------
__device__ float g_xh [N_MAX * H];
__device__ float g_o2 [N_MAX * H];
__device__ float g_t  [N_MAX * H];

__device__ __nv_bfloat16 g_xh_h[N_MAX * H];
__device__ __nv_bfloat16 g_xh_l[N_MAX * H];
__device__ __nv_bfloat16 g_tx_h[N_MAX * H];
__device__ __nv_bfloat16 g_tx_l[N_MAX * H];
__device__ __nv_bfloat16 g_s_h [N_MAX * H];
__device__ __nv_bfloat16 g_s_l [N_MAX * H];
__device__ __nv_bfloat16 g_t_h [N_MAX * H];
__device__ __nv_bfloat16 g_t_l [N_MAX * H];

__device__ float g_deg   [N_MAX];
__device__ float g_dis   [N_MAX];
__device__ float g_loopw [N_MAX];
__device__ float g_invcnt[N_MAX];
__device__ int   g_nloop [N_MAX];
__device__ int   g_hist  [N_MAX];
__device__ int   g_off   [N_MAX + 1];
__device__ int   g_cursor[N_MAX];
__device__ int   g_bsum  [64];
__device__ int   g_esrc  [E_MAX];
__device__ float g_enorm [E_MAX];
__device__ float g_ewe   [E_MAX];

__device__ float g_W12[H * H];
__device__ float g_b12[H];
__device__ float g_Wc [H * C_OUT];
__device__ float g_bc [C_OUT];

// B in mma-fragment order: hi plane [K*64 u32] then lo plane [K*64 u32].
// u32 index = ((ks16*8 + jpair)*32 + lane)*4 + jo*2 + r
//   k = ks16*16 + (lane&3)*2 + r*8 (+1 in hi half of u32), n = (jpair*2+jo)*8 + lane/4
__device__ uint32_t g_Fpre1 [2 * 512 * 64];
__device__ uint32_t g_Fcw0_1[2 * 128 * 64];
__device__ uint32_t g_Fcw1_1[2 * 128 * 64];
__device__ uint32_t g_Fsw1  [2 * 128 * 64];
__device__ uint32_t g_FW12  [2 * 128 * 64];
__device__ uint32_t g_Fcw0_2[2 * 128 * 64];
__device__ uint32_t g_Fcw1_2[2 * 128 * 64];
__device__ uint32_t g_Fsw2  [2 * 128 * 64];

// ---------------- helpers ----------------
__device__ __forceinline__ uint32_t smem_u32(const void* p) {
    uint32_t a;
    asm("{ .reg .u64 t; cvta.to.shared.u64 t, %1; cvt.u32.u64 %0, t; }"
        : "=r"(a) : "l"(p));
    return a;
}
__device__ __forceinline__ void split2(float a, float b, uint32_t& h, uint32_t& l) {
    asm("cvt.rn.bf16x2.f32 %0,%1,%2;" : "=r"(h) : "f"(b), "f"(a));
    float fa = __uint_as_float(h << 16);
    float fb = __uint_as_float(h & 0xFFFF0000u);
    float la = a - fa, lb = b - fb;
    asm("cvt.rn.bf16x2.f32 %0,%1,%2;" : "=r"(l) : "f"(lb), "f"(la));
}
__device__ __forceinline__ void ldm4(uint32_t* r, uint32_t addr) {
    asm volatile("ldmatrix.sync.aligned.m8n8.x4.shared.b16 {%0,%1,%2,%3},[%4];"
                 : "=r"(r[0]), "=r"(r[1]), "=r"(r[2]), "=r"(r[3]) : "r"(addr));
}
__device__ __forceinline__ void mma16816(float* d, const uint32_t* a, uint32_t b0, uint32_t b1) {
    asm volatile("mma.sync.aligned.m16n8k16.row.col.f32.bf16.bf16.f32 "
                 "{%0,%1,%2,%3},{%4,%5,%6,%7},{%8,%9},{%0,%1,%2,%3};"
                 : "+f"(d[0]), "+f"(d[1]), "+f"(d[2]), "+f"(d[3])
                 : "r"(a[0]), "r"(a[1]), "r"(a[2]), "r"(a[3]), "r"(b0), "r"(b1));
}
__device__ __forceinline__ void cp16(uint32_t dst, const void* src, int szbytes) {
    asm volatile("cp.async.cg.shared.global [%0],[%1],16,%2;"
                 :: "r"(dst), "l"(src), "r"(szbytes));
}
template<int NN> __device__ __forceinline__ void cp_wait() {
    asm volatile("cp.async.wait_group %0;" :: "n"(NN));
}

// ---------------- preprocessing kernels ----------------
__global__ void init_nodes(float* loopw, float* deg, int* nloop, int* hist, int n) {
    int i = blockIdx.x * blockDim.x + threadIdx.x;
    if (i < n) { loopw[i] = 1.0f; deg[i] = 0.0f; nloop[i] = 0; hist[i] = 0; }
}

__global__ void edge_pass1(const int* __restrict__ src, const int* __restrict__ dst,
                           const float* __restrict__ w,
                           float* __restrict__ deg, int* __restrict__ nloop,
                           float* __restrict__ loopw, int* __restrict__ hist, int E) {
    int i = blockIdx.x * blockDim.x + threadIdx.x;
    if (i >= E) return;
    int s = src[i], d = dst[i];
    float wt = w[i];
    if (s == d) {
        loopw[s] = wt;
        atomicAdd(&nloop[s], 1);
    } else {
        atomicAdd(&deg[s], wt);
    }
    atomicAdd(&hist[d], 1);
}

__global__ void scan1(const int* __restrict__ hist, int* __restrict__ bsum,
                      const float* __restrict__ deg, const int* __restrict__ nloop,
                      float* __restrict__ dis, float* __restrict__ invcnt, int n) {
    __shared__ int sh[256];
    int base = blockIdx.x * 1024;
    int s = 0;
#pragma unroll
    for (int j = 0; j < 4; j++) {
        int i = base + threadIdx.x + j * 256;
        if (i < n) {
            int h = hist[i];
            s += h;
            float dg = deg[i];
            dis[i]    = (dg > 0.0f) ? rsqrtf(dg) : 0.0f;
            invcnt[i] = 1.0f / ((float)(h - nloop[i]) + 1.0f);
        }
    }
    sh[threadIdx.x] = s;
    __syncthreads();
    for (int o = 128; o > 0; o >>= 1) {
        if (threadIdx.x < o) sh[threadIdx.x] += sh[threadIdx.x + o];
        __syncthreads();
    }
    if (threadIdx.x == 0) bsum[blockIdx.x] = sh[0];
}
__global__ void scan2(int* __restrict__ bsum, int nb, int* __restrict__ off, int n) {
    if (threadIdx.x == 0) {
        int run = 0;
        for (int i = 0; i < nb; i++) { int v = bsum[i]; bsum[i] = run; run += v; }
        off[n] = run;
    }
}
__global__ void scan3(const int* __restrict__ hist, const int* __restrict__ bsum,
                      int* __restrict__ off, int* __restrict__ cursor, int n) {
    __shared__ int sh[256];
    int base = blockIdx.x * 1024 + threadIdx.x * 4;
    int v[4]; int s = 0;
#pragma unroll
    for (int j = 0; j < 4; j++) {
        int i = base + j;
        v[j] = (i < n) ? hist[i] : 0;
        s += v[j];
    }
    sh[threadIdx.x] = s;
    __syncthreads();
    for (int o = 1; o < 256; o <<= 1) {
        int t = (threadIdx.x >= o) ? sh[threadIdx.x - o] : 0;
        __syncthreads();
        sh[threadIdx.x] += t;
        __syncthreads();
    }
    int run = bsum[blockIdx.x] + sh[threadIdx.x] - s;
#pragma unroll
    for (int j = 0; j < 4; j++) {
        int i = base + j;
        if (i < n) { off[i] = run; cursor[i] = run; }
        run += v[j];
    }
}

__global__ void edge_pass2(const int* __restrict__ src, const int* __restrict__ dst,
                           const float* __restrict__ w, const float* __restrict__ dis,
                           int* __restrict__ cursor,
                           int* __restrict__ esrc, float* __restrict__ enorm,
                           float* __restrict__ ewe, int E) {
    int i = blockIdx.x * blockDim.x + threadIdx.x;
    if (i >= E) return;
    int s = src[i], d = dst[i];
    float wt = w[i];
    float wc = (s == d) ? 0.0f : wt;
    float nm = -dis[s] * wc * dis[d];
    int pos = atomicAdd(&cursor[d], 1);
    esrc[pos]  = s;
    enorm[pos] = nm;
    ewe[pos]   = wc;
}

// warp-per-node CSR aggregation with fused sage-mean; emits bf16 hi/lo planes
__global__ void __launch_bounds__(256) aggregate(
        const float* __restrict__ xh, const int* __restrict__ off,
        const int* __restrict__ esrc, const float* __restrict__ enorm,
        const float* __restrict__ ewe,
        const float* __restrict__ loopw, const float* __restrict__ invcnt,
        __nv_bfloat16* __restrict__ txh, __nv_bfloat16* __restrict__ txl,
        __nv_bfloat16* __restrict__ sh,  __nv_bfloat16* __restrict__ sl, int N) {
    int warp = (blockIdx.x * blockDim.x + threadIdx.x) >> 5;
    int lane = threadIdx.x & 31;
    if (warp >= N) return;
    int beg = off[warp], end = off[warp + 1];
    const float4* xh4 = (const float4*)xh;
    float4 a1 = make_float4(0, 0, 0, 0);
    float4 a2 = make_float4(0, 0, 0, 0);
    int j = beg;
    for (; j + 4 <= end; j += 4) {
        int   s0 = __ldg(&esrc[j]),     s1 = __ldg(&esrc[j + 1]);
        int   s2 = __ldg(&esrc[j + 2]), s3 = __ldg(&esrc[j + 3]);
        float n0 = __ldg(&enorm[j]),     n1 = __ldg(&enorm[j + 1]);
        float n2 = __ldg(&enorm[j + 2]), n3 = __ldg(&enorm[j + 3]);
        float w0 = __ldg(&ewe[j]),       w1 = __ldg(&ewe[j + 1]);
        float w2 = __ldg(&ewe[j + 2]),   w3 = __ldg(&ewe[j + 3]);
        float4 v0 = __ldg(&xh4[(size_t)s0 * 32 + lane]);
        float4 v1 = __ldg(&xh4[(size_t)s1 * 32 + lane]);
        float4 v2 = __ldg(&xh4[(size_t)s2 * 32 + lane]);
        float4 v3 = __ldg(&xh4[(size_t)s3 * 32 + lane]);
        a1.x += n0 * v0.x + n1 * v1.x + n2 * v2.x + n3 * v3.x;
        a1.y += n0 * v0.y + n1 * v1.y + n2 * v2.y + n3 * v3.y;
        a1.z += n0 * v0.z + n1 * v1.z + n2 * v2.z + n3 * v3.z;
        a1.w += n0 * v0.w + n1 * v1.w + n2 * v2.w + n3 * v3.w;
        a2.x += w0 * v0.x + w1 * v1.x + w2 * v2.x + w3 * v3.x;
        a2.y += w0 * v0.y + w1 * v1.y + w2 * v2.y + w3 * v3.y;
        a2.z += w0 * v0.z + w1 * v1.z + w2 * v2.z + w3 * v3.z;
        a2.w += w0 * v0.w + w1 * v1.w + w2 * v2.w + w3 * v3.w;
    }
    for (; j < end; j++) {
        int sn = __ldg(&esrc[j]);
        float nm = __ldg(&enorm[j]);
        float we = __ldg(&ewe[j]);
        float4 v = __ldg(&xh4[(size_t)sn * 32 + lane]);
        a1.x += nm * v.x; a1.y += nm * v.y; a1.z += nm * v.z; a1.w += nm * v.w;
        a2.x += we * v.x; a2.y += we * v.y; a2.z += we * v.z; a2.w += we * v.w;
    }
    float lw = __ldg(&loopw[warp]);
    float ic = __ldg(&invcnt[warp]);
    float4 xv = __ldg(&xh4[(size_t)warp * 32 + lane]);
    a2.x = (a2.x + lw * xv.x) * ic;
    a2.y = (a2.y + lw * xv.y) * ic;
    a2.z = (a2.z + lw * xv.z) * ic;
    a2.w = (a2.w + lw * xv.w) * ic;
    uint32_t h0, l0, h1, l1;
    int idx = warp * 32 + lane;
    split2(a1.x, a1.y, h0, l0);
    split2(a1.z, a1.w, h1, l1);
    ((uint2*)txh)[idx] = make_uint2(h0, h1);
    ((uint2*)txl)[idx] = make_uint2(l0, l1);
    split2(a2.x, a2.y, h0, l0);
    split2(a2.z, a2.w, h1, l1);
    ((uint2*)sh)[idx] = make_uint2(h0, h1);
    ((uint2*)sl)[idx] = make_uint2(l0, l1);
}

// ---------------- setup kernels ----------------
__device__ __forceinline__ void wfuse_body(
        const float* __restrict__ A, const float* __restrict__ B,
        const float* __restrict__ bA, const float* __restrict__ bB,
        float* __restrict__ W, float* __restrict__ bOut, int K2, int blk) {
    int c = threadIdx.x;
    if (c >= K2) return;
    if (blk < H) {
        float acc = 0.0f;
        for (int j = 0; j < H; j++) acc += __ldg(&A[blk * H + j]) * __ldg(&B[j * K2 + c]);
        W[blk * K2 + c] = acc;
    } else {
        float acc = bB[c];
        for (int j = 0; j < H; j++) acc += __ldg(&bA[j]) * __ldg(&B[j * K2 + c]);
        bOut[c] = acc;
    }
}

// prestage W[K][128] -> fragment-order hi/lo u32 planes
__device__ __forceinline__ void prestage_frag(const float* __restrict__ W,
                                              uint32_t* __restrict__ out,
                                              int K, int tid, int nthreads) {
    int total = K * 64;   // u32 per plane
    for (int i = tid; i < total; i += nthreads) {
        int sub = i & 3, jo = sub >> 1, r = sub & 1;
        int q = i >> 2;
        int lane = q & 31;
        int t = q >> 5;
        int jp = t & 7, ks = t >> 3;
        int k = ks * 16 + (lane & 3) * 2 + r * 8;
        int n = (jp * 2 + jo) * 8 + (lane >> 2);
        float v0 = __ldg(&W[(size_t)k * 128 + n]);
        float v1 = __ldg(&W[(size_t)(k + 1) * 128 + n]);
        uint32_t h, l;
        split2(v0, v1, h, l);
        out[i] = h;
        out[total + i] = l;
    }
}

// setup1: wfuse x2 + prestage(pre_w1). grid = 129+129+64
__global__ void setup1(
        const float* lw1, const float* pw2, const float* lb1, const float* pb2,
        const float* lw2, const float* clsw, const float* lb2, const float* clsb,
        const float* pw1,
        float* W12, float* b12, float* Wc, float* bc, uint32_t* Fpre1) {
    int b = blockIdx.x;
    if (b < 129) {
        wfuse_body(lw1, pw2, lb1, pb2, W12, b12, H, b);
    } else if (b < 258) {
        wfuse_body(lw2, clsw, lb2, clsb, Wc, bc, C_OUT, b - 129);
    } else {
        prestage_frag(pw1, Fpre1, 512, (b - 258) * 256 + threadIdx.x, 64 * 256);
    }
}

__global__ void prestage_all(
        const float* W0, const float* W1, const float* W2, const float* W3,
        const float* W4, const float* W5, const float* W6,
        uint32_t* O0, uint32_t* O1, uint32_t* O2, uint32_t* O3,
        uint32_t* O4, uint32_t* O5, uint32_t* O6) {
    int wsel = blockIdx.x >> 4;
    int bi = blockIdx.x & 15;
    const float* W; uint32_t* O;
    switch (wsel) {
        case 0: W = W0; O = O0; break;
        case 1: W = W1; O = O1; break;
        case 2: W = W2; O = O2; break;
        case 3: W = W3; O = O3; break;
        case 4: W = W4; O = O4; break;
        case 5: W = W5; O = O5; break;
        default: W = W6; O = O6; break;
    }
    prestage_frag(W, O, 128, bi * 256 + threadIdx.x, 16 * 256);
}

// ---------------- HMMA GEMM: A via smem planes, B via fragment LDG -------------
#define TG_STRIDE 40
#define ARR_B 10240
#define STAGE_B 20480
#define TG_SMEM (2 * STAGE_B)   // 40960

template<bool DUAL, int EPI, int EM>
__global__ void __launch_bounds__(256, 2) tgemm(
        const __nv_bfloat16* __restrict__ Ah0, const __nv_bfloat16* __restrict__ Al0,
        const __nv_bfloat16* __restrict__ Ah1, const __nv_bfloat16* __restrict__ Al1,
        const uint32_t* __restrict__ F0, const uint32_t* __restrict__ F1,
        const float* __restrict__ bias, const float* __restrict__ addsrc,
        float* __restrict__ Cf, __nv_bfloat16* __restrict__ Ch, __nv_bfloat16* __restrict__ Cl,
        int M, int K) {
    extern __shared__ __align__(16) char dsm[];
    uint32_t base = smem_u32(dsm);

    int tid = threadIdx.x, lane = tid & 31, warp = tid >> 5;
    int warp_m = warp & 3, warp_n = warp >> 2;
    int brow = blockIdx.x * 128;
    int K64 = K * 64;

    int lr = lane & 7;
    int a_off = ((warp_m * 32 + ((lane >> 3) & 1) * 8 + lr) * TG_STRIDE + (lane >> 4) * 8) * 2;

    float acc[2][8][4];
#pragma unroll
    for (int mi = 0; mi < 2; mi++)
#pragma unroll
        for (int ni = 0; ni < 8; ni++)
#pragma unroll
            for (int c = 0; c < 4; c++) acc[mi][ni][c] = 0.0f;

    int r = tid >> 1, half = tid & 1;
    int grow = brow + r;
    bool rowok = grow < M;
    int growc = rowok ? grow : (M - 1);
    int asz = rowok ? 16 : 0;
    uint32_t s_a = r * (TG_STRIDE * 2) + half * 32;
    int cpa = K >> 5;
    int total = DUAL ? cpa * 2 : cpa;

    auto issue = [&](int c, int stage) {
        int st = (DUAL && c >= cpa) ? 1 : 0;
        int ci = c - (st ? cpa : 0);
        const __nv_bfloat16* Ah = st ? Ah1 : Ah0;
        const __nv_bfloat16* Al = st ? Al1 : Al0;
        int k0 = ci << 5;
        uint32_t sb = base + stage * STAGE_B + s_a;
        const char* gah = (const char*)(Ah + (size_t)growc * K + k0 + half * 16);
        const char* gal = (const char*)(Al + (size_t)growc * K + k0 + half * 16);
        cp16(sb,              gah,      asz);
        cp16(sb + 16,         gah + 16, asz);
        cp16(sb + ARR_B,      gal,      asz);
        cp16(sb + ARR_B + 16, gal + 16, asz);
        asm volatile("cp.async.commit_group;");
    };

    issue(0, 0);
    for (int c = 0; c < total; c++) {
        int cur = c & 1;
        int st = (DUAL && c >= cpa) ? 1 : 0;
        int ci = c - (st ? cpa : 0);
        const uint32_t* Fb = st ? F1 : F0;
        const uint4* F4h = (const uint4*)Fb;
        const uint4* F4l = (const uint4*)(Fb + K64);
        cp_wait<0>();
        __syncthreads();
        if (c + 1 < total) issue(c + 1, cur ^ 1);

        uint32_t uAh = base + cur * STAGE_B;
        uint32_t uAl = uAh + ARR_B;
#pragma unroll
        for (int ks = 0; ks < 2; ks++) {
            int ko = ks * 32;
            int kidx = ci * 2 + ks;
            int qb = (kidx * 8 + warp_n * 4) * 32 + lane;
            uint4 fh[4], fl[4];
#pragma unroll
            for (int nj = 0; nj < 4; nj++) fh[nj] = __ldg(&F4h[qb + nj * 32]);
            uint32_t afh[2][4], afl[2][4];
#pragma unroll
            for (int mi = 0; mi < 2; mi++) {
                ldm4(afh[mi], uAh + a_off + ko + mi * 16 * TG_STRIDE * 2);
                ldm4(afl[mi], uAl + a_off + ko + mi * 16 * TG_STRIDE * 2);
            }
#pragma unroll
            for (int mi = 0; mi < 2; mi++)
#pragma unroll
                for (int ni = 0; ni < 8; ni++) {
                    uint32_t b0 = (ni & 1) ? fh[ni >> 1].z : fh[ni >> 1].x;
                    uint32_t b1 = (ni & 1) ? fh[ni >> 1].w : fh[ni >> 1].y;
                    mma16816(acc[mi][ni], afh[mi], b0, b1);
                }
#pragma unroll
            for (int nj = 0; nj < 4; nj++) fl[nj] = __ldg(&F4l[qb + nj * 32]);
#pragma unroll
            for (int mi = 0; mi < 2; mi++)
#pragma unroll
                for (int ni = 0; ni < 8; ni++) {
                    uint32_t b0 = (ni & 1) ? fh[ni >> 1].z : fh[ni >> 1].x;
                    uint32_t b1 = (ni & 1) ? fh[ni >> 1].w : fh[ni >> 1].y;
                    mma16816(acc[mi][ni], afl[mi], b0, b1);
                }
#pragma unroll
            for (int mi = 0; mi < 2; mi++)
#pragma unroll
                for (int ni = 0; ni < 8; ni++) {
                    uint32_t b0 = (ni & 1) ? fl[ni >> 1].z : fl[ni >> 1].x;
                    uint32_t b1 = (ni & 1) ? fl[ni >> 1].w : fl[ni >> 1].y;
                    mma16816(acc[mi][ni], afh[mi], b0, b1);
                }
        }
    }

    int g = lane >> 2, tg = lane & 3;
#pragma unroll
    for (int mi = 0; mi < 2; mi++) {
#pragma unroll
        for (int h = 0; h < 2; h++) {
            int row = brow + warp_m * 32 + mi * 16 + h * 8 + g;
            if (row >= M) continue;
#pragma unroll
            for (int ni = 0; ni < 8; ni++) {
                int col = warp_n * 64 + ni * 8 + tg * 2;
                float v0 = acc[mi][ni][h * 2 + 0] + __ldg(&bias[col]);
                float v1 = acc[mi][ni][h * 2 + 1] + __ldg(&bias[col + 1]);
                if (EPI >= 1) {
                    v0 = v0 > 0.0f ? v0 : NEG_SLOPE * v0;
                    v1 = v1 > 0.0f ? v1 : NEG_SLOPE * v1;
                }
                if (EPI == 2) {
                    float2 o = *(const float2*)(addsrc + (size_t)row * 128 + col);
                    v0 += o.x; v1 += o.y;
                }
                if (EM != 2)
                    *(float2*)(Cf + (size_t)row * 128 + col) = make_float2(v0, v1);
                if (EM >= 1) {
                    uint32_t hh, ll;
                    split2(v0, v1, hh, ll);
                    *(uint32_t*)(Ch + (size_t)row * 128 + col) = hh;
                    *(uint32_t*)(Cl + (size_t)row * 128 + col) = ll;
                }
            }
        }
    }
}

// ---------------- conv GEMM (fp32 A -> split in-kernel), B via fragment LDG --------
#define CV_AF(s) ((s) * 16384)
#define CV_AH 32768
#define CV_AL (32768 + 10240)
#define CV_SMEM 53248

__global__ void __launch_bounds__(256, 2) tgemm_conv(
        const float* __restrict__ Af, const uint32_t* __restrict__ F0,
        const float* __restrict__ bias,
        float* __restrict__ Cf, __nv_bfloat16* __restrict__ Ch, __nv_bfloat16* __restrict__ Cl,
        int M, int K) {
    extern __shared__ __align__(16) char dsm[];
    uint32_t base = smem_u32(dsm);

    int tid = threadIdx.x, lane = tid & 31, warp = tid >> 5;
    int warp_m = warp & 3, warp_n = warp >> 2;
    int brow = blockIdx.x * 128;
    int K64 = K * 64;
    const uint4* F4h = (const uint4*)F0;
    const uint4* F4l = (const uint4*)(F0 + K64);

    int lr = lane & 7;
    int a_off = ((warp_m * 32 + ((lane >> 3) & 1) * 8 + lr) * TG_STRIDE + (lane >> 4) * 8) * 2;

    float acc[2][8][4];
#pragma unroll
    for (int mi = 0; mi < 2; mi++)
#pragma unroll
        for (int ni = 0; ni < 8; ni++)
#pragma unroll
            for (int c = 0; c < 4; c++) acc[mi][ni][c] = 0.0f;

    int r = tid >> 1, half = tid & 1;
    int grow = brow + r;
    bool rowok = grow < M;
    int growc = rowok ? grow : (M - 1);
    int asz = rowok ? 16 : 0;
    uint32_t s_b = r * (TG_STRIDE * 2) + half * 32;
    uint32_t s_f = r * 128 + half * 64;
    int nk = K >> 5;

    auto issue = [&](int c, int stage) {
        int k0 = c << 5;
        const char* ga = (const char*)(Af + (size_t)growc * K + k0 + half * 16);
        uint32_t af = base + CV_AF(stage) + s_f;
        cp16(af,      ga,      asz);
        cp16(af + 16, ga + 16, asz);
        cp16(af + 32, ga + 32, asz);
        cp16(af + 48, ga + 48, asz);
        asm volatile("cp.async.commit_group;");
    };

    issue(0, 0);
    for (int c = 0; c < nk; c++) {
        int cur = c & 1;
        cp_wait<0>();
        __syncthreads();               // stage cur visible; prior MMAs done (AH/AL free)
        if (c + 1 < nk) issue(c + 1, cur ^ 1);

        {
            const float4* ap = (const float4*)(dsm + CV_AF(cur) + s_f);
            float4 f0 = ap[0], f1 = ap[1], f2 = ap[2], f3 = ap[3];
            uint32_t h[8], l[8];
            split2(f0.x, f0.y, h[0], l[0]); split2(f0.z, f0.w, h[1], l[1]);
            split2(f1.x, f1.y, h[2], l[2]); split2(f1.z, f1.w, h[3], l[3]);
            split2(f2.x, f2.y, h[4], l[4]); split2(f2.z, f2.w, h[5], l[5]);
            split2(f3.x, f3.y, h[6], l[6]); split2(f3.z, f3.w, h[7], l[7]);
            uint4* hp = (uint4*)(dsm + CV_AH + s_b);
            uint4* lp = (uint4*)(dsm + CV_AL + s_b);
            hp[0] = make_uint4(h[0], h[1], h[2], h[3]);
            hp[1] = make_uint4(h[4], h[5], h[6], h[7]);
            lp[0] = make_uint4(l[0], l[1], l[2], l[3]);
            lp[1] = make_uint4(l[4], l[5], l[6], l[7]);
        }
        __syncthreads();

        uint32_t uAh = base + CV_AH;
        uint32_t uAl = base + CV_AL;
#pragma unroll
        for (int ks = 0; ks < 2; ks++) {
            int ko = ks * 32;
            int kidx = c * 2 + ks;
            int qb = (kidx * 8 + warp_n * 4) * 32 + lane;
            uint4 fh[4], fl[4];
#pragma unroll
            for (int nj = 0; nj < 4; nj++) fh[nj] = __ldg(&F4h[qb + nj * 32]);
            uint32_t afh[2][4], afl[2][4];
#pragma unroll
            for (int mi = 0; mi < 2; mi++) {
                ldm4(afh[mi], uAh + a_off + ko + mi * 16 * TG_STRIDE * 2);
                ldm4(afl[mi], uAl + a_off + ko + mi * 16 * TG_STRIDE * 2);
            }
#pragma unroll
            for (int mi = 0; mi < 2; mi++)
#pragma unroll
                for (int ni = 0; ni < 8; ni++) {
                    uint32_t b0 = (ni & 1) ? fh[ni >> 1].z : fh[ni >> 1].x;
                    uint32_t b1 = (ni & 1) ? fh[ni >> 1].w : fh[ni >> 1].y;
                    mma16816(acc[mi][ni], afh[mi], b0, b1);
                }
#pragma unroll
            for (int nj = 0; nj < 4; nj++) fl[nj] = __ldg(&F4l[qb + nj * 32]);
#pragma unroll
            for (int mi = 0; mi < 2; mi++)
#pragma unroll
                for (int ni = 0; ni < 8; ni++) {
                    uint32_t b0 = (ni & 1) ? fh[ni >> 1].z : fh[ni >> 1].x;
                    uint32_t b1 = (ni & 1) ? fh[ni >> 1].w : fh[ni >> 1].y;
                    mma16816(acc[mi][ni], afl[mi], b0, b1);
                }
#pragma unroll
            for (int mi = 0; mi < 2; mi++)
#pragma unroll
                for (int ni = 0; ni < 8; ni++) {
                    uint32_t b0 = (ni & 1) ? fl[ni >> 1].z : fl[ni >> 1].x;
                    uint32_t b1 = (ni & 1) ? fl[ni >> 1].w : fl[ni >> 1].y;
                    mma16816(acc[mi][ni], afh[mi], b0, b1);
                }
        }
        __syncthreads();               // MMAs done before next convert overwrites AH/AL
    }

    int g = lane >> 2, tg = lane & 3;
#pragma unroll
    for (int mi = 0; mi < 2; mi++) {
#pragma unroll
        for (int h = 0; h < 2; h++) {
            int row = brow + warp_m * 32 + mi * 16 + h * 8 + g;
            if (row >= M) continue;
#pragma unroll
            for (int ni = 0; ni < 8; ni++) {
                int col = warp_n * 64 + ni * 8 + tg * 2;
                float v0 = acc[mi][ni][h * 2 + 0] + __ldg(&bias[col]);
                float v1 = acc[mi][ni][h * 2 + 1] + __ldg(&bias[col + 1]);
                *(float2*)(Cf + (size_t)row * 128 + col) = make_float2(v0, v1);
                uint32_t hh, ll;
                split2(v0, v1, hh, ll);
                *(uint32_t*)(Ch + (size_t)row * 128 + col) = hh;
                *(uint32_t*)(Cl + (size_t)row * 128 + col) = ll;
            }
        }
    }
}

// ---------------- classifier + log_softmax (warp per row) ----------------
__global__ void __launch_bounds__(256) cls_kernel(
        const float* __restrict__ x, const float* __restrict__ W,
        const float* __restrict__ b, float* __restrict__ out, int M) {
    __shared__ float Wt[C_OUT][128];
    __shared__ float bs[C_OUT];
    for (int i = threadIdx.x; i < 128 * C_OUT; i += 256) {
        int k = i / C_OUT, c = i % C_OUT;
        Wt[c][k] = W[i];
    }
    if (threadIdx.x < C_OUT) bs[threadIdx.x] = b[threadIdx.x];
    __syncthreads();

    int warp = threadIdx.x >> 5, lane = threadIdx.x & 31;
    int row = blockIdx.x * 8 + warp;
    if (row >= M) return;

    float xr[4];
#pragma unroll
    for (int j = 0; j < 4; j++) xr[j] = x[(size_t)row * 128 + lane + 32 * j];

    float acc[C_OUT];
#pragma unroll
    for (int c = 0; c < C_OUT; c++) {
        float a = 0.0f;
#pragma unroll
        for (int j = 0; j < 4; j++) a += xr[j] * Wt[c][lane + 32 * j];
#pragma unroll
        for (int o = 16; o > 0; o >>= 1) a += __shfl_down_sync(0xFFFFFFFFu, a, o);
        acc[c] = a;
    }
    if (lane == 0) {
        float mx = -1e30f;
#pragma unroll
        for (int c = 0; c < C_OUT; c++) { acc[c] += bs[c]; mx = fmaxf(mx, acc[c]); }
        float se = 0.0f;
#pragma unroll
        for (int c = 0; c < C_OUT; c++) se += expf(acc[c] - mx);
        float l = mx + logf(se);
#pragma unroll
        for (int c = 0; c < C_OUT; c++) out[(size_t)row * C_OUT + c] = acc[c] - l;
    }
}

// ---------------- host ----------------
static void* symaddr(const void* sym) {
    void* p = nullptr;
    cudaGetSymbolAddress(&p, sym);
    return p;
}

extern "C" void kernel_launch(void* const* d_in, const int* in_sizes, int n_in,
                              void* d_out, int out_size) {
    const float* x   = (const float*)d_in[0];
    const int*   ei  = (const int*)d_in[1];
    const float* ew  = (const float*)d_in[2];
    const float* pre_w1 = (const float*)d_in[3];  const float* pre_b1 = (const float*)d_in[4];
    const float* cw0_1  = (const float*)d_in[5];  const float* cw1_1  = (const float*)d_in[6];
    const float* cb_1   = (const float*)d_in[7];
    const float* sw_1   = (const float*)d_in[8];  const float* sb_1   = (const float*)d_in[9];
    const float* lw_1   = (const float*)d_in[10]; const float* lb_1   = (const float*)d_in[11];
    const float* pre_w2 = (const float*)d_in[12]; const float* pre_b2 = (const float*)d_in[13];
    const float* cw0_2  = (const float*)d_in[14]; const float* cw1_2  = (const float*)d_in[15];
    const float* cb_2   = (const float*)d_in[16];
    const float* sw_2   = (const float*)d_in[17]; const float* sb_2   = (const float*)d_in[18];
    const float* lw_2   = (const float*)d_in[19]; const float* lb_2   = (const float*)d_in[20];
    const float* cls_w  = (const float*)d_in[21]; const float* cls_b  = (const float*)d_in[22];
    float* out = (float*)d_out;

    int E = in_sizes[2];
    int N = in_sizes[0] / F_IN;
    const int* src = ei;
    const int* dst = ei + E;

    float* xh    = (float*)symaddr(g_xh);
    float* o2    = (float*)symaddr(g_o2);
    float* tbuf  = (float*)symaddr(g_t);
    float* deg   = (float*)symaddr(g_deg);
    float* dis   = (float*)symaddr(g_dis);
    float* loopw = (float*)symaddr(g_loopw);
    float* invc  = (float*)symaddr(g_invcnt);
    int*   nloop = (int*)symaddr(g_nloop);
    int*   hist  = (int*)symaddr(g_hist);
    int*   off   = (int*)symaddr(g_off);
    int*   cur   = (int*)symaddr(g_cursor);
    int*   bsum  = (int*)symaddr(g_bsum);
    int*   esrc  = (int*)symaddr(g_esrc);
    float* enorm = (float*)symaddr(g_enorm);
    float* ewe   = (float*)symaddr(g_ewe);
    float* W12   = (float*)symaddr(g_W12);
    float* b12   = (float*)symaddr(g_b12);
    float* Wc    = (float*)symaddr(g_Wc);
    float* bc    = (float*)symaddr(g_bc);

    __nv_bfloat16* xh_h = (__nv_bfloat16*)symaddr(g_xh_h);
    __nv_bfloat16* xh_l = (__nv_bfloat16*)symaddr(g_xh_l);
    __nv_bfloat16* tx_h = (__nv_bfloat16*)symaddr(g_tx_h);
    __nv_bfloat16* tx_l = (__nv_bfloat16*)symaddr(g_tx_l);
    __nv_bfloat16* s_h  = (__nv_bfloat16*)symaddr(g_s_h);
    __nv_bfloat16* s_l  = (__nv_bfloat16*)symaddr(g_s_l);
    __nv_bfloat16* t_h  = (__nv_bfloat16*)symaddr(g_t_h);
    __nv_bfloat16* t_l  = (__nv_bfloat16*)symaddr(g_t_l);

    uint32_t* Fpre1  = (uint32_t*)symaddr(g_Fpre1);
    uint32_t* Fcw0_1 = (uint32_t*)symaddr(g_Fcw0_1);
    uint32_t* Fcw1_1 = (uint32_t*)symaddr(g_Fcw1_1);
    uint32_t* Fsw1   = (uint32_t*)symaddr(g_Fsw1);
    uint32_t* FW12   = (uint32_t*)symaddr(g_FW12);
    uint32_t* Fcw0_2 = (uint32_t*)symaddr(g_Fcw0_2);
    uint32_t* Fcw1_2 = (uint32_t*)symaddr(g_Fcw1_2);
    uint32_t* Fsw2   = (uint32_t*)symaddr(g_Fsw2);

    cudaFuncSetAttribute(tgemm<false, 1, 0>, cudaFuncAttributeMaxDynamicSharedMemorySize, TG_SMEM);
    cudaFuncSetAttribute(tgemm<false, 0, 1>, cudaFuncAttributeMaxDynamicSharedMemorySize, TG_SMEM);
    cudaFuncSetAttribute(tgemm<true, 2, 2>,  cudaFuncAttributeMaxDynamicSharedMemorySize, TG_SMEM);
    cudaFuncSetAttribute(tgemm<true, 2, 0>,  cudaFuncAttributeMaxDynamicSharedMemorySize, TG_SMEM);
    cudaFuncSetAttribute(tgemm_conv,         cudaFuncAttributeMaxDynamicSharedMemorySize, CV_SMEM);

    int eB = (E + 255) / 256;
    int nB = (N + 255) / 256;
    int nbScan = (N + 1023) / 1024;
    int gG = (N + 127) / 128;
    int aggB = (N * 32 + 255) / 256;

    // ---- fork: preprocessing chain on side stream ----
    cudaStream_t s2;
    cudaStreamCreateWithFlags(&s2, cudaStreamNonBlocking);
    cudaEvent_t evA, evB;
    cudaEventCreateWithFlags(&evA, cudaEventDisableTiming);
    cudaEventCreateWithFlags(&evB, cudaEventDisableTiming);
    cudaEventRecord(evA, 0);
    cudaStreamWaitEvent(s2, evA, 0);

    setup1<<<322, 256>>>(lw_1, pre_w2, lb_1, pre_b2, lw_2, cls_w, lb_2, cls_b,
                         pre_w1, W12, b12, Wc, bc, Fpre1);
    init_nodes<<<nB, 256, 0, s2>>>(loopw, deg, nloop, hist, N);
    edge_pass1<<<eB, 256, 0, s2>>>(src, dst, ew, deg, nloop, loopw, hist, E);
    // launch #4 (ncu capture slot): K=512 GEMM
    tgemm_conv<<<gG, 256, CV_SMEM>>>(x, Fpre1, pre_b1, xh, xh_h, xh_l, N, 512);
    prestage_all<<<7 * 16, 256>>>(cw0_1, cw1_1, sw_1, W12, cw0_2, cw1_2, sw_2,
                                  Fcw0_1, Fcw1_1, Fsw1, FW12, Fcw0_2, Fcw1_2, Fsw2);
    scan1<<<nbScan, 256, 0, s2>>>(hist, bsum, deg, nloop, dis, invc, N);
    scan2<<<1, 32, 0, s2>>>(bsum, nbScan, off, N);
    scan3<<<nbScan, 256, 0, s2>>>(hist, bsum, off, cur, N);
    edge_pass2<<<eB, 256, 0, s2>>>(src, dst, ew, dis, cur, esrc, enorm, ewe, E);
    cudaEventRecord(evB, s2);
    cudaStreamWaitEvent(0, evB, 0);

    // ---- cell 1 ----
    aggregate<<<aggB, 256>>>(xh, off, esrc, enorm, ewe, loopw, invc,
                             tx_h, tx_l, s_h, s_l, N);
    tgemm<false, 1, 0><<<gG, 256, TG_SMEM>>>(s_h, s_l, nullptr, nullptr, Fsw1, nullptr,
                                             sb_1, nullptr, o2, nullptr, nullptr, N, 128);
    tgemm<true, 2, 2><<<gG, 256, TG_SMEM>>>(xh_h, xh_l, tx_h, tx_l, Fcw0_1, Fcw1_1,
                                            cb_1, o2, nullptr, t_h, t_l, N, 128);

    // ---- fused lin1+pre2 ----
    tgemm<false, 0, 1><<<gG, 256, TG_SMEM>>>(t_h, t_l, nullptr, nullptr, FW12, nullptr,
                                             b12, nullptr, xh, xh_h, xh_l, N, 128);

    // ---- cell 2 ----
    aggregate<<<aggB, 256>>>(xh, off, esrc, enorm, ewe, loopw, invc,
                             tx_h, tx_l, s_h, s_l, N);
    tgemm<false, 1, 0><<<gG, 256, TG_SMEM>>>(s_h, s_l, nullptr, nullptr, Fsw2, nullptr,
                                             sb_2, nullptr, o2, nullptr, nullptr, N, 128);
    tgemm<true, 2, 0><<<gG, 256, TG_SMEM>>>(xh_h, xh_l, tx_h, tx_l, Fcw0_2, Fcw1_2,
                                            cb_2, o2, tbuf, nullptr, nullptr, N, 128);

    // ---- fused lin2 + classifier + log_softmax ----
    cls_kernel<<<(N + 7) / 8, 256>>>(tbuf, Wc, bc, out, N);
}

// round 10
// speedup vs baseline: 2.1039x; 1.0093x over previous
#include <cuda_runtime.h>
#include <cuda_bf16.h>
#include <math.h>
#include <stdint.h>

// ---------------- problem constants ----------------
#define N_MAX 40000
#define E_MAX 640000
#define F_IN  512
#define H     128
#define C_OUT 40
#define NEG_SLOPE 0.01f

// ---------------- scratch (device globals; no runtime alloc) ----------------
__device__ float g_xh [N_MAX * H];
__device__ float g_o2 [N_MAX * H];
__device__ float g_t  [N_MAX * H];

__device__ __nv_bfloat16 g_xh_h[N_MAX * H];
__device__ __nv_bfloat16 g_xh_l[N_MAX * H];
__device__ __nv_bfloat16 g_tx_h[N_MAX * H];
__device__ __nv_bfloat16 g_tx_l[N_MAX * H];
__device__ __nv_bfloat16 g_s_h [N_MAX * H];
__device__ __nv_bfloat16 g_s_l [N_MAX * H];
__device__ __nv_bfloat16 g_t_h [N_MAX * H];
__device__ __nv_bfloat16 g_t_l [N_MAX * H];

__device__ float g_deg   [N_MAX];
__device__ float g_dis   [N_MAX];
__device__ float g_loopw [N_MAX];
__device__ float g_invcnt[N_MAX];
__device__ int   g_nloop [N_MAX];
__device__ int   g_hist  [N_MAX];
__device__ int   g_off   [N_MAX + 1];
__device__ int   g_cursor[N_MAX];
__device__ int   g_bsum  [64];
__device__ int   g_esrc  [E_MAX];
__device__ float g_enorm [E_MAX];
__device__ float g_ewe   [E_MAX];

__device__ float g_W12[H * H];
__device__ float g_b12[H];
__device__ float g_Wc [H * C_OUT];
__device__ float g_bc [C_OUT];

// B in mma-fragment order: hi plane [K*64 u32] then lo plane [K*64 u32].
__device__ uint32_t g_Fpre1 [2 * 512 * 64];
__device__ uint32_t g_Fcw0_1[2 * 128 * 64];
__device__ uint32_t g_Fcw1_1[2 * 128 * 64];
__device__ uint32_t g_Fsw1  [2 * 128 * 64];
__device__ uint32_t g_FW12  [2 * 128 * 64];
__device__ uint32_t g_Fcw0_2[2 * 128 * 64];
__device__ uint32_t g_Fcw1_2[2 * 128 * 64];
__device__ uint32_t g_Fsw2  [2 * 128 * 64];

// ---------------- helpers ----------------
__device__ __forceinline__ uint32_t smem_u32(const void* p) {
    uint32_t a;
    asm("{ .reg .u64 t; cvta.to.shared.u64 t, %1; cvt.u32.u64 %0, t; }"
        : "=r"(a) : "l"(p));
    return a;
}
__device__ __forceinline__ void split2(float a, float b, uint32_t& h, uint32_t& l) {
    asm("cvt.rn.bf16x2.f32 %0,%1,%2;" : "=r"(h) : "f"(b), "f"(a));
    float fa = __uint_as_float(h << 16);
    float fb = __uint_as_float(h & 0xFFFF0000u);
    float la = a - fa, lb = b - fb;
    asm("cvt.rn.bf16x2.f32 %0,%1,%2;" : "=r"(l) : "f"(lb), "f"(la));
}
__device__ __forceinline__ void ldm4(uint32_t* r, uint32_t addr) {
    asm volatile("ldmatrix.sync.aligned.m8n8.x4.shared.b16 {%0,%1,%2,%3},[%4];"
                 : "=r"(r[0]), "=r"(r[1]), "=r"(r[2]), "=r"(r[3]) : "r"(addr));
}
__device__ __forceinline__ void mma16816(float* d, const uint32_t* a, uint32_t b0, uint32_t b1) {
    asm volatile("mma.sync.aligned.m16n8k16.row.col.f32.bf16.bf16.f32 "
                 "{%0,%1,%2,%3},{%4,%5,%6,%7},{%8,%9},{%0,%1,%2,%3};"
                 : "+f"(d[0]), "+f"(d[1]), "+f"(d[2]), "+f"(d[3])
                 : "r"(a[0]), "r"(a[1]), "r"(a[2]), "r"(a[3]), "r"(b0), "r"(b1));
}
__device__ __forceinline__ void cp16(uint32_t dst, const void* src, int szbytes) {
    asm volatile("cp.async.cg.shared.global [%0],[%1],16,%2;"
                 :: "r"(dst), "l"(src), "r"(szbytes));
}
template<int NN> __device__ __forceinline__ void cp_wait() {
    asm volatile("cp.async.wait_group %0;" :: "n"(NN));
}

// ---------------- preprocessing kernels ----------------
__global__ void init_nodes(float* loopw, float* deg, int* nloop, int* hist, int n) {
    int i = blockIdx.x * blockDim.x + threadIdx.x;
    if (i < n) { loopw[i] = 1.0f; deg[i] = 0.0f; nloop[i] = 0; hist[i] = 0; }
}

__global__ void edge_pass1(const int* __restrict__ src, const int* __restrict__ dst,
                           const float* __restrict__ w,
                           float* __restrict__ deg, int* __restrict__ nloop,
                           float* __restrict__ loopw, int* __restrict__ hist, int E) {
    int i = blockIdx.x * blockDim.x + threadIdx.x;
    if (i >= E) return;
    int s = src[i], d = dst[i];
    float wt = w[i];
    if (s == d) {
        loopw[s] = wt;
        atomicAdd(&nloop[s], 1);
    } else {
        atomicAdd(&deg[s], wt);
    }
    atomicAdd(&hist[d], 1);
}

__global__ void scan1(const int* __restrict__ hist, int* __restrict__ bsum,
                      const float* __restrict__ deg, const int* __restrict__ nloop,
                      float* __restrict__ dis, float* __restrict__ invcnt, int n) {
    __shared__ int sh[256];
    int base = blockIdx.x * 1024;
    int s = 0;
#pragma unroll
    for (int j = 0; j < 4; j++) {
        int i = base + threadIdx.x + j * 256;
        if (i < n) {
            int h = hist[i];
            s += h;
            float dg = deg[i];
            dis[i]    = (dg > 0.0f) ? rsqrtf(dg) : 0.0f;
            invcnt[i] = 1.0f / ((float)(h - nloop[i]) + 1.0f);
        }
    }
    sh[threadIdx.x] = s;
    __syncthreads();
    for (int o = 128; o > 0; o >>= 1) {
        if (threadIdx.x < o) sh[threadIdx.x] += sh[threadIdx.x + o];
        __syncthreads();
    }
    if (threadIdx.x == 0) bsum[blockIdx.x] = sh[0];
}
__global__ void scan2(int* __restrict__ bsum, int nb, int* __restrict__ off, int n) {
    if (threadIdx.x == 0) {
        int run = 0;
        for (int i = 0; i < nb; i++) { int v = bsum[i]; bsum[i] = run; run += v; }
        off[n] = run;
    }
}
__global__ void scan3(const int* __restrict__ hist, const int* __restrict__ bsum,
                      int* __restrict__ off, int* __restrict__ cursor, int n) {
    __shared__ int sh[256];
    int base = blockIdx.x * 1024 + threadIdx.x * 4;
    int v[4]; int s = 0;
#pragma unroll
    for (int j = 0; j < 4; j++) {
        int i = base + j;
        v[j] = (i < n) ? hist[i] : 0;
        s += v[j];
    }
    sh[threadIdx.x] = s;
    __syncthreads();
    for (int o = 1; o < 256; o <<= 1) {
        int t = (threadIdx.x >= o) ? sh[threadIdx.x - o] : 0;
        __syncthreads();
        sh[threadIdx.x] += t;
        __syncthreads();
    }
    int run = bsum[blockIdx.x] + sh[threadIdx.x] - s;
#pragma unroll
    for (int j = 0; j < 4; j++) {
        int i = base + j;
        if (i < n) { off[i] = run; cursor[i] = run; }
        run += v[j];
    }
}

__global__ void edge_pass2(const int* __restrict__ src, const int* __restrict__ dst,
                           const float* __restrict__ w, const float* __restrict__ dis,
                           int* __restrict__ cursor,
                           int* __restrict__ esrc, float* __restrict__ enorm,
                           float* __restrict__ ewe, int E) {
    int i = blockIdx.x * blockDim.x + threadIdx.x;
    if (i >= E) return;
    int s = src[i], d = dst[i];
    float wt = w[i];
    float wc = (s == d) ? 0.0f : wt;
    float nm = -dis[s] * wc * dis[d];
    int pos = atomicAdd(&cursor[d], 1);
    esrc[pos]  = s;
    enorm[pos] = nm;
    ewe[pos]   = wc;
}

// warp-per-node CSR aggregation with fused sage-mean; emits bf16 hi/lo planes
__global__ void __launch_bounds__(256) aggregate(
        const float* __restrict__ xh, const int* __restrict__ off,
        const int* __restrict__ esrc, const float* __restrict__ enorm,
        const float* __restrict__ ewe,
        const float* __restrict__ loopw, const float* __restrict__ invcnt,
        __nv_bfloat16* __restrict__ txh, __nv_bfloat16* __restrict__ txl,
        __nv_bfloat16* __restrict__ sh,  __nv_bfloat16* __restrict__ sl, int N) {
    int warp = (blockIdx.x * blockDim.x + threadIdx.x) >> 5;
    int lane = threadIdx.x & 31;
    if (warp >= N) return;
    int beg = off[warp], end = off[warp + 1];
    const float4* xh4 = (const float4*)xh;
    float4 a1 = make_float4(0, 0, 0, 0);
    float4 a2 = make_float4(0, 0, 0, 0);
    int j = beg;
    for (; j + 4 <= end; j += 4) {
        int   s0 = __ldg(&esrc[j]),     s1 = __ldg(&esrc[j + 1]);
        int   s2 = __ldg(&esrc[j + 2]), s3 = __ldg(&esrc[j + 3]);
        float n0 = __ldg(&enorm[j]),     n1 = __ldg(&enorm[j + 1]);
        float n2 = __ldg(&enorm[j + 2]), n3 = __ldg(&enorm[j + 3]);
        float w0 = __ldg(&ewe[j]),       w1 = __ldg(&ewe[j + 1]);
        float w2 = __ldg(&ewe[j + 2]),   w3 = __ldg(&ewe[j + 3]);
        float4 v0 = __ldg(&xh4[(size_t)s0 * 32 + lane]);
        float4 v1 = __ldg(&xh4[(size_t)s1 * 32 + lane]);
        float4 v2 = __ldg(&xh4[(size_t)s2 * 32 + lane]);
        float4 v3 = __ldg(&xh4[(size_t)s3 * 32 + lane]);
        a1.x += n0 * v0.x + n1 * v1.x + n2 * v2.x + n3 * v3.x;
        a1.y += n0 * v0.y + n1 * v1.y + n2 * v2.y + n3 * v3.y;
        a1.z += n0 * v0.z + n1 * v1.z + n2 * v2.z + n3 * v3.z;
        a1.w += n0 * v0.w + n1 * v1.w + n2 * v2.w + n3 * v3.w;
        a2.x += w0 * v0.x + w1 * v1.x + w2 * v2.x + w3 * v3.x;
        a2.y += w0 * v0.y + w1 * v1.y + w2 * v2.y + w3 * v3.y;
        a2.z += w0 * v0.z + w1 * v1.z + w2 * v2.z + w3 * v3.z;
        a2.w += w0 * v0.w + w1 * v1.w + w2 * v2.w + w3 * v3.w;
    }
    for (; j < end; j++) {
        int sn = __ldg(&esrc[j]);
        float nm = __ldg(&enorm[j]);
        float we = __ldg(&ewe[j]);
        float4 v = __ldg(&xh4[(size_t)sn * 32 + lane]);
        a1.x += nm * v.x; a1.y += nm * v.y; a1.z += nm * v.z; a1.w += nm * v.w;
        a2.x += we * v.x; a2.y += we * v.y; a2.z += we * v.z; a2.w += we * v.w;
    }
    float lw = __ldg(&loopw[warp]);
    float ic = __ldg(&invcnt[warp]);
    float4 xv = __ldg(&xh4[(size_t)warp * 32 + lane]);
    a2.x = (a2.x + lw * xv.x) * ic;
    a2.y = (a2.y + lw * xv.y) * ic;
    a2.z = (a2.z + lw * xv.z) * ic;
    a2.w = (a2.w + lw * xv.w) * ic;
    uint32_t h0, l0, h1, l1;
    int idx = warp * 32 + lane;
    split2(a1.x, a1.y, h0, l0);
    split2(a1.z, a1.w, h1, l1);
    ((uint2*)txh)[idx] = make_uint2(h0, h1);
    ((uint2*)txl)[idx] = make_uint2(l0, l1);
    split2(a2.x, a2.y, h0, l0);
    split2(a2.z, a2.w, h1, l1);
    ((uint2*)sh)[idx] = make_uint2(h0, h1);
    ((uint2*)sl)[idx] = make_uint2(l0, l1);
}

// ---------------- setup kernels ----------------
__device__ __forceinline__ void wfuse_body(
        const float* __restrict__ A, const float* __restrict__ B,
        const float* __restrict__ bA, const float* __restrict__ bB,
        float* __restrict__ W, float* __restrict__ bOut, int K2, int blk) {
    int c = threadIdx.x;
    if (c >= K2) return;
    if (blk < H) {
        float acc = 0.0f;
        for (int j = 0; j < H; j++) acc += __ldg(&A[blk * H + j]) * __ldg(&B[j * K2 + c]);
        W[blk * K2 + c] = acc;
    } else {
        float acc = bB[c];
        for (int j = 0; j < H; j++) acc += __ldg(&bA[j]) * __ldg(&B[j * K2 + c]);
        bOut[c] = acc;
    }
}

// prestage W[K][128] -> fragment-order hi/lo u32 planes
__device__ __forceinline__ void prestage_frag(const float* __restrict__ W,
                                              uint32_t* __restrict__ out,
                                              int K, int tid, int nthreads) {
    int total = K * 64;
    for (int i = tid; i < total; i += nthreads) {
        int sub = i & 3, jo = sub >> 1, r = sub & 1;
        int q = i >> 2;
        int lane = q & 31;
        int t = q >> 5;
        int jp = t & 7, ks = t >> 3;
        int k = ks * 16 + (lane & 3) * 2 + r * 8;
        int n = (jp * 2 + jo) * 8 + (lane >> 2);
        float v0 = __ldg(&W[(size_t)k * 128 + n]);
        float v1 = __ldg(&W[(size_t)(k + 1) * 128 + n]);
        uint32_t h, l;
        split2(v0, v1, h, l);
        out[i] = h;
        out[total + i] = l;
    }
}

__global__ void setup1(
        const float* lw1, const float* pw2, const float* lb1, const float* pb2,
        const float* lw2, const float* clsw, const float* lb2, const float* clsb,
        const float* pw1,
        float* W12, float* b12, float* Wc, float* bc, uint32_t* Fpre1) {
    int b = blockIdx.x;
    if (b < 129) {
        wfuse_body(lw1, pw2, lb1, pb2, W12, b12, H, b);
    } else if (b < 258) {
        wfuse_body(lw2, clsw, lb2, clsb, Wc, bc, C_OUT, b - 129);
    } else {
        prestage_frag(pw1, Fpre1, 512, (b - 258) * 256 + threadIdx.x, 64 * 256);
    }
}

__global__ void prestage_all(
        const float* W0, const float* W1, const float* W2, const float* W3,
        const float* W4, const float* W5, const float* W6,
        uint32_t* O0, uint32_t* O1, uint32_t* O2, uint32_t* O3,
        uint32_t* O4, uint32_t* O5, uint32_t* O6) {
    int wsel = blockIdx.x >> 4;
    int bi = blockIdx.x & 15;
    const float* W; uint32_t* O;
    switch (wsel) {
        case 0: W = W0; O = O0; break;
        case 1: W = W1; O = O1; break;
        case 2: W = W2; O = O2; break;
        case 3: W = W3; O = O3; break;
        case 4: W = W4; O = O4; break;
        case 5: W = W5; O = O5; break;
        default: W = W6; O = O6; break;
    }
    prestage_frag(W, O, 128, bi * 256 + threadIdx.x, 16 * 256);
}

// ---------------- HMMA GEMM: A via smem planes, B via fragment LDG -------------
#define TG_STRIDE 40
#define ARR_B 10240
#define STAGE_B 20480
#define TG_SMEM (2 * STAGE_B)   // 40960

template<bool DUAL, int EPI, int EM>
__global__ void __launch_bounds__(256, 2) tgemm(
        const __nv_bfloat16* __restrict__ Ah0, const __nv_bfloat16* __restrict__ Al0,
        const __nv_bfloat16* __restrict__ Ah1, const __nv_bfloat16* __restrict__ Al1,
        const uint32_t* __restrict__ F0, const uint32_t* __restrict__ F1,
        const float* __restrict__ bias, const float* __restrict__ addsrc,
        float* __restrict__ Cf, __nv_bfloat16* __restrict__ Ch, __nv_bfloat16* __restrict__ Cl,
        int M, int K) {
    extern __shared__ __align__(16) char dsm[];
    uint32_t base = smem_u32(dsm);

    int tid = threadIdx.x, lane = tid & 31, warp = tid >> 5;
    int warp_m = warp & 3, warp_n = warp >> 2;
    int brow = blockIdx.x * 128;
    int K64 = K * 64;

    int lr = lane & 7;
    int a_off = ((warp_m * 32 + ((lane >> 3) & 1) * 8 + lr) * TG_STRIDE + (lane >> 4) * 8) * 2;

    float acc[2][8][4];
#pragma unroll
    for (int mi = 0; mi < 2; mi++)
#pragma unroll
        for (int ni = 0; ni < 8; ni++)
#pragma unroll
            for (int c = 0; c < 4; c++) acc[mi][ni][c] = 0.0f;

    int r = tid >> 1, half = tid & 1;
    int grow = brow + r;
    bool rowok = grow < M;
    int growc = rowok ? grow : (M - 1);
    int asz = rowok ? 16 : 0;
    uint32_t s_a = r * (TG_STRIDE * 2) + half * 32;
    int cpa = K >> 5;
    int total = DUAL ? cpa * 2 : cpa;

    auto issue = [&](int c, int stage) {
        int st = (DUAL && c >= cpa) ? 1 : 0;
        int ci = c - (st ? cpa : 0);
        const __nv_bfloat16* Ah = st ? Ah1 : Ah0;
        const __nv_bfloat16* Al = st ? Al1 : Al0;
        int k0 = ci << 5;
        uint32_t sb = base + stage * STAGE_B + s_a;
        const char* gah = (const char*)(Ah + (size_t)growc * K + k0 + half * 16);
        const char* gal = (const char*)(Al + (size_t)growc * K + k0 + half * 16);
        cp16(sb,              gah,      asz);
        cp16(sb + 16,         gah + 16, asz);
        cp16(sb + ARR_B,      gal,      asz);
        cp16(sb + ARR_B + 16, gal + 16, asz);
        asm volatile("cp.async.commit_group;");
    };

    issue(0, 0);
    for (int c = 0; c < total; c++) {
        int cur = c & 1;
        int st = (DUAL && c >= cpa) ? 1 : 0;
        int ci = c - (st ? cpa : 0);
        const uint32_t* Fb = st ? F1 : F0;
        const uint4* F4h = (const uint4*)Fb;
        const uint4* F4l = (const uint4*)(Fb + K64);
        cp_wait<0>();
        __syncthreads();
        if (c + 1 < total) issue(c + 1, cur ^ 1);

        uint32_t uAh = base + cur * STAGE_B;
        uint32_t uAl = uAh + ARR_B;
#pragma unroll
        for (int ks = 0; ks < 2; ks++) {
            int ko = ks * 32;
            int kidx = ci * 2 + ks;
            int qb = (kidx * 8 + warp_n * 4) * 32 + lane;
            // prefetch ALL B fragments first (LDG latency overlaps LDSM + MMA)
            uint4 fh[4], fl[4];
#pragma unroll
            for (int nj = 0; nj < 4; nj++) fh[nj] = __ldg(&F4h[qb + nj * 32]);
#pragma unroll
            for (int nj = 0; nj < 4; nj++) fl[nj] = __ldg(&F4l[qb + nj * 32]);
            uint32_t afh[2][4], afl[2][4];
#pragma unroll
            for (int mi = 0; mi < 2; mi++) {
                ldm4(afh[mi], uAh + a_off + ko + mi * 16 * TG_STRIDE * 2);
                ldm4(afl[mi], uAl + a_off + ko + mi * 16 * TG_STRIDE * 2);
            }
#pragma unroll
            for (int mi = 0; mi < 2; mi++)
#pragma unroll
                for (int ni = 0; ni < 8; ni++) {
                    uint32_t b0 = (ni & 1) ? fh[ni >> 1].z : fh[ni >> 1].x;
                    uint32_t b1 = (ni & 1) ? fh[ni >> 1].w : fh[ni >> 1].y;
                    mma16816(acc[mi][ni], afh[mi], b0, b1);
                }
#pragma unroll
            for (int mi = 0; mi < 2; mi++)
#pragma unroll
                for (int ni = 0; ni < 8; ni++) {
                    uint32_t b0 = (ni & 1) ? fh[ni >> 1].z : fh[ni >> 1].x;
                    uint32_t b1 = (ni & 1) ? fh[ni >> 1].w : fh[ni >> 1].y;
                    mma16816(acc[mi][ni], afl[mi], b0, b1);
                }
#pragma unroll
            for (int mi = 0; mi < 2; mi++)
#pragma unroll
                for (int ni = 0; ni < 8; ni++) {
                    uint32_t b0 = (ni & 1) ? fl[ni >> 1].z : fl[ni >> 1].x;
                    uint32_t b1 = (ni & 1) ? fl[ni >> 1].w : fl[ni >> 1].y;
                    mma16816(acc[mi][ni], afh[mi], b0, b1);
                }
        }
    }

    int g = lane >> 2, tg = lane & 3;
#pragma unroll
    for (int mi = 0; mi < 2; mi++) {
#pragma unroll
        for (int h = 0; h < 2; h++) {
            int row = brow + warp_m * 32 + mi * 16 + h * 8 + g;
            if (row >= M) continue;
#pragma unroll
            for (int ni = 0; ni < 8; ni++) {
                int col = warp_n * 64 + ni * 8 + tg * 2;
                float v0 = acc[mi][ni][h * 2 + 0] + __ldg(&bias[col]);
                float v1 = acc[mi][ni][h * 2 + 1] + __ldg(&bias[col + 1]);
                if (EPI >= 1) {
                    v0 = v0 > 0.0f ? v0 : NEG_SLOPE * v0;
                    v1 = v1 > 0.0f ? v1 : NEG_SLOPE * v1;
                }
                if (EPI == 2) {
                    float2 o = *(const float2*)(addsrc + (size_t)row * 128 + col);
                    v0 += o.x; v1 += o.y;
                }
                if (EM != 2)
                    *(float2*)(Cf + (size_t)row * 128 + col) = make_float2(v0, v1);
                if (EM >= 1) {
                    uint32_t hh, ll;
                    split2(v0, v1, hh, ll);
                    *(uint32_t*)(Ch + (size_t)row * 128 + col) = hh;
                    *(uint32_t*)(Cl + (size_t)row * 128 + col) = ll;
                }
            }
        }
    }
}

// ---------------- conv GEMM: fp32 A -> split in-kernel, double-buffered planes ----
#define CV_AF(s) ((s) * 16384)                   // fp32 A stages: 0, 16384
#define CV_AH(s) (32768 + (s) * 10240)           // hi planes: 32768, 43008
#define CV_AL(s) (53248 + (s) * 10240)           // lo planes: 53248, 63488
#define CV_SMEM 73728

__global__ void __launch_bounds__(256, 2) tgemm_conv(
        const float* __restrict__ Af, const uint32_t* __restrict__ F0,
        const float* __restrict__ bias,
        float* __restrict__ Cf, __nv_bfloat16* __restrict__ Ch, __nv_bfloat16* __restrict__ Cl,
        int M, int K) {
    extern __shared__ __align__(16) char dsm[];
    uint32_t base = smem_u32(dsm);

    int tid = threadIdx.x, lane = tid & 31, warp = tid >> 5;
    int warp_m = warp & 3, warp_n = warp >> 2;
    int brow = blockIdx.x * 128;
    int K64 = K * 64;
    const uint4* F4h = (const uint4*)F0;
    const uint4* F4l = (const uint4*)(F0 + K64);

    int lr = lane & 7;
    int a_off = ((warp_m * 32 + ((lane >> 3) & 1) * 8 + lr) * TG_STRIDE + (lane >> 4) * 8) * 2;

    float acc[2][8][4];
#pragma unroll
    for (int mi = 0; mi < 2; mi++)
#pragma unroll
        for (int ni = 0; ni < 8; ni++)
#pragma unroll
            for (int c = 0; c < 4; c++) acc[mi][ni][c] = 0.0f;

    int r = tid >> 1, half = tid & 1;
    int grow = brow + r;
    bool rowok = grow < M;
    int growc = rowok ? grow : (M - 1);
    int asz = rowok ? 16 : 0;
    uint32_t s_b = r * (TG_STRIDE * 2) + half * 32;
    uint32_t s_f = r * 128 + half * 64;
    int nk = K >> 5;

    auto issue = [&](int c, int stage) {
        int k0 = c << 5;
        const char* ga = (const char*)(Af + (size_t)growc * K + k0 + half * 16);
        uint32_t af = base + CV_AF(stage) + s_f;
        cp16(af,      ga,      asz);
        cp16(af + 16, ga + 16, asz);
        cp16(af + 32, ga + 32, asz);
        cp16(af + 48, ga + 48, asz);
        asm volatile("cp.async.commit_group;");
    };

    issue(0, 0);
    for (int c = 0; c < nk; c++) {
        int cur = c & 1;
        cp_wait<0>();      // own A data in Af[cur] (thread-local: we convert what we copied)
        // convert own 16 fp32 -> planes[cur]. WAR vs MMA(c-2) on planes[cur] is ordered
        // by the barrier in iteration c-1 (every thread passed it only after MMA(c-2)).
        {
            const float4* ap = (const float4*)(dsm + CV_AF(cur) + s_f);
            float4 f0 = ap[0], f1 = ap[1], f2 = ap[2], f3 = ap[3];
            uint32_t h[8], l[8];
            split2(f0.x, f0.y, h[0], l[0]); split2(f0.z, f0.w, h[1], l[1]);
            split2(f1.x, f1.y, h[2], l[2]); split2(f1.z, f1.w, h[3], l[3]);
            split2(f2.x, f2.y, h[4], l[4]); split2(f2.z, f2.w, h[5], l[5]);
            split2(f3.x, f3.y, h[6], l[6]); split2(f3.z, f3.w, h[7], l[7]);
            uint4* hp = (uint4*)(dsm + CV_AH(cur) + s_b);
            uint4* lp = (uint4*)(dsm + CV_AL(cur) + s_b);
            hp[0] = make_uint4(h[0], h[1], h[2], h[3]);
            hp[1] = make_uint4(h[4], h[5], h[6], h[7]);
            lp[0] = make_uint4(l[0], l[1], l[2], l[3]);
            lp[1] = make_uint4(l[4], l[5], l[6], l[7]);
        }
        if (c + 1 < nk) issue(c + 1, cur ^ 1);
        __syncthreads();   // converted planes[cur] visible to all warps

        uint32_t uAh = base + CV_AH(cur);
        uint32_t uAl = base + CV_AL(cur);
#pragma unroll
        for (int ks = 0; ks < 2; ks++) {
            int ko = ks * 32;
            int kidx = c * 2 + ks;
            int qb = (kidx * 8 + warp_n * 4) * 32 + lane;
            uint4 fh[4], fl[4];
#pragma unroll
            for (int nj = 0; nj < 4; nj++) fh[nj] = __ldg(&F4h[qb + nj * 32]);
#pragma unroll
            for (int nj = 0; nj < 4; nj++) fl[nj] = __ldg(&F4l[qb + nj * 32]);
            uint32_t afh[2][4], afl[2][4];
#pragma unroll
            for (int mi = 0; mi < 2; mi++) {
                ldm4(afh[mi], uAh + a_off + ko + mi * 16 * TG_STRIDE * 2);
                ldm4(afl[mi], uAl + a_off + ko + mi * 16 * TG_STRIDE * 2);
            }
#pragma unroll
            for (int mi = 0; mi < 2; mi++)
#pragma unroll
                for (int ni = 0; ni < 8; ni++) {
                    uint32_t b0 = (ni & 1) ? fh[ni >> 1].z : fh[ni >> 1].x;
                    uint32_t b1 = (ni & 1) ? fh[ni >> 1].w : fh[ni >> 1].y;
                    mma16816(acc[mi][ni], afh[mi], b0, b1);
                }
#pragma unroll
            for (int mi = 0; mi < 2; mi++)
#pragma unroll
                for (int ni = 0; ni < 8; ni++) {
                    uint32_t b0 = (ni & 1) ? fh[ni >> 1].z : fh[ni >> 1].x;
                    uint32_t b1 = (ni & 1) ? fh[ni >> 1].w : fh[ni >> 1].y;
                    mma16816(acc[mi][ni], afl[mi], b0, b1);
                }
#pragma unroll
            for (int mi = 0; mi < 2; mi++)
#pragma unroll
                for (int ni = 0; ni < 8; ni++) {
                    uint32_t b0 = (ni & 1) ? fl[ni >> 1].z : fl[ni >> 1].x;
                    uint32_t b1 = (ni & 1) ? fl[ni >> 1].w : fl[ni >> 1].y;
                    mma16816(acc[mi][ni], afh[mi], b0, b1);
                }
        }
    }

    int g = lane >> 2, tg = lane & 3;
#pragma unroll
    for (int mi = 0; mi < 2; mi++) {
#pragma unroll
        for (int h = 0; h < 2; h++) {
            int row = brow + warp_m * 32 + mi * 16 + h * 8 + g;
            if (row >= M) continue;
#pragma unroll
            for (int ni = 0; ni < 8; ni++) {
                int col = warp_n * 64 + ni * 8 + tg * 2;
                float v0 = acc[mi][ni][h * 2 + 0] + __ldg(&bias[col]);
                float v1 = acc[mi][ni][h * 2 + 1] + __ldg(&bias[col + 1]);
                *(float2*)(Cf + (size_t)row * 128 + col) = make_float2(v0, v1);
                uint32_t hh, ll;
                split2(v0, v1, hh, ll);
                *(uint32_t*)(Ch + (size_t)row * 128 + col) = hh;
                *(uint32_t*)(Cl + (size_t)row * 128 + col) = ll;
            }
        }
    }
}

// ---------------- classifier + log_softmax (warp per row) ----------------
__global__ void __launch_bounds__(256) cls_kernel(
        const float* __restrict__ x, const float* __restrict__ W,
        const float* __restrict__ b, float* __restrict__ out, int M) {
    __shared__ float Wt[C_OUT][128];
    __shared__ float bs[C_OUT];
    for (int i = threadIdx.x; i < 128 * C_OUT; i += 256) {
        int k = i / C_OUT, c = i % C_OUT;
        Wt[c][k] = W[i];
    }
    if (threadIdx.x < C_OUT) bs[threadIdx.x] = b[threadIdx.x];
    __syncthreads();

    int warp = threadIdx.x >> 5, lane = threadIdx.x & 31;
    int row = blockIdx.x * 8 + warp;
    if (row >= M) return;

    float xr[4];
#pragma unroll
    for (int j = 0; j < 4; j++) xr[j] = x[(size_t)row * 128 + lane + 32 * j];

    float acc[C_OUT];
#pragma unroll
    for (int c = 0; c < C_OUT; c++) {
        float a = 0.0f;
#pragma unroll
        for (int j = 0; j < 4; j++) a += xr[j] * Wt[c][lane + 32 * j];
#pragma unroll
        for (int o = 16; o > 0; o >>= 1) a += __shfl_down_sync(0xFFFFFFFFu, a, o);
        acc[c] = a;
    }
    if (lane == 0) {
        float mx = -1e30f;
#pragma unroll
        for (int c = 0; c < C_OUT; c++) { acc[c] += bs[c]; mx = fmaxf(mx, acc[c]); }
        float se = 0.0f;
#pragma unroll
        for (int c = 0; c < C_OUT; c++) se += expf(acc[c] - mx);
        float l = mx + logf(se);
#pragma unroll
        for (int c = 0; c < C_OUT; c++) out[(size_t)row * C_OUT + c] = acc[c] - l;
    }
}

// ---------------- host ----------------
static void* symaddr(const void* sym) {
    void* p = nullptr;
    cudaGetSymbolAddress(&p, sym);
    return p;
}

extern "C" void kernel_launch(void* const* d_in, const int* in_sizes, int n_in,
                              void* d_out, int out_size) {
    const float* x   = (const float*)d_in[0];
    const int*   ei  = (const int*)d_in[1];
    const float* ew  = (const float*)d_in[2];
    const float* pre_w1 = (const float*)d_in[3];  const float* pre_b1 = (const float*)d_in[4];
    const float* cw0_1  = (const float*)d_in[5];  const float* cw1_1  = (const float*)d_in[6];
    const float* cb_1   = (const float*)d_in[7];
    const float* sw_1   = (const float*)d_in[8];  const float* sb_1   = (const float*)d_in[9];
    const float* lw_1   = (const float*)d_in[10]; const float* lb_1   = (const float*)d_in[11];
    const float* pre_w2 = (const float*)d_in[12]; const float* pre_b2 = (const float*)d_in[13];
    const float* cw0_2  = (const float*)d_in[14]; const float* cw1_2  = (const float*)d_in[15];
    const float* cb_2   = (const float*)d_in[16];
    const float* sw_2   = (const float*)d_in[17]; const float* sb_2   = (const float*)d_in[18];
    const float* lw_2   = (const float*)d_in[19]; const float* lb_2   = (const float*)d_in[20];
    const float* cls_w  = (const float*)d_in[21]; const float* cls_b  = (const float*)d_in[22];
    float* out = (float*)d_out;

    int E = in_sizes[2];
    int N = in_sizes[0] / F_IN;
    const int* src = ei;
    const int* dst = ei + E;

    float* xh    = (float*)symaddr(g_xh);
    float* o2    = (float*)symaddr(g_o2);
    float* tbuf  = (float*)symaddr(g_t);
    float* deg   = (float*)symaddr(g_deg);
    float* dis   = (float*)symaddr(g_dis);
    float* loopw = (float*)symaddr(g_loopw);
    float* invc  = (float*)symaddr(g_invcnt);
    int*   nloop = (int*)symaddr(g_nloop);
    int*   hist  = (int*)symaddr(g_hist);
    int*   off   = (int*)symaddr(g_off);
    int*   cur   = (int*)symaddr(g_cursor);
    int*   bsum  = (int*)symaddr(g_bsum);
    int*   esrc  = (int*)symaddr(g_esrc);
    float* enorm = (float*)symaddr(g_enorm);
    float* ewe   = (float*)symaddr(g_ewe);
    float* W12   = (float*)symaddr(g_W12);
    float* b12   = (float*)symaddr(g_b12);
    float* Wc    = (float*)symaddr(g_Wc);
    float* bc    = (float*)symaddr(g_bc);

    __nv_bfloat16* xh_h = (__nv_bfloat16*)symaddr(g_xh_h);
    __nv_bfloat16* xh_l = (__nv_bfloat16*)symaddr(g_xh_l);
    __nv_bfloat16* tx_h = (__nv_bfloat16*)symaddr(g_tx_h);
    __nv_bfloat16* tx_l = (__nv_bfloat16*)symaddr(g_tx_l);
    __nv_bfloat16* s_h  = (__nv_bfloat16*)symaddr(g_s_h);
    __nv_bfloat16* s_l  = (__nv_bfloat16*)symaddr(g_s_l);
    __nv_bfloat16* t_h  = (__nv_bfloat16*)symaddr(g_t_h);
    __nv_bfloat16* t_l  = (__nv_bfloat16*)symaddr(g_t_l);

    uint32_t* Fpre1  = (uint32_t*)symaddr(g_Fpre1);
    uint32_t* Fcw0_1 = (uint32_t*)symaddr(g_Fcw0_1);
    uint32_t* Fcw1_1 = (uint32_t*)symaddr(g_Fcw1_1);
    uint32_t* Fsw1   = (uint32_t*)symaddr(g_Fsw1);
    uint32_t* FW12   = (uint32_t*)symaddr(g_FW12);
    uint32_t* Fcw0_2 = (uint32_t*)symaddr(g_Fcw0_2);
    uint32_t* Fcw1_2 = (uint32_t*)symaddr(g_Fcw1_2);
    uint32_t* Fsw2   = (uint32_t*)symaddr(g_Fsw2);

    cudaFuncSetAttribute(tgemm<false, 1, 0>, cudaFuncAttributeMaxDynamicSharedMemorySize, TG_SMEM);
    cudaFuncSetAttribute(tgemm<false, 0, 1>, cudaFuncAttributeMaxDynamicSharedMemorySize, TG_SMEM);
    cudaFuncSetAttribute(tgemm<true, 2, 2>,  cudaFuncAttributeMaxDynamicSharedMemorySize, TG_SMEM);
    cudaFuncSetAttribute(tgemm<true, 2, 0>,  cudaFuncAttributeMaxDynamicSharedMemorySize, TG_SMEM);
    cudaFuncSetAttribute(tgemm_conv,         cudaFuncAttributeMaxDynamicSharedMemorySize, CV_SMEM);

    int eB = (E + 255) / 256;
    int nB = (N + 255) / 256;
    int nbScan = (N + 1023) / 1024;
    int gG = (N + 127) / 128;
    int aggB = (N * 32 + 255) / 256;

    // ---- fork: preprocessing chain on side stream ----
    cudaStream_t s2;
    cudaStreamCreateWithFlags(&s2, cudaStreamNonBlocking);
    cudaEvent_t evA, evB;
    cudaEventCreateWithFlags(&evA, cudaEventDisableTiming);
    cudaEventCreateWithFlags(&evB, cudaEventDisableTiming);
    cudaEventRecord(evA, 0);
    cudaStreamWaitEvent(s2, evA, 0);

    setup1<<<322, 256>>>(lw_1, pre_w2, lb_1, pre_b2, lw_2, cls_w, lb_2, cls_b,
                         pre_w1, W12, b12, Wc, bc, Fpre1);
    init_nodes<<<nB, 256, 0, s2>>>(loopw, deg, nloop, hist, N);
    edge_pass1<<<eB, 256, 0, s2>>>(src, dst, ew, deg, nloop, loopw, hist, E);
    // launch #4 (ncu capture slot): K=512 GEMM
    tgemm_conv<<<gG, 256, CV_SMEM>>>(x, Fpre1, pre_b1, xh, xh_h, xh_l, N, 512);
    prestage_all<<<7 * 16, 256>>>(cw0_1, cw1_1, sw_1, W12, cw0_2, cw1_2, sw_2,
                                  Fcw0_1, Fcw1_1, Fsw1, FW12, Fcw0_2, Fcw1_2, Fsw2);
    scan1<<<nbScan, 256, 0, s2>>>(hist, bsum, deg, nloop, dis, invc, N);
    scan2<<<1, 32, 0, s2>>>(bsum, nbScan, off, N);
    scan3<<<nbScan, 256, 0, s2>>>(hist, bsum, off, cur, N);
    edge_pass2<<<eB, 256, 0, s2>>>(src, dst, ew, dis, cur, esrc, enorm, ewe, E);
    cudaEventRecord(evB, s2);
    cudaStreamWaitEvent(0, evB, 0);

    // ---- cell 1 ----
    aggregate<<<aggB, 256>>>(xh, off, esrc, enorm, ewe, loopw, invc,
                             tx_h, tx_l, s_h, s_l, N);
    tgemm<false, 1, 0><<<gG, 256, TG_SMEM>>>(s_h, s_l, nullptr, nullptr, Fsw1, nullptr,
                                             sb_1, nullptr, o2, nullptr, nullptr, N, 128);
    tgemm<true, 2, 2><<<gG, 256, TG_SMEM>>>(xh_h, xh_l, tx_h, tx_l, Fcw0_1, Fcw1_1,
                                            cb_1, o2, nullptr, t_h, t_l, N, 128);

    // ---- fused lin1+pre2 ----
    tgemm<false, 0, 1><<<gG, 256, TG_SMEM>>>(t_h, t_l, nullptr, nullptr, FW12, nullptr,
                                             b12, nullptr, xh, xh_h, xh_l, N, 128);

    // ---- cell 2 ----
    aggregate<<<aggB, 256>>>(xh, off, esrc, enorm, ewe, loopw, invc,
                             tx_h, tx_l, s_h, s_l, N);
    tgemm<false, 1, 0><<<gG, 256, TG_SMEM>>>(s_h, s_l, nullptr, nullptr, Fsw2, nullptr,
                                             sb_2, nullptr, o2, nullptr, nullptr, N, 128);
    tgemm<true, 2, 0><<<gG, 256, TG_SMEM>>>(xh_h, xh_l, tx_h, tx_l, Fcw0_2, Fcw1_2,
                                            cb_2, o2, tbuf, nullptr, nullptr, N, 128);

    // ---- fused lin2 + classifier + log_softmax ----
    cls_kernel<<<(N + 7) / 8, 256>>>(tbuf, Wc, bc, out, N);
}